// round 8
// baseline (speedup 1.0000x reference)
#include <cuda_runtime.h>
#include <cuda_bf16.h>
#include <math_constants.h>
#include <cstdint>

// Problem dims
#define BB   2
#define SS   2048
#define HID  2048
#define NH   16
#define NKV  4
#define HD   128
#define RR   64
#define NTOK (BB*SS)          // 4096
#define QKVO ((NH+2*NKV)*HD)  // 3072

// Scratch (device globals; no allocation allowed)
__device__ float g_qkv[(size_t)NTOK * QKVO];                    // fp32 QKV out
__device__ float g_q[(size_t)BB * NH  * SS * HD];
__device__ float g_k[(size_t)BB * NKV * SS * HD];
__device__ float g_v[(size_t)BB * NKV * SS * HD];
__device__ __nv_bfloat16 g_xh[(size_t)NTOK * HID];              // hidden / attn hi
__device__ __nv_bfloat16 g_xl[(size_t)NTOK * HID];              // hidden / attn lo
__device__ __nv_bfloat16 g_wh[(size_t)QKVO * HID];              // weight hi
__device__ __nv_bfloat16 g_wl[(size_t)QKVO * HID];              // weight lo

// ---------------------------------------------------------------------------
// PTX helpers (base PTX only — compute_103-safe)
// ---------------------------------------------------------------------------
__device__ __forceinline__ void mma_bf16(float* c, const uint32_t* a, const uint32_t* b) {
    asm volatile(
        "mma.sync.aligned.m16n8k16.row.col.f32.bf16.bf16.f32 "
        "{%0,%1,%2,%3}, {%4,%5,%6,%7}, {%8,%9}, {%0,%1,%2,%3};"
        : "+f"(c[0]), "+f"(c[1]), "+f"(c[2]), "+f"(c[3])
        : "r"(a[0]), "r"(a[1]), "r"(a[2]), "r"(a[3]), "r"(b[0]), "r"(b[1]));
}

__device__ __forceinline__ void ldsm_x4(uint32_t* r, uint32_t addr) {
    asm volatile("ldmatrix.sync.aligned.m8n8.x4.shared.b16 {%0,%1,%2,%3}, [%4];"
        : "=r"(r[0]), "=r"(r[1]), "=r"(r[2]), "=r"(r[3]) : "r"(addr));
}

__device__ __forceinline__ void ldsm_x4_t(uint32_t* r, uint32_t addr) {
    asm volatile("ldmatrix.sync.aligned.m8n8.x4.trans.shared.b16 {%0,%1,%2,%3}, [%4];"
        : "=r"(r[0]), "=r"(r[1]), "=r"(r[2]), "=r"(r[3]) : "r"(addr));
}

__device__ __forceinline__ uint32_t smem_u32(const void* p) {
    uint32_t a;
    asm("{ .reg .u64 t; cvta.to.shared.u64 t, %1; cvt.u32.u64 %0, t; }"
        : "=r"(a) : "l"(p));
    return a;
}

#define CP_ASYNC16(saddr, gptr) \
    asm volatile("cp.async.cg.shared.global [%0], [%1], 16;" \
                 :: "r"(saddr), "l"(gptr))
#define CP_COMMIT() asm volatile("cp.async.commit_group;" ::: "memory")
#define CP_WAIT(n)  asm volatile("cp.async.wait_group %0;" :: "n"(n) : "memory")

__device__ __forceinline__ uint32_t bf16hi2(float x, float y) {
    __nv_bfloat162 h = __floats2bfloat162_rn(x, y);
    return *(uint32_t*)&h;
}

__device__ __forceinline__ void split4(float4 v, uint2& hi, uint2& lo) {
    uint32_t h0 = bf16hi2(v.x, v.y);
    uint32_t h1 = bf16hi2(v.z, v.w);
    __nv_bfloat162 hh0 = *(__nv_bfloat162*)&h0;
    __nv_bfloat162 hh1 = *(__nv_bfloat162*)&h1;
    uint32_t l0 = bf16hi2(v.x - __bfloat162float(hh0.x), v.y - __bfloat162float(hh0.y));
    uint32_t l1 = bf16hi2(v.z - __bfloat162float(hh1.x), v.w - __bfloat162float(hh1.y));
    hi = make_uint2(h0, h1);
    lo = make_uint2(l0, l1);
}

// ---------------------------------------------------------------------------
// Elementwise fp32 -> bf16 hi/lo split
// ---------------------------------------------------------------------------
__global__ __launch_bounds__(256) void split_kernel(
    const float* __restrict__ in, __nv_bfloat16* __restrict__ hi,
    __nv_bfloat16* __restrict__ lo, int n4)
{
    int i = blockIdx.x * blockDim.x + threadIdx.x;
    if (i < n4) {
        float4 v = ((const float4*)in)[i];
        uint2 h, l;
        split4(v, h, l);
        ((uint2*)hi)[i] = h;
        ((uint2*)lo)[i] = l;
    }
}

// ---------------------------------------------------------------------------
// Tensor GEMM: C[M,N] = A[M,K] * B[N,K]^T, pre-split bf16 hi/lo inputs.
// 128x128 tile, BK=32, 256 threads, cp.async double-buffer, ldmatrix.
// 2 CTAs/SM (80 KB smem each, <=128 regs).
// ---------------------------------------------------------------------------
#define TBK 32
#define ASTR 40
#define ARR (128 * ASTR)
#define STAGE_BF16 (4 * ARR)
#define GEMM_SMEM (2 * STAGE_BF16 * 2)    // 80 KB

__global__ __launch_bounds__(256, 2) void gemm_mma_kernel(
    const __nv_bfloat16* __restrict__ Ah, const __nv_bfloat16* __restrict__ Al,
    const __nv_bfloat16* __restrict__ Bh, const __nv_bfloat16* __restrict__ Bl,
    float* __restrict__ C, int N, int K)
{
    extern __shared__ __nv_bfloat16 smb[];
    const int tid  = threadIdx.x;
    const int wid  = tid >> 5;
    const int lane = tid & 31;
    const int wm   = wid >> 2;
    const int wn   = wid & 3;
    const int row0 = blockIdx.y * 128;
    const int col0 = blockIdx.x * 128;

    const int lr = lane >> 2;
    const int lc = (lane & 3) * 2;

    const uint32_t sb = smem_u32(smb);
    const uint32_t laneA = ((lane & 15) * ASTR + (lane >> 4) * 8) * 2;
    const uint32_t laneB = (((lane >> 4) * 8 + (lane & 7)) * ASTR + ((lane >> 3) & 1) * 8) * 2;

    float acc[4][4][4];
    #pragma unroll
    for (int mt = 0; mt < 4; ++mt)
        #pragma unroll
        for (int nt = 0; nt < 4; ++nt)
            #pragma unroll
            for (int q = 0; q < 4; ++q) acc[mt][nt][q] = 0.f;

    const int nchunk = K / TBK;

    const __nv_bfloat16* srcs[4] = {
        Ah + (size_t)row0 * K, Al + (size_t)row0 * K,
        Bh + (size_t)col0 * K, Bl + (size_t)col0 * K };

    auto issue_chunk = [&](int ic, int stg) {
        uint32_t sbase = sb + (uint32_t)stg * (STAGE_BF16 * 2);
        #pragma unroll
        for (int arr = 0; arr < 4; ++arr) {
            #pragma unroll
            for (int it = 0; it < 2; ++it) {
                int id = tid + it * 256;
                int r = id >> 2, g = id & 3;
                CP_ASYNC16(sbase + (uint32_t)arr * (ARR * 2)
                               + (uint32_t)(r * ASTR * 2 + g * 16),
                           srcs[arr] + (size_t)r * K + (size_t)ic * TBK + g * 8);
            }
        }
    };

    issue_chunk(0, 0);
    CP_COMMIT();

    for (int ic = 0; ic < nchunk; ++ic) {
        const int cur = ic & 1;
        if (ic + 1 < nchunk) {
            issue_chunk(ic + 1, 1 - cur);
            CP_COMMIT();
            CP_WAIT(1);
        } else {
            CP_WAIT(0);
        }
        __syncthreads();

        const uint32_t stOff = (uint32_t)cur * (STAGE_BF16 * 2);
        const uint32_t aBase = sb + stOff + (uint32_t)(wm * 64) * (ASTR * 2) + laneA;
        const uint32_t bBase = sb + stOff + (uint32_t)(2 * ARR) * 2
                             + (uint32_t)(wn * 32) * (ASTR * 2) + laneB;

        #pragma unroll
        for (int ks = 0; ks < 2; ++ks) {
            const uint32_t kkB = ks * 32;
            uint32_t ah[4][4], al[4][4], bh[2][4], bl[2][4];
            #pragma unroll
            for (int mt = 0; mt < 4; ++mt) {
                ldsm_x4(ah[mt], aBase + (uint32_t)mt * (16 * ASTR * 2) + kkB);
                ldsm_x4(al[mt], aBase + (uint32_t)(ARR * 2) + (uint32_t)mt * (16 * ASTR * 2) + kkB);
            }
            #pragma unroll
            for (int np = 0; np < 2; ++np) {
                ldsm_x4(bh[np], bBase + (uint32_t)np * (16 * ASTR * 2) + kkB);
                ldsm_x4(bl[np], bBase + (uint32_t)(ARR * 2) + (uint32_t)np * (16 * ASTR * 2) + kkB);
            }
            #pragma unroll
            for (int mt = 0; mt < 4; ++mt)
                #pragma unroll
                for (int nt = 0; nt < 4; ++nt) {
                    const uint32_t* pbh = &bh[nt >> 1][(nt & 1) * 2];
                    const uint32_t* pbl = &bl[nt >> 1][(nt & 1) * 2];
                    mma_bf16(acc[mt][nt], ah[mt], pbh);
                    mma_bf16(acc[mt][nt], ah[mt], pbl);
                    mma_bf16(acc[mt][nt], al[mt], pbh);
                }
        }
        __syncthreads();
    }

    #pragma unroll
    for (int mt = 0; mt < 4; ++mt) {
        int row = row0 + wm * 64 + mt * 16 + lr;
        #pragma unroll
        for (int nt = 0; nt < 4; ++nt) {
            int col = col0 + wn * 32 + nt * 8 + lc;
            *(float2*)&C[(size_t)row * N + col] =
                make_float2(acc[mt][nt][0], acc[mt][nt][1]);
            *(float2*)&C[(size_t)(row + 8) * N + col] =
                make_float2(acc[mt][nt][2], acc[mt][nt][3]);
        }
    }
}

// ---------------------------------------------------------------------------
// Per-head RMSNorm + RoPE + split into fp32 Q/K/V tensors.
// ---------------------------------------------------------------------------
__global__ __launch_bounds__(128) void prep_kernel(
    const float* __restrict__ cos_t, const float* __restrict__ sin_t,
    const float* __restrict__ q_ln, const float* __restrict__ k_ln)
{
    const int hh = blockIdx.x;
    const int s  = blockIdx.y;
    const int b  = blockIdx.z;
    const int d  = threadIdx.x;

    const size_t t = (size_t)b * SS + s;
    float x = g_qkv[t * QKVO + hh * HD + d];

    __shared__ float sy[HD];
    __shared__ float red[4];

    if (hh < NH + NKV) {
        float sq = x * x;
        #pragma unroll
        for (int o = 16; o; o >>= 1) sq += __shfl_xor_sync(0xFFFFFFFFu, sq, o);
        if ((d & 31) == 0) red[d >> 5] = sq;
        __syncthreads();
        float var = (red[0] + red[1] + red[2] + red[3]) * (1.f / HD);
        const float* w = (hh < NH) ? q_ln : k_ln;
        float y = x * rsqrtf(var + 1e-6f) * w[d];
        sy[d] = y;
        __syncthreads();

        float out = y;
        if (d < RR) {
            float c  = cos_t[t * RR + d];
            float sn = sin_t[t * RR + d];
            float rot = (d < RR / 2) ? -sy[d + RR / 2] : sy[d - RR / 2];
            out = fmaf(y, c, rot * sn);
        }
        if (hh < NH)
            g_q[(((size_t)(b * NH + hh)) * SS + s) * HD + d] = out;
        else
            g_k[(((size_t)(b * NKV + (hh - NH))) * SS + s) * HD + d] = out;
    } else {
        g_v[(((size_t)(b * NKV + (hh - NH - NKV))) * SS + s) * HD + d] = x;
    }
}

// ---------------------------------------------------------------------------
// Flash attention on mma.sync (round-6 proven form: fp32 loads, inline split,
// ldmatrix fragments). CTA: 128 q x (b,h), 8 warps.
// Epilogue writes output directly as split bf16 into g_xh/g_xl.
// ---------------------------------------------------------------------------
#define DSTR 136

#define AQ_OFF  0                         // Qhi[128*DSTR], Qlo
#define AK_OFF  (2 * 128 * DSTR)          // Khi[64*DSTR],  Klo
#define AV_OFF  (AK_OFF + 2 * 64 * DSTR)  // Vhi[64*DSTR],  Vlo
#define ATTN2_BF16 (AV_OFF + 2 * 64 * DSTR)
#define ATTN2_SMEM (ATTN2_BF16 * 2)       // ~136 KB

__global__ __launch_bounds__(256, 1) void attn_mma_kernel()
{
    extern __shared__ __nv_bfloat16 smb[];
    __nv_bfloat16* Qhi = smb + AQ_OFF;
    __nv_bfloat16* Qlo = Qhi + 128 * DSTR;
    __nv_bfloat16* Khi = smb + AK_OFF;
    __nv_bfloat16* Klo = Khi + 64 * DSTR;
    __nv_bfloat16* Vhi = smb + AV_OFF;
    __nv_bfloat16* Vlo = Vhi + 64 * DSTR;

    const int tid  = threadIdx.x;
    const int wid  = tid >> 5;
    const int lane = tid & 31;
    const int gr   = lane >> 2;
    const int gc   = (lane & 3) * 2;
    const int q0 = blockIdx.x * 128;
    const int bh = blockIdx.y;
    const int b = bh >> 4;
    const int h = bh & 15;
    const int hk = h / (NH / NKV);
    const int m0 = wid * 16;

    const float qscale = 0.08838834764831845f;  // 1/sqrt(128)

    const uint32_t sb = smem_u32(smb);
    const uint32_t laneA = ((lane & 15) * DSTR + (lane >> 4) * 8) * 2;
    const uint32_t laneB = (((lane >> 4) * 8 + (lane & 7)) * DSTR + ((lane >> 3) & 1) * 8) * 2;
    const uint32_t laneV = ((lane & 15) * DSTR + (lane >> 4) * 8) * 2;

    const uint32_t qBaseHi = sb + (uint32_t)(m0 * DSTR) * 2 + laneA;
    const uint32_t qBaseLo = qBaseHi + (uint32_t)(128 * DSTR) * 2;
    const uint32_t kBaseHi = sb + (uint32_t)AK_OFF * 2 + laneB;
    const uint32_t kBaseLo = kBaseHi + (uint32_t)(64 * DSTR) * 2;
    const uint32_t vBaseHi = sb + (uint32_t)AV_OFF * 2 + laneV;
    const uint32_t vBaseLo = vBaseHi + (uint32_t)(64 * DSTR) * 2;

    // ---- load Q tile 128x128, pre-scaled, split hi/lo ----
    {
        const float* qsrc = &g_q[(((size_t)(b * NH + h)) * SS + q0) * HD];
        #pragma unroll
        for (int it = 0; it < 16; ++it) {
            int f4 = tid + it * 256;
            int r  = f4 >> 5;
            int c4 = f4 & 31;
            float4 v = *(const float4*)&qsrc[(size_t)r * HD + c4 * 4];
            v.x *= qscale; v.y *= qscale; v.z *= qscale; v.w *= qscale;
            uint2 hi, lo;
            split4(v, hi, lo);
            *(uint2*)&Qhi[r * DSTR + c4 * 4] = hi;
            *(uint2*)&Qlo[r * DSTR + c4 * 4] = lo;
        }
    }

    float m_[2] = {-CUDART_INF_F, -CUDART_INF_F};
    float l_[2] = {0.f, 0.f};
    float O[16][4];
    #pragma unroll
    for (int nt = 0; nt < 16; ++nt)
        #pragma unroll
        for (int q = 0; q < 4; ++q) O[nt][q] = 0.f;

    const float* kbase = &g_k[((size_t)(b * NKV + hk)) * SS * HD];
    const float* vbase = &g_v[((size_t)(b * NKV + hk)) * SS * HD];

    __syncthreads();

    for (int kt = 0; kt < SS / 64; ++kt) {
        // ---- load K and V tiles 64x128 (row-major), split hi/lo ----
        {
            const float* ks = kbase + (size_t)kt * 64 * HD;
            const float* vs = vbase + (size_t)kt * 64 * HD;
            #pragma unroll
            for (int it = 0; it < 8; ++it) {
                int f4 = tid + it * 256;
                int r  = f4 >> 5;
                int c4 = f4 & 31;
                float4 v = *(const float4*)&ks[(size_t)r * HD + c4 * 4];
                uint2 hi, lo;
                split4(v, hi, lo);
                *(uint2*)&Khi[r * DSTR + c4 * 4] = hi;
                *(uint2*)&Klo[r * DSTR + c4 * 4] = lo;
                float4 w = *(const float4*)&vs[(size_t)r * HD + c4 * 4];
                split4(w, hi, lo);
                *(uint2*)&Vhi[r * DSTR + c4 * 4] = hi;
                *(uint2*)&Vlo[r * DSTR + c4 * 4] = lo;
            }
        }
        __syncthreads();

        // ---- S = Q K^T ----
        float sc[8][4];
        #pragma unroll
        for (int nt = 0; nt < 8; ++nt)
            #pragma unroll
            for (int q = 0; q < 4; ++q) sc[nt][q] = 0.f;

        #pragma unroll
        for (int ks = 0; ks < 8; ++ks) {
            const uint32_t kkB = ks * 32;
            uint32_t qh[4], ql[4];
            ldsm_x4(qh, qBaseHi + kkB);
            ldsm_x4(ql, qBaseLo + kkB);
            #pragma unroll
            for (int np = 0; np < 4; ++np) {
                uint32_t kb4[4], kl4[4];
                ldsm_x4(kb4, kBaseHi + (uint32_t)np * (16 * DSTR * 2) + kkB);
                ldsm_x4(kl4, kBaseLo + (uint32_t)np * (16 * DSTR * 2) + kkB);
                mma_bf16(sc[2*np],   qh, &kb4[0]);
                mma_bf16(sc[2*np],   qh, &kl4[0]);
                mma_bf16(sc[2*np],   ql, &kb4[0]);
                mma_bf16(sc[2*np+1], qh, &kb4[2]);
                mma_bf16(sc[2*np+1], qh, &kl4[2]);
                mma_bf16(sc[2*np+1], ql, &kb4[2]);
            }
        }

        // ---- online softmax (warp-local) ----
        float mx0 = -CUDART_INF_F, mx1 = -CUDART_INF_F;
        #pragma unroll
        for (int nt = 0; nt < 8; ++nt) {
            mx0 = fmaxf(mx0, fmaxf(sc[nt][0], sc[nt][1]));
            mx1 = fmaxf(mx1, fmaxf(sc[nt][2], sc[nt][3]));
        }
        mx0 = fmaxf(mx0, __shfl_xor_sync(0xFFFFFFFFu, mx0, 1));
        mx0 = fmaxf(mx0, __shfl_xor_sync(0xFFFFFFFFu, mx0, 2));
        mx1 = fmaxf(mx1, __shfl_xor_sync(0xFFFFFFFFu, mx1, 1));
        mx1 = fmaxf(mx1, __shfl_xor_sync(0xFFFFFFFFu, mx1, 2));

        float mn0 = fmaxf(m_[0], mx0);
        float mn1 = fmaxf(m_[1], mx1);
        float scl0 = __expf(m_[0] - mn0);
        float scl1 = __expf(m_[1] - mn1);
        m_[0] = mn0; m_[1] = mn1;

        uint32_t pah[4][4], pal[4][4];
        float rs0 = 0.f, rs1 = 0.f;
        #pragma unroll
        for (int k2 = 0; k2 < 4; ++k2) {
            float p00 = __expf(sc[2*k2][0] - mn0);
            float p01 = __expf(sc[2*k2][1] - mn0);
            float p02 = __expf(sc[2*k2][2] - mn1);
            float p03 = __expf(sc[2*k2][3] - mn1);
            float p10 = __expf(sc[2*k2+1][0] - mn0);
            float p11 = __expf(sc[2*k2+1][1] - mn0);
            float p12 = __expf(sc[2*k2+1][2] - mn1);
            float p13 = __expf(sc[2*k2+1][3] - mn1);
            rs0 += p00 + p01 + p10 + p11;
            rs1 += p02 + p03 + p12 + p13;
            uint32_t hh;
            hh = bf16hi2(p00, p01); pah[k2][0] = hh;
            {   __nv_bfloat162 t = *(__nv_bfloat162*)&hh;
                pal[k2][0] = bf16hi2(p00 - __bfloat162float(t.x), p01 - __bfloat162float(t.y)); }
            hh = bf16hi2(p02, p03); pah[k2][1] = hh;
            {   __nv_bfloat162 t = *(__nv_bfloat162*)&hh;
                pal[k2][1] = bf16hi2(p02 - __bfloat162float(t.x), p03 - __bfloat162float(t.y)); }
            hh = bf16hi2(p10, p11); pah[k2][2] = hh;
            {   __nv_bfloat162 t = *(__nv_bfloat162*)&hh;
                pal[k2][2] = bf16hi2(p10 - __bfloat162float(t.x), p11 - __bfloat162float(t.y)); }
            hh = bf16hi2(p12, p13); pah[k2][3] = hh;
            {   __nv_bfloat162 t = *(__nv_bfloat162*)&hh;
                pal[k2][3] = bf16hi2(p12 - __bfloat162float(t.x), p13 - __bfloat162float(t.y)); }
        }
        rs0 += __shfl_xor_sync(0xFFFFFFFFu, rs0, 1);
        rs0 += __shfl_xor_sync(0xFFFFFFFFu, rs0, 2);
        rs1 += __shfl_xor_sync(0xFFFFFFFFu, rs1, 1);
        rs1 += __shfl_xor_sync(0xFFFFFFFFu, rs1, 2);
        l_[0] = l_[0] * scl0 + rs0;
        l_[1] = l_[1] * scl1 + rs1;

        #pragma unroll
        for (int nt = 0; nt < 16; ++nt) {
            O[nt][0] *= scl0; O[nt][1] *= scl0;
            O[nt][2] *= scl1; O[nt][3] *= scl1;
        }

        // ---- PV ----
        #pragma unroll
        for (int k2 = 0; k2 < 4; ++k2) {
            const uint32_t kOff = (uint32_t)k2 * (16 * DSTR * 2);
            #pragma unroll
            for (int np = 0; np < 8; ++np) {
                uint32_t vb4[4], vl4[4];
                ldsm_x4_t(vb4, vBaseHi + kOff + (uint32_t)np * 32);
                ldsm_x4_t(vl4, vBaseLo + kOff + (uint32_t)np * 32);
                mma_bf16(O[2*np],   pah[k2], &vb4[0]);
                mma_bf16(O[2*np],   pah[k2], &vl4[0]);
                mma_bf16(O[2*np],   pal[k2], &vb4[0]);
                mma_bf16(O[2*np+1], pah[k2], &vb4[2]);
                mma_bf16(O[2*np+1], pah[k2], &vl4[2]);
                mma_bf16(O[2*np+1], pal[k2], &vb4[2]);
            }
        }
        __syncthreads();
    }

    // ---- epilogue: normalize, split, write bf16 hi/lo to g_xh/g_xl ----
    const float inv0 = 1.f / l_[0];
    const float inv1 = 1.f / l_[1];
    const int s0 = q0 + m0 + gr;
    #pragma unroll
    for (int nt = 0; nt < 16; ++nt) {
        int col = nt * 8 + gc;
        size_t off0 = (((size_t)b * SS + s0) * NH + h) * HD + col;
        size_t off1 = (((size_t)b * SS + s0 + 8) * NH + h) * HD + col;
        float a0 = O[nt][0] * inv0, a1 = O[nt][1] * inv0;
        float a2 = O[nt][2] * inv1, a3 = O[nt][3] * inv1;
        uint32_t h0 = bf16hi2(a0, a1);
        __nv_bfloat162 t0 = *(__nv_bfloat162*)&h0;
        uint32_t l0 = bf16hi2(a0 - __bfloat162float(t0.x), a1 - __bfloat162float(t0.y));
        uint32_t h1 = bf16hi2(a2, a3);
        __nv_bfloat162 t1 = *(__nv_bfloat162*)&h1;
        uint32_t l1 = bf16hi2(a2 - __bfloat162float(t1.x), a3 - __bfloat162float(t1.y));
        *(uint32_t*)&g_xh[off0] = h0;
        *(uint32_t*)&g_xl[off0] = l0;
        *(uint32_t*)&g_xh[off1] = h1;
        *(uint32_t*)&g_xl[off1] = l1;
    }
}

// ---------------------------------------------------------------------------
extern "C" void kernel_launch(void* const* d_in, const int* in_sizes, int n_in,
                              void* d_out, int out_size)
{
    const float* hidden  = (const float*)d_in[0];
    const float* cos_t   = (const float*)d_in[1];
    const float* sin_t   = (const float*)d_in[2];
    const float* w_qkv   = (const float*)d_in[3];
    const float* q_ln    = (const float*)d_in[4];
    const float* k_ln    = (const float*)d_in[5];
    const float* w_dense = (const float*)d_in[6];
    float* out = (float*)d_out;

    void *p_qkv, *p_xh, *p_xl, *p_wh, *p_wl;
    cudaGetSymbolAddress(&p_qkv, g_qkv);
    cudaGetSymbolAddress(&p_xh, g_xh);
    cudaGetSymbolAddress(&p_xl, g_xl);
    cudaGetSymbolAddress(&p_wh, g_wh);
    cudaGetSymbolAddress(&p_wl, g_wl);
    float* qkv = (float*)p_qkv;
    __nv_bfloat16* xh = (__nv_bfloat16*)p_xh;
    __nv_bfloat16* xl = (__nv_bfloat16*)p_xl;
    __nv_bfloat16* wh = (__nv_bfloat16*)p_wh;
    __nv_bfloat16* wl = (__nv_bfloat16*)p_wl;

    cudaFuncSetAttribute(gemm_mma_kernel,
                         cudaFuncAttributeMaxDynamicSharedMemorySize, GEMM_SMEM);
    cudaFuncSetAttribute(attn_mma_kernel,
                         cudaFuncAttributeMaxDynamicSharedMemorySize, ATTN2_SMEM);

    // 0) pre-split hidden and w_qkv
    split_kernel<<<(NTOK * HID / 4 + 255) / 256, 256>>>(hidden, xh, xl, NTOK * HID / 4);
    split_kernel<<<(QKVO * HID / 4 + 255) / 256, 256>>>(w_qkv, wh, wl, QKVO * HID / 4);

    // 1) QKV projection (2 CTAs/SM)
    gemm_mma_kernel<<<dim3(QKVO / 128, NTOK / 128), 256, GEMM_SMEM>>>(
        xh, xl, wh, wl, qkv, QKVO, HID);

    // 2) RMSNorm + RoPE -> fp32 Q/K/V
    prep_kernel<<<dim3(NH + 2 * NKV, SS, BB), 128>>>(cos_t, sin_t, q_ln, k_ln);

    // 3) Flash attention (round-6 form) -> split bf16 output in g_xh/g_xl
    attn_mma_kernel<<<dim3(SS / 128, BB * NH), 256, ATTN2_SMEM>>>();

    // 3b) pre-split w_dense (overwrites g_wh/g_wl, safe after GEMM1)
    split_kernel<<<(HID * HID / 4 + 255) / 256, 256>>>(w_dense, wh, wl, HID * HID / 4);

    // 4) Output projection (2 CTAs/SM)
    gemm_mma_kernel<<<dim3(HID / 128, NTOK / 128), 256, GEMM_SMEM>>>(
        xh, xl, wh, wl, out, HID, HID);
}

// round 9
// speedup vs baseline: 1.4972x; 1.4972x over previous
#include <cuda_runtime.h>
#include <cuda_bf16.h>
#include <math_constants.h>
#include <cstdint>

// Problem dims
#define BB   2
#define SS   2048
#define HID  2048
#define NH   16
#define NKV  4
#define HD   128
#define RR   64
#define NTOK (BB*SS)          // 4096
#define QKVO ((NH+2*NKV)*HD)  // 3072

// Scratch (device globals; no allocation allowed)
__device__ float g_qkv[(size_t)NTOK * QKVO];
__device__ float g_q[(size_t)BB * NH  * SS * HD];
__device__ float g_k[(size_t)BB * NKV * SS * HD];
__device__ float g_v[(size_t)BB * NKV * SS * HD];
__device__ float g_attn[(size_t)NTOK * (NH*HD)];

// ---------------------------------------------------------------------------
// PTX helpers (base PTX only — compute_103-safe)
// ---------------------------------------------------------------------------
__device__ __forceinline__ void mma_bf16(float* c, const uint32_t* a, const uint32_t* b) {
    asm volatile(
        "mma.sync.aligned.m16n8k16.row.col.f32.bf16.bf16.f32 "
        "{%0,%1,%2,%3}, {%4,%5,%6,%7}, {%8,%9}, {%0,%1,%2,%3};"
        : "+f"(c[0]), "+f"(c[1]), "+f"(c[2]), "+f"(c[3])
        : "r"(a[0]), "r"(a[1]), "r"(a[2]), "r"(a[3]), "r"(b[0]), "r"(b[1]));
}

__device__ __forceinline__ void ldsm_x4(uint32_t* r, uint32_t addr) {
    asm volatile("ldmatrix.sync.aligned.m8n8.x4.shared.b16 {%0,%1,%2,%3}, [%4];"
        : "=r"(r[0]), "=r"(r[1]), "=r"(r[2]), "=r"(r[3]) : "r"(addr));
}

__device__ __forceinline__ void ldsm_x4_t(uint32_t* r, uint32_t addr) {
    asm volatile("ldmatrix.sync.aligned.m8n8.x4.trans.shared.b16 {%0,%1,%2,%3}, [%4];"
        : "=r"(r[0]), "=r"(r[1]), "=r"(r[2]), "=r"(r[3]) : "r"(addr));
}

__device__ __forceinline__ uint32_t smem_u32(const void* p) {
    uint32_t a;
    asm("{ .reg .u64 t; cvta.to.shared.u64 t, %1; cvt.u32.u64 %0, t; }"
        : "=r"(a) : "l"(p));
    return a;
}

__device__ __forceinline__ uint32_t bf16hi2(float x, float y) {
    __nv_bfloat162 h = __floats2bfloat162_rn(x, y);
    return *(uint32_t*)&h;
}

__device__ __forceinline__ void split4(float4 v, uint2& hi, uint2& lo) {
    uint32_t h0 = bf16hi2(v.x, v.y);
    uint32_t h1 = bf16hi2(v.z, v.w);
    __nv_bfloat162 hh0 = *(__nv_bfloat162*)&h0;
    __nv_bfloat162 hh1 = *(__nv_bfloat162*)&h1;
    uint32_t l0 = bf16hi2(v.x - __bfloat162float(hh0.x), v.y - __bfloat162float(hh0.y));
    uint32_t l1 = bf16hi2(v.z - __bfloat162float(hh1.x), v.w - __bfloat162float(hh1.y));
    hi = make_uint2(h0, h1);
    lo = make_uint2(l0, l1);
}

// ---------------------------------------------------------------------------
// Tensor GEMM: C[M,N] = A[M,K] * B[N,K]^T, fp32 in/out, bf16 3-term split.
// 128x128 tile, BK=32, 512 threads (warps 4x4, warp tile 32x32).
// 4 warps/SMSP for HMMA latency hiding; term-major MMA ordering.
// ---------------------------------------------------------------------------
#define TBK 32
#define ASTR 40
#define ARR (128 * ASTR)
#define STAGE_BF16 (4 * ARR)
#define GEMM_SMEM (2 * STAGE_BF16 * 2)   // 80 KB

__global__ __launch_bounds__(512, 1) void gemm_mma_kernel(
    const float* __restrict__ A, const float* __restrict__ Bm,
    float* __restrict__ C, int N, int K)
{
    extern __shared__ __nv_bfloat16 smb[];
    const int tid  = threadIdx.x;
    const int wid  = tid >> 5;
    const int lane = tid & 31;
    const int wm   = wid >> 2;          // 0..3 -> rows wm*32
    const int wn   = wid & 3;           // 0..3 -> cols wn*32
    const int row0 = blockIdx.y * 128;
    const int col0 = blockIdx.x * 128;

    const int lr = lane >> 2;
    const int lc = (lane & 3) * 2;

    const int ldr  = tid >> 3;          // 0..63
    const int ldc4 = (tid & 7) * 4;     // col group

    const uint32_t sb = smem_u32(smb);
    const uint32_t laneA = ((lane & 15) * ASTR + (lane >> 4) * 8) * 2;
    const uint32_t laneB = (((lane >> 4) * 8 + (lane & 7)) * ASTR + ((lane >> 3) & 1) * 8) * 2;

    float acc[2][4][4];
    #pragma unroll
    for (int mt = 0; mt < 2; ++mt)
        #pragma unroll
        for (int nt = 0; nt < 4; ++nt)
            #pragma unroll
            for (int q = 0; q < 4; ++q) acc[mt][nt][q] = 0.f;

    const int nchunk = K / TBK;

    auto put = [&](__nv_bfloat16* hi, __nv_bfloat16* lo, int r, int c, float4 v) {
        uint2 h, l;
        split4(v, h, l);
        *(uint2*)&hi[r * ASTR + c] = h;
        *(uint2*)&lo[r * ASTR + c] = l;
    };

    float4 pa[2], pb[2];

    // initial chunk load (128x32 A, 128x32 B; 1024 float4 each / 512 thr = 2 iters)
    {
        const float* Ab = A + (size_t)row0 * K;
        const float* Bb = Bm + (size_t)col0 * K;
        __nv_bfloat16* s = smb;
        #pragma unroll
        for (int it = 0; it < 2; ++it) {
            int r = ldr + it * 64;
            float4 va = *(const float4*)&Ab[(size_t)r * K + ldc4];
            put(s, s + ARR, r, ldc4, va);
            float4 vb = *(const float4*)&Bb[(size_t)r * K + ldc4];
            put(s + 2 * ARR, s + 3 * ARR, r, ldc4, vb);
        }
    }
    __syncthreads();

    for (int ic = 0; ic < nchunk; ++ic) {
        const int cur = ic & 1;

        if (ic + 1 < nchunk) {
            const float* Ab = A + (size_t)row0 * K + (ic + 1) * TBK;
            const float* Bb = Bm + (size_t)col0 * K + (ic + 1) * TBK;
            #pragma unroll
            for (int it = 0; it < 2; ++it) {
                int r = ldr + it * 64;
                pa[it] = *(const float4*)&Ab[(size_t)r * K + ldc4];
                pb[it] = *(const float4*)&Bb[(size_t)r * K + ldc4];
            }
        }

        const uint32_t stOff = (uint32_t)cur * (STAGE_BF16 * 2);
        const uint32_t aHi = sb + stOff + (uint32_t)(wm * 32) * (ASTR * 2) + laneA;
        const uint32_t aLo = aHi + (uint32_t)(ARR * 2);
        const uint32_t bHi = sb + stOff + (uint32_t)(2 * ARR) * 2
                           + (uint32_t)(wn * 32) * (ASTR * 2) + laneB;
        const uint32_t bLo = bHi + (uint32_t)(ARR * 2);

        #pragma unroll
        for (int ks = 0; ks < 2; ++ks) {
            const uint32_t kkB = ks * 32;
            uint32_t ah[2][4], al[2][4], bh[2][4], bl[2][4];
            #pragma unroll
            for (int mt = 0; mt < 2; ++mt) {
                ldsm_x4(ah[mt], aHi + (uint32_t)mt * (16 * ASTR * 2) + kkB);
                ldsm_x4(al[mt], aLo + (uint32_t)mt * (16 * ASTR * 2) + kkB);
            }
            #pragma unroll
            for (int np = 0; np < 2; ++np) {
                ldsm_x4(bh[np], bHi + (uint32_t)np * (16 * ASTR * 2) + kkB);
                ldsm_x4(bl[np], bLo + (uint32_t)np * (16 * ASTR * 2) + kkB);
            }
            // term-major ordering: same-acc HMMAs are 8 apart (no RAW chains)
            #pragma unroll
            for (int mt = 0; mt < 2; ++mt)
                #pragma unroll
                for (int nt = 0; nt < 4; ++nt)
                    mma_bf16(acc[mt][nt], ah[mt], &bh[nt >> 1][(nt & 1) * 2]);
            #pragma unroll
            for (int mt = 0; mt < 2; ++mt)
                #pragma unroll
                for (int nt = 0; nt < 4; ++nt)
                    mma_bf16(acc[mt][nt], ah[mt], &bl[nt >> 1][(nt & 1) * 2]);
            #pragma unroll
            for (int mt = 0; mt < 2; ++mt)
                #pragma unroll
                for (int nt = 0; nt < 4; ++nt)
                    mma_bf16(acc[mt][nt], al[mt], &bh[nt >> 1][(nt & 1) * 2]);
        }

        if (ic + 1 < nchunk) {
            __nv_bfloat16* d = smb + (1 - cur) * STAGE_BF16;
            #pragma unroll
            for (int it = 0; it < 2; ++it) {
                int r = ldr + it * 64;
                put(d, d + ARR, r, ldc4, pa[it]);
                put(d + 2 * ARR, d + 3 * ARR, r, ldc4, pb[it]);
            }
        }
        __syncthreads();
    }

    #pragma unroll
    for (int mt = 0; mt < 2; ++mt) {
        int row = row0 + wm * 32 + mt * 16 + lr;
        #pragma unroll
        for (int nt = 0; nt < 4; ++nt) {
            int col = col0 + wn * 32 + nt * 8 + lc;
            *(float2*)&C[(size_t)row * N + col] =
                make_float2(acc[mt][nt][0], acc[mt][nt][1]);
            *(float2*)&C[(size_t)(row + 8) * N + col] =
                make_float2(acc[mt][nt][2], acc[mt][nt][3]);
        }
    }
}

// ---------------------------------------------------------------------------
// Per-head RMSNorm + RoPE + split into fp32 Q/K/V tensors.
// ---------------------------------------------------------------------------
__global__ __launch_bounds__(128) void prep_kernel(
    const float* __restrict__ cos_t, const float* __restrict__ sin_t,
    const float* __restrict__ q_ln, const float* __restrict__ k_ln)
{
    const int hh = blockIdx.x;
    const int s  = blockIdx.y;
    const int b  = blockIdx.z;
    const int d  = threadIdx.x;

    const size_t t = (size_t)b * SS + s;
    float x = g_qkv[t * QKVO + hh * HD + d];

    __shared__ float sy[HD];
    __shared__ float red[4];

    if (hh < NH + NKV) {
        float sq = x * x;
        #pragma unroll
        for (int o = 16; o; o >>= 1) sq += __shfl_xor_sync(0xFFFFFFFFu, sq, o);
        if ((d & 31) == 0) red[d >> 5] = sq;
        __syncthreads();
        float var = (red[0] + red[1] + red[2] + red[3]) * (1.f / HD);
        const float* w = (hh < NH) ? q_ln : k_ln;
        float y = x * rsqrtf(var + 1e-6f) * w[d];
        sy[d] = y;
        __syncthreads();

        float out = y;
        if (d < RR) {
            float c  = cos_t[t * RR + d];
            float sn = sin_t[t * RR + d];
            float rot = (d < RR / 2) ? -sy[d + RR / 2] : sy[d - RR / 2];
            out = fmaf(y, c, rot * sn);
        }
        if (hh < NH)
            g_q[(((size_t)(b * NH + hh)) * SS + s) * HD + d] = out;
        else
            g_k[(((size_t)(b * NKV + (hh - NH))) * SS + s) * HD + d] = out;
    } else {
        g_v[(((size_t)(b * NKV + (hh - NH - NKV))) * SS + s) * HD + d] = x;
    }
}

// ---------------------------------------------------------------------------
// Flash attention on mma.sync (round-6 proven form: fp32 loads, inline split,
// ldmatrix fragments). CTA: 128 q x (b,h), 8 warps (16 q-rows each).
// ---------------------------------------------------------------------------
#define DSTR 136

#define AQ_OFF  0                         // Qhi[128*DSTR], Qlo
#define AK_OFF  (2 * 128 * DSTR)          // Khi[64*DSTR],  Klo
#define AV_OFF  (AK_OFF + 2 * 64 * DSTR)  // Vhi[64*DSTR],  Vlo
#define ATTN2_BF16 (AV_OFF + 2 * 64 * DSTR)
#define ATTN2_SMEM (ATTN2_BF16 * 2)       // ~136 KB

__global__ __launch_bounds__(256, 1) void attn_mma_kernel()
{
    extern __shared__ __nv_bfloat16 smb[];
    __nv_bfloat16* Qhi = smb + AQ_OFF;
    __nv_bfloat16* Qlo = Qhi + 128 * DSTR;
    __nv_bfloat16* Khi = smb + AK_OFF;
    __nv_bfloat16* Klo = Khi + 64 * DSTR;
    __nv_bfloat16* Vhi = smb + AV_OFF;
    __nv_bfloat16* Vlo = Vhi + 64 * DSTR;

    const int tid  = threadIdx.x;
    const int wid  = tid >> 5;
    const int lane = tid & 31;
    const int gr   = lane >> 2;
    const int gc   = (lane & 3) * 2;
    const int q0 = blockIdx.x * 128;
    const int bh = blockIdx.y;
    const int b = bh >> 4;
    const int h = bh & 15;
    const int hk = h / (NH / NKV);
    const int m0 = wid * 16;

    const float qscale = 0.08838834764831845f;  // 1/sqrt(128)

    const uint32_t sb = smem_u32(smb);
    const uint32_t laneA = ((lane & 15) * DSTR + (lane >> 4) * 8) * 2;
    const uint32_t laneB = (((lane >> 4) * 8 + (lane & 7)) * DSTR + ((lane >> 3) & 1) * 8) * 2;
    const uint32_t laneV = ((lane & 15) * DSTR + (lane >> 4) * 8) * 2;

    const uint32_t qBaseHi = sb + (uint32_t)(m0 * DSTR) * 2 + laneA;
    const uint32_t qBaseLo = qBaseHi + (uint32_t)(128 * DSTR) * 2;
    const uint32_t kBaseHi = sb + (uint32_t)AK_OFF * 2 + laneB;
    const uint32_t kBaseLo = kBaseHi + (uint32_t)(64 * DSTR) * 2;
    const uint32_t vBaseHi = sb + (uint32_t)AV_OFF * 2 + laneV;
    const uint32_t vBaseLo = vBaseHi + (uint32_t)(64 * DSTR) * 2;

    // ---- load Q tile 128x128, pre-scaled, split hi/lo ----
    {
        const float* qsrc = &g_q[(((size_t)(b * NH + h)) * SS + q0) * HD];
        #pragma unroll
        for (int it = 0; it < 16; ++it) {
            int f4 = tid + it * 256;
            int r  = f4 >> 5;
            int c4 = f4 & 31;
            float4 v = *(const float4*)&qsrc[(size_t)r * HD + c4 * 4];
            v.x *= qscale; v.y *= qscale; v.z *= qscale; v.w *= qscale;
            uint2 hi, lo;
            split4(v, hi, lo);
            *(uint2*)&Qhi[r * DSTR + c4 * 4] = hi;
            *(uint2*)&Qlo[r * DSTR + c4 * 4] = lo;
        }
    }

    float m_[2] = {-CUDART_INF_F, -CUDART_INF_F};
    float l_[2] = {0.f, 0.f};
    float O[16][4];
    #pragma unroll
    for (int nt = 0; nt < 16; ++nt)
        #pragma unroll
        for (int q = 0; q < 4; ++q) O[nt][q] = 0.f;

    const float* kbase = &g_k[((size_t)(b * NKV + hk)) * SS * HD];
    const float* vbase = &g_v[((size_t)(b * NKV + hk)) * SS * HD];

    __syncthreads();

    for (int kt = 0; kt < SS / 64; ++kt) {
        // ---- load K and V tiles 64x128 (row-major), split hi/lo ----
        {
            const float* ks = kbase + (size_t)kt * 64 * HD;
            const float* vs = vbase + (size_t)kt * 64 * HD;
            #pragma unroll
            for (int it = 0; it < 8; ++it) {
                int f4 = tid + it * 256;
                int r  = f4 >> 5;
                int c4 = f4 & 31;
                float4 v = *(const float4*)&ks[(size_t)r * HD + c4 * 4];
                uint2 hi, lo;
                split4(v, hi, lo);
                *(uint2*)&Khi[r * DSTR + c4 * 4] = hi;
                *(uint2*)&Klo[r * DSTR + c4 * 4] = lo;
                float4 w = *(const float4*)&vs[(size_t)r * HD + c4 * 4];
                split4(w, hi, lo);
                *(uint2*)&Vhi[r * DSTR + c4 * 4] = hi;
                *(uint2*)&Vlo[r * DSTR + c4 * 4] = lo;
            }
        }
        __syncthreads();

        // ---- S = Q K^T ----
        float sc[8][4];
        #pragma unroll
        for (int nt = 0; nt < 8; ++nt)
            #pragma unroll
            for (int q = 0; q < 4; ++q) sc[nt][q] = 0.f;

        #pragma unroll
        for (int ks = 0; ks < 8; ++ks) {
            const uint32_t kkB = ks * 32;
            uint32_t qh[4], ql[4];
            ldsm_x4(qh, qBaseHi + kkB);
            ldsm_x4(ql, qBaseLo + kkB);
            #pragma unroll
            for (int np = 0; np < 4; ++np) {
                uint32_t kb4[4], kl4[4];
                ldsm_x4(kb4, kBaseHi + (uint32_t)np * (16 * DSTR * 2) + kkB);
                ldsm_x4(kl4, kBaseLo + (uint32_t)np * (16 * DSTR * 2) + kkB);
                mma_bf16(sc[2*np],   qh, &kb4[0]);
                mma_bf16(sc[2*np],   qh, &kl4[0]);
                mma_bf16(sc[2*np],   ql, &kb4[0]);
                mma_bf16(sc[2*np+1], qh, &kb4[2]);
                mma_bf16(sc[2*np+1], qh, &kl4[2]);
                mma_bf16(sc[2*np+1], ql, &kb4[2]);
            }
        }

        // ---- online softmax (warp-local) ----
        float mx0 = -CUDART_INF_F, mx1 = -CUDART_INF_F;
        #pragma unroll
        for (int nt = 0; nt < 8; ++nt) {
            mx0 = fmaxf(mx0, fmaxf(sc[nt][0], sc[nt][1]));
            mx1 = fmaxf(mx1, fmaxf(sc[nt][2], sc[nt][3]));
        }
        mx0 = fmaxf(mx0, __shfl_xor_sync(0xFFFFFFFFu, mx0, 1));
        mx0 = fmaxf(mx0, __shfl_xor_sync(0xFFFFFFFFu, mx0, 2));
        mx1 = fmaxf(mx1, __shfl_xor_sync(0xFFFFFFFFu, mx1, 1));
        mx1 = fmaxf(mx1, __shfl_xor_sync(0xFFFFFFFFu, mx1, 2));

        float mn0 = fmaxf(m_[0], mx0);
        float mn1 = fmaxf(m_[1], mx1);
        float scl0 = __expf(m_[0] - mn0);
        float scl1 = __expf(m_[1] - mn1);
        m_[0] = mn0; m_[1] = mn1;

        uint32_t pah[4][4], pal[4][4];
        float rs0 = 0.f, rs1 = 0.f;
        #pragma unroll
        for (int k2 = 0; k2 < 4; ++k2) {
            float p00 = __expf(sc[2*k2][0] - mn0);
            float p01 = __expf(sc[2*k2][1] - mn0);
            float p02 = __expf(sc[2*k2][2] - mn1);
            float p03 = __expf(sc[2*k2][3] - mn1);
            float p10 = __expf(sc[2*k2+1][0] - mn0);
            float p11 = __expf(sc[2*k2+1][1] - mn0);
            float p12 = __expf(sc[2*k2+1][2] - mn1);
            float p13 = __expf(sc[2*k2+1][3] - mn1);
            rs0 += p00 + p01 + p10 + p11;
            rs1 += p02 + p03 + p12 + p13;
            uint32_t hh;
            hh = bf16hi2(p00, p01); pah[k2][0] = hh;
            {   __nv_bfloat162 t = *(__nv_bfloat162*)&hh;
                pal[k2][0] = bf16hi2(p00 - __bfloat162float(t.x), p01 - __bfloat162float(t.y)); }
            hh = bf16hi2(p02, p03); pah[k2][1] = hh;
            {   __nv_bfloat162 t = *(__nv_bfloat162*)&hh;
                pal[k2][1] = bf16hi2(p02 - __bfloat162float(t.x), p03 - __bfloat162float(t.y)); }
            hh = bf16hi2(p10, p11); pah[k2][2] = hh;
            {   __nv_bfloat162 t = *(__nv_bfloat162*)&hh;
                pal[k2][2] = bf16hi2(p10 - __bfloat162float(t.x), p11 - __bfloat162float(t.y)); }
            hh = bf16hi2(p12, p13); pah[k2][3] = hh;
            {   __nv_bfloat162 t = *(__nv_bfloat162*)&hh;
                pal[k2][3] = bf16hi2(p12 - __bfloat162float(t.x), p13 - __bfloat162float(t.y)); }
        }
        rs0 += __shfl_xor_sync(0xFFFFFFFFu, rs0, 1);
        rs0 += __shfl_xor_sync(0xFFFFFFFFu, rs0, 2);
        rs1 += __shfl_xor_sync(0xFFFFFFFFu, rs1, 1);
        rs1 += __shfl_xor_sync(0xFFFFFFFFu, rs1, 2);
        l_[0] = l_[0] * scl0 + rs0;
        l_[1] = l_[1] * scl1 + rs1;

        #pragma unroll
        for (int nt = 0; nt < 16; ++nt) {
            O[nt][0] *= scl0; O[nt][1] *= scl0;
            O[nt][2] *= scl1; O[nt][3] *= scl1;
        }

        // ---- PV ----
        #pragma unroll
        for (int k2 = 0; k2 < 4; ++k2) {
            const uint32_t kOff = (uint32_t)k2 * (16 * DSTR * 2);
            #pragma unroll
            for (int np = 0; np < 8; ++np) {
                uint32_t vb4[4], vl4[4];
                ldsm_x4_t(vb4, vBaseHi + kOff + (uint32_t)np * 32);
                ldsm_x4_t(vl4, vBaseLo + kOff + (uint32_t)np * 32);
                mma_bf16(O[2*np],   pah[k2], &vb4[0]);
                mma_bf16(O[2*np],   pah[k2], &vl4[0]);
                mma_bf16(O[2*np],   pal[k2], &vb4[0]);
                mma_bf16(O[2*np+1], pah[k2], &vb4[2]);
                mma_bf16(O[2*np+1], pah[k2], &vl4[2]);
                mma_bf16(O[2*np+1], pal[k2], &vb4[2]);
            }
        }
        __syncthreads();
    }

    // ---- epilogue: normalize, write g_attn[b, s, h*128 + c] ----
    const float inv0 = 1.f / l_[0];
    const float inv1 = 1.f / l_[1];
    const int s0 = q0 + m0 + gr;
    #pragma unroll
    for (int nt = 0; nt < 16; ++nt) {
        int col = nt * 8 + gc;
        size_t off0 = (((size_t)b * SS + s0) * NH + h) * HD + col;
        size_t off1 = (((size_t)b * SS + s0 + 8) * NH + h) * HD + col;
        *(float2*)&g_attn[off0] = make_float2(O[nt][0] * inv0, O[nt][1] * inv0);
        *(float2*)&g_attn[off1] = make_float2(O[nt][2] * inv1, O[nt][3] * inv1);
    }
}

// ---------------------------------------------------------------------------
extern "C" void kernel_launch(void* const* d_in, const int* in_sizes, int n_in,
                              void* d_out, int out_size)
{
    const float* hidden  = (const float*)d_in[0];
    const float* cos_t   = (const float*)d_in[1];
    const float* sin_t   = (const float*)d_in[2];
    const float* w_qkv   = (const float*)d_in[3];
    const float* q_ln    = (const float*)d_in[4];
    const float* k_ln    = (const float*)d_in[5];
    const float* w_dense = (const float*)d_in[6];
    float* out = (float*)d_out;

    void *p_qkv = nullptr, *p_attn = nullptr;
    cudaGetSymbolAddress(&p_qkv, g_qkv);
    cudaGetSymbolAddress(&p_attn, g_attn);
    float* qkv  = (float*)p_qkv;
    float* attn = (float*)p_attn;

    cudaFuncSetAttribute(gemm_mma_kernel,
                         cudaFuncAttributeMaxDynamicSharedMemorySize, GEMM_SMEM);
    cudaFuncSetAttribute(attn_mma_kernel,
                         cudaFuncAttributeMaxDynamicSharedMemorySize, ATTN2_SMEM);

    // 1) QKV projection (512 threads, 16 warps/CTA)
    gemm_mma_kernel<<<dim3(QKVO / 128, NTOK / 128), 512, GEMM_SMEM>>>(
        hidden, w_qkv, qkv, QKVO, HID);

    // 2) RMSNorm + RoPE + split
    prep_kernel<<<dim3(NH + 2 * NKV, SS, BB), 128>>>(cos_t, sin_t, q_ln, k_ln);

    // 3) Flash attention (round-6 proven form)
    attn_mma_kernel<<<dim3(SS / 128, BB * NH), 256, ATTN2_SMEM>>>();

    // 4) Output projection
    gemm_mma_kernel<<<dim3(HID / 128, NTOK / 128), 512, GEMM_SMEM>>>(
        attn, w_dense, out, NTOK == 0 ? HID : HID, HID);
}

// round 11
// speedup vs baseline: 2.0183x; 1.3481x over previous
#include <cuda_runtime.h>
#include <cuda_fp16.h>
#include <math_constants.h>
#include <cstdint>

// Problem dims
#define BB   2
#define SS   2048
#define HID  2048
#define NH   16
#define NKV  4
#define HD   128
#define RR   64
#define NTOK (BB*SS)          // 4096
#define QKVO ((NH+2*NKV)*HD)  // 3072

// Scratch (device globals; no allocation allowed)
__device__ float g_qkv[(size_t)NTOK * QKVO];
__device__ float g_q[(size_t)BB * NH  * SS * HD];
__device__ float g_k[(size_t)BB * NKV * SS * HD];
__device__ float g_v[(size_t)BB * NKV * SS * HD];
__device__ float g_attn[(size_t)NTOK * (NH*HD)];

// ---------------------------------------------------------------------------
// PTX helpers (base PTX only — compute_103-safe)
// ---------------------------------------------------------------------------
__device__ __forceinline__ void mma_f16(float* c, const uint32_t* a, const uint32_t* b) {
    asm volatile(
        "mma.sync.aligned.m16n8k16.row.col.f32.f16.f16.f32 "
        "{%0,%1,%2,%3}, {%4,%5,%6,%7}, {%8,%9}, {%0,%1,%2,%3};"
        : "+f"(c[0]), "+f"(c[1]), "+f"(c[2]), "+f"(c[3])
        : "r"(a[0]), "r"(a[1]), "r"(a[2]), "r"(a[3]), "r"(b[0]), "r"(b[1]));
}

__device__ __forceinline__ void ldsm_x4(uint32_t* r, uint32_t addr) {
    asm volatile("ldmatrix.sync.aligned.m8n8.x4.shared.b16 {%0,%1,%2,%3}, [%4];"
        : "=r"(r[0]), "=r"(r[1]), "=r"(r[2]), "=r"(r[3]) : "r"(addr));
}

__device__ __forceinline__ void ldsm_x4_t(uint32_t* r, uint32_t addr) {
    asm volatile("ldmatrix.sync.aligned.m8n8.x4.trans.shared.b16 {%0,%1,%2,%3}, [%4];"
        : "=r"(r[0]), "=r"(r[1]), "=r"(r[2]), "=r"(r[3]) : "r"(addr));
}

__device__ __forceinline__ uint32_t smem_u32(const void* p) {
    uint32_t a;
    asm("{ .reg .u64 t; cvta.to.shared.u64 t, %1; cvt.u32.u64 %0, t; }"
        : "=r"(a) : "l"(p));
    return a;
}

__device__ __forceinline__ uint32_t f16x2(float x, float y) {
    __half2 h = __floats2half2_rn(x, y);
    return *(uint32_t*)&h;
}

// fp16 split of float4 -> hi pair-words and lo pair-words
__device__ __forceinline__ void splitf16(float4 v, uint2& hi, uint2& lo) {
    uint32_t h0 = f16x2(v.x, v.y);
    uint32_t h1 = f16x2(v.z, v.w);
    __half2 hh0 = *(__half2*)&h0;
    __half2 hh1 = *(__half2*)&h1;
    uint32_t l0 = f16x2(v.x - __low2float(hh0), v.y - __high2float(hh0));
    uint32_t l1 = f16x2(v.z - __low2float(hh1), v.w - __high2float(hh1));
    hi = make_uint2(h0, h1);
    lo = make_uint2(l0, l1);
}

// ---------------------------------------------------------------------------
// Tensor GEMM: C[M,N] = A[M,K] * B[N,K]^T, fp32 in/out.
// fp16 2-term: A single fp16, B split hi/lo.  A*B ~= Ah*Bh + Ah*Bl.
// 128x128 tile, BK=32, 256 threads, warp tile 64x32, reg-prefetch, ldmatrix.
// ---------------------------------------------------------------------------
#define TBK 32
#define ASTR 40
#define ARR (128 * ASTR)
#define STAGE3 (3 * ARR)                 // Ah, Bh, Bl
#define GEMM_SMEM (2 * STAGE3 * 2)       // 60 KB

__global__ __launch_bounds__(256, 1) void gemm_mma_kernel(
    const float* __restrict__ A, const float* __restrict__ Bm,
    float* __restrict__ C, int N, int K)
{
    extern __shared__ __half smb[];
    const int tid  = threadIdx.x;
    const int wid  = tid >> 5;
    const int lane = tid & 31;
    const int wm   = wid >> 2;
    const int wn   = wid & 3;
    const int row0 = blockIdx.y * 128;
    const int col0 = blockIdx.x * 128;

    const int lr = lane >> 2;
    const int lc = (lane & 3) * 2;

    const int ldr  = tid >> 3;
    const int ldc4 = (tid & 7) * 4;

    const uint32_t sb = smem_u32(smb);
    const uint32_t laneA = ((lane & 15) * ASTR + (lane >> 4) * 8) * 2;
    const uint32_t laneB = (((lane >> 4) * 8 + (lane & 7)) * ASTR + ((lane >> 3) & 1) * 8) * 2;

    float acc[4][4][4];
    #pragma unroll
    for (int mt = 0; mt < 4; ++mt)
        #pragma unroll
        for (int nt = 0; nt < 4; ++nt)
            #pragma unroll
            for (int q = 0; q < 4; ++q) acc[mt][nt][q] = 0.f;

    const int nchunk = K / TBK;

    auto putA = [&](__half* dst, int r, int c, float4 v) {
        uint32_t h0 = f16x2(v.x, v.y);
        uint32_t h1 = f16x2(v.z, v.w);
        *(uint2*)&dst[r * ASTR + c] = make_uint2(h0, h1);
    };
    auto putB = [&](__half* hi, __half* lo, int r, int c, float4 v) {
        uint2 h, l;
        splitf16(v, h, l);
        *(uint2*)&hi[r * ASTR + c] = h;
        *(uint2*)&lo[r * ASTR + c] = l;
    };

    float4 pa[4], pb[4];

    {
        const float* Ab = A + (size_t)row0 * K;
        const float* Bb = Bm + (size_t)col0 * K;
        __half* s = smb;
        #pragma unroll
        for (int it = 0; it < 4; ++it) {
            int r = ldr + it * 32;
            float4 va = *(const float4*)&Ab[(size_t)r * K + ldc4];
            putA(s, r, ldc4, va);
            float4 vb = *(const float4*)&Bb[(size_t)r * K + ldc4];
            putB(s + ARR, s + 2 * ARR, r, ldc4, vb);
        }
    }
    __syncthreads();

    for (int ic = 0; ic < nchunk; ++ic) {
        const int cur = ic & 1;
        const uint32_t stOff = (uint32_t)cur * (STAGE3 * 2);
        const uint32_t aBase  = sb + stOff + (uint32_t)(wm * 64) * (ASTR * 2) + laneA;
        const uint32_t bhBase = sb + stOff + (uint32_t)ARR * 2
                              + (uint32_t)(wn * 32) * (ASTR * 2) + laneB;
        const uint32_t blBase = bhBase + (uint32_t)ARR * 2;

        if (ic + 1 < nchunk) {
            const float* Ab = A + (size_t)row0 * K + (ic + 1) * TBK;
            const float* Bb = Bm + (size_t)col0 * K + (ic + 1) * TBK;
            #pragma unroll
            for (int it = 0; it < 4; ++it) {
                int r = ldr + it * 32;
                pa[it] = *(const float4*)&Ab[(size_t)r * K + ldc4];
                pb[it] = *(const float4*)&Bb[(size_t)r * K + ldc4];
            }
        }

        #pragma unroll
        for (int ks = 0; ks < 2; ++ks) {
            const uint32_t kkB = ks * 32;
            uint32_t ah[4][4], bh[2][4], bl[2][4];
            #pragma unroll
            for (int mt = 0; mt < 4; ++mt)
                ldsm_x4(ah[mt], aBase + (uint32_t)mt * (16 * ASTR * 2) + kkB);
            #pragma unroll
            for (int np = 0; np < 2; ++np) {
                ldsm_x4(bh[np], bhBase + (uint32_t)np * (16 * ASTR * 2) + kkB);
                ldsm_x4(bl[np], blBase + (uint32_t)np * (16 * ASTR * 2) + kkB);
            }
            #pragma unroll
            for (int mt = 0; mt < 4; ++mt)
                #pragma unroll
                for (int nt = 0; nt < 4; ++nt) {
                    mma_f16(acc[mt][nt], ah[mt], &bh[nt >> 1][(nt & 1) * 2]);
                    mma_f16(acc[mt][nt], ah[mt], &bl[nt >> 1][(nt & 1) * 2]);
                }
        }

        if (ic + 1 < nchunk) {
            __half* d = smb + (1 - cur) * STAGE3;
            #pragma unroll
            for (int it = 0; it < 4; ++it) {
                int r = ldr + it * 32;
                putA(d, r, ldc4, pa[it]);
                putB(d + ARR, d + 2 * ARR, r, ldc4, pb[it]);
            }
        }
        __syncthreads();
    }

    #pragma unroll
    for (int mt = 0; mt < 4; ++mt) {
        int row = row0 + wm * 64 + mt * 16 + lr;
        #pragma unroll
        for (int nt = 0; nt < 4; ++nt) {
            int col = col0 + wn * 32 + nt * 8 + lc;
            *(float2*)&C[(size_t)row * N + col] =
                make_float2(acc[mt][nt][0], acc[mt][nt][1]);
            *(float2*)&C[(size_t)(row + 8) * N + col] =
                make_float2(acc[mt][nt][2], acc[mt][nt][3]);
        }
    }
}

// ---------------------------------------------------------------------------
// Per-head RMSNorm + RoPE + split into fp32 Q/K/V tensors.
// ---------------------------------------------------------------------------
__global__ __launch_bounds__(128) void prep_kernel(
    const float* __restrict__ cos_t, const float* __restrict__ sin_t,
    const float* __restrict__ q_ln, const float* __restrict__ k_ln)
{
    const int hh = blockIdx.x;
    const int s  = blockIdx.y;
    const int b  = blockIdx.z;
    const int d  = threadIdx.x;

    const size_t t = (size_t)b * SS + s;
    float x = g_qkv[t * QKVO + hh * HD + d];

    __shared__ float sy[HD];
    __shared__ float red[4];

    if (hh < NH + NKV) {
        float sq = x * x;
        #pragma unroll
        for (int o = 16; o; o >>= 1) sq += __shfl_xor_sync(0xFFFFFFFFu, sq, o);
        if ((d & 31) == 0) red[d >> 5] = sq;
        __syncthreads();
        float var = (red[0] + red[1] + red[2] + red[3]) * (1.f / HD);
        const float* w = (hh < NH) ? q_ln : k_ln;
        float y = x * rsqrtf(var + 1e-6f) * w[d];
        sy[d] = y;
        __syncthreads();

        float out = y;
        if (d < RR) {
            float c  = cos_t[t * RR + d];
            float sn = sin_t[t * RR + d];
            float rot = (d < RR / 2) ? -sy[d + RR / 2] : sy[d - RR / 2];
            out = fmaf(y, c, rot * sn);
        }
        if (hh < NH)
            g_q[(((size_t)(b * NH + hh)) * SS + s) * HD + d] = out;
        else
            g_k[(((size_t)(b * NKV + (hh - NH))) * SS + s) * HD + d] = out;
    } else {
        g_v[(((size_t)(b * NKV + (hh - NH - NKV))) * SS + s) * HD + d] = x;
    }
}

// ---------------------------------------------------------------------------
// Flash attention on fp16 mma.sync.
//   S = QK^T: Q split hi/lo (2 terms), K single fp16.
//   PV: P split hi/lo IN REGISTERS (2 terms), V single fp16.
// CTA: 128 q x (b,h), 8 warps (16 q-rows each). ldmatrix fragments.
// ---------------------------------------------------------------------------
#define DSTR 136

#define AQ_OFF  0                         // Qhi[128*DSTR], Qlo[128*DSTR]
#define AK_OFF  (2 * 128 * DSTR)          // Kh[64*DSTR]
#define AV_OFF  (AK_OFF + 64 * DSTR)      // Vh[64*DSTR]
#define ATTN2_F16 (AV_OFF + 64 * DSTR)
#define ATTN2_SMEM (ATTN2_F16 * 2)        // ~102 KB

__global__ __launch_bounds__(256, 1) void attn_mma_kernel()
{
    extern __shared__ __half smh[];
    __half* Qhi = smh + AQ_OFF;
    __half* Qlo = Qhi + 128 * DSTR;
    __half* Kh  = smh + AK_OFF;
    __half* Vh  = smh + AV_OFF;

    const int tid  = threadIdx.x;
    const int wid  = tid >> 5;
    const int lane = tid & 31;
    const int gr   = lane >> 2;
    const int gc   = (lane & 3) * 2;
    const int q0 = blockIdx.x * 128;
    const int bh = blockIdx.y;
    const int b = bh >> 4;
    const int h = bh & 15;
    const int hk = h / (NH / NKV);
    const int m0 = wid * 16;

    const float qscale = 0.08838834764831845f;  // 1/sqrt(128)

    const uint32_t sb = smem_u32(smh);
    const uint32_t laneA = ((lane & 15) * DSTR + (lane >> 4) * 8) * 2;
    const uint32_t laneB = (((lane >> 4) * 8 + (lane & 7)) * DSTR + ((lane >> 3) & 1) * 8) * 2;
    const uint32_t laneV = ((lane & 15) * DSTR + (lane >> 4) * 8) * 2;

    const uint32_t qBaseHi = sb + (uint32_t)(m0 * DSTR) * 2 + laneA;
    const uint32_t qBaseLo = qBaseHi + (uint32_t)(128 * DSTR) * 2;
    const uint32_t kBase   = sb + (uint32_t)AK_OFF * 2 + laneB;
    const uint32_t vBase   = sb + (uint32_t)AV_OFF * 2 + laneV;

    // ---- load Q tile 128x128, pre-scaled, split hi/lo ----
    {
        const float* qsrc = &g_q[(((size_t)(b * NH + h)) * SS + q0) * HD];
        #pragma unroll
        for (int it = 0; it < 16; ++it) {
            int f4 = tid + it * 256;
            int r  = f4 >> 5;
            int c4 = f4 & 31;
            float4 v = *(const float4*)&qsrc[(size_t)r * HD + c4 * 4];
            v.x *= qscale; v.y *= qscale; v.z *= qscale; v.w *= qscale;
            uint2 hi, lo;
            splitf16(v, hi, lo);
            *(uint2*)&Qhi[r * DSTR + c4 * 4] = hi;
            *(uint2*)&Qlo[r * DSTR + c4 * 4] = lo;
        }
    }

    float m_[2] = {-CUDART_INF_F, -CUDART_INF_F};
    float l_[2] = {0.f, 0.f};
    float O[16][4];
    #pragma unroll
    for (int nt = 0; nt < 16; ++nt)
        #pragma unroll
        for (int q = 0; q < 4; ++q) O[nt][q] = 0.f;

    const float* kbase = &g_k[((size_t)(b * NKV + hk)) * SS * HD];
    const float* vbase = &g_v[((size_t)(b * NKV + hk)) * SS * HD];

    __syncthreads();

    for (int kt = 0; kt < SS / 64; ++kt) {
        // ---- load K and V tiles 64x128 (single fp16) ----
        {
            const float* ks = kbase + (size_t)kt * 64 * HD;
            const float* vs = vbase + (size_t)kt * 64 * HD;
            #pragma unroll
            for (int it = 0; it < 8; ++it) {
                int f4 = tid + it * 256;
                int r  = f4 >> 5;
                int c4 = f4 & 31;
                float4 v = *(const float4*)&ks[(size_t)r * HD + c4 * 4];
                *(uint2*)&Kh[r * DSTR + c4 * 4] =
                    make_uint2(f16x2(v.x, v.y), f16x2(v.z, v.w));
                float4 w = *(const float4*)&vs[(size_t)r * HD + c4 * 4];
                *(uint2*)&Vh[r * DSTR + c4 * 4] =
                    make_uint2(f16x2(w.x, w.y), f16x2(w.z, w.w));
            }
        }
        __syncthreads();

        // ---- S = Q K^T (Q split, K single: 2 terms) ----
        float sc[8][4];
        #pragma unroll
        for (int nt = 0; nt < 8; ++nt)
            #pragma unroll
            for (int q = 0; q < 4; ++q) sc[nt][q] = 0.f;

        #pragma unroll
        for (int ks = 0; ks < 8; ++ks) {
            const uint32_t kkB = ks * 32;
            uint32_t qh[4], ql[4];
            ldsm_x4(qh, qBaseHi + kkB);
            ldsm_x4(ql, qBaseLo + kkB);
            #pragma unroll
            for (int np = 0; np < 4; ++np) {
                uint32_t kb4[4];
                ldsm_x4(kb4, kBase + (uint32_t)np * (16 * DSTR * 2) + kkB);
                mma_f16(sc[2*np],   qh, &kb4[0]);
                mma_f16(sc[2*np],   ql, &kb4[0]);
                mma_f16(sc[2*np+1], qh, &kb4[2]);
                mma_f16(sc[2*np+1], ql, &kb4[2]);
            }
        }

        // ---- online softmax (warp-local) ----
        float mx0 = -CUDART_INF_F, mx1 = -CUDART_INF_F;
        #pragma unroll
        for (int nt = 0; nt < 8; ++nt) {
            mx0 = fmaxf(mx0, fmaxf(sc[nt][0], sc[nt][1]));
            mx1 = fmaxf(mx1, fmaxf(sc[nt][2], sc[nt][3]));
        }
        mx0 = fmaxf(mx0, __shfl_xor_sync(0xFFFFFFFFu, mx0, 1));
        mx0 = fmaxf(mx0, __shfl_xor_sync(0xFFFFFFFFu, mx0, 2));
        mx1 = fmaxf(mx1, __shfl_xor_sync(0xFFFFFFFFu, mx1, 1));
        mx1 = fmaxf(mx1, __shfl_xor_sync(0xFFFFFFFFu, mx1, 2));

        float mn0 = fmaxf(m_[0], mx0);
        float mn1 = fmaxf(m_[1], mx1);
        float scl0 = __expf(m_[0] - mn0);
        float scl1 = __expf(m_[1] - mn1);
        m_[0] = mn0; m_[1] = mn1;

        // exp, pack P hi/lo into registers, row sums
        uint32_t pah[4][4], pal[4][4];
        float rs0 = 0.f, rs1 = 0.f;
        #pragma unroll
        for (int k2 = 0; k2 < 4; ++k2) {
            float p00 = __expf(sc[2*k2][0] - mn0);
            float p01 = __expf(sc[2*k2][1] - mn0);
            float p02 = __expf(sc[2*k2][2] - mn1);
            float p03 = __expf(sc[2*k2][3] - mn1);
            float p10 = __expf(sc[2*k2+1][0] - mn0);
            float p11 = __expf(sc[2*k2+1][1] - mn0);
            float p12 = __expf(sc[2*k2+1][2] - mn1);
            float p13 = __expf(sc[2*k2+1][3] - mn1);
            rs0 += p00 + p01 + p10 + p11;
            rs1 += p02 + p03 + p12 + p13;
            uint32_t hh;
            hh = f16x2(p00, p01); pah[k2][0] = hh;
            {   __half2 t = *(__half2*)&hh;
                pal[k2][0] = f16x2(p00 - __low2float(t), p01 - __high2float(t)); }
            hh = f16x2(p02, p03); pah[k2][1] = hh;
            {   __half2 t = *(__half2*)&hh;
                pal[k2][1] = f16x2(p02 - __low2float(t), p03 - __high2float(t)); }
            hh = f16x2(p10, p11); pah[k2][2] = hh;
            {   __half2 t = *(__half2*)&hh;
                pal[k2][2] = f16x2(p10 - __low2float(t), p11 - __high2float(t)); }
            hh = f16x2(p12, p13); pah[k2][3] = hh;
            {   __half2 t = *(__half2*)&hh;
                pal[k2][3] = f16x2(p12 - __low2float(t), p13 - __high2float(t)); }
        }
        rs0 += __shfl_xor_sync(0xFFFFFFFFu, rs0, 1);
        rs0 += __shfl_xor_sync(0xFFFFFFFFu, rs0, 2);
        rs1 += __shfl_xor_sync(0xFFFFFFFFu, rs1, 1);
        rs1 += __shfl_xor_sync(0xFFFFFFFFu, rs1, 2);
        l_[0] = l_[0] * scl0 + rs0;
        l_[1] = l_[1] * scl1 + rs1;

        #pragma unroll
        for (int nt = 0; nt < 16; ++nt) {
            O[nt][0] *= scl0; O[nt][1] *= scl0;
            O[nt][2] *= scl1; O[nt][3] *= scl1;
        }

        // ---- PV: P split (regs), V single: 2 terms ----
        #pragma unroll
        for (int k2 = 0; k2 < 4; ++k2) {
            const uint32_t kOff = (uint32_t)k2 * (16 * DSTR * 2);
            #pragma unroll
            for (int np = 0; np < 8; ++np) {
                uint32_t vb4[4];
                ldsm_x4_t(vb4, vBase + kOff + (uint32_t)np * 32);
                mma_f16(O[2*np],   pah[k2], &vb4[0]);
                mma_f16(O[2*np],   pal[k2], &vb4[0]);
                mma_f16(O[2*np+1], pah[k2], &vb4[2]);
                mma_f16(O[2*np+1], pal[k2], &vb4[2]);
            }
        }
        __syncthreads();
    }

    // ---- epilogue: normalize, write g_attn[b, s, h*128 + c] ----
    const float inv0 = 1.f / l_[0];
    const float inv1 = 1.f / l_[1];
    const int s0 = q0 + m0 + gr;
    #pragma unroll
    for (int nt = 0; nt < 16; ++nt) {
        int col = nt * 8 + gc;
        size_t off0 = (((size_t)b * SS + s0) * NH + h) * HD + col;
        size_t off1 = (((size_t)b * SS + s0 + 8) * NH + h) * HD + col;
        *(float2*)&g_attn[off0] = make_float2(O[nt][0] * inv0, O[nt][1] * inv0);
        *(float2*)&g_attn[off1] = make_float2(O[nt][2] * inv1, O[nt][3] * inv1);
    }
}

// ---------------------------------------------------------------------------
extern "C" void kernel_launch(void* const* d_in, const int* in_sizes, int n_in,
                              void* d_out, int out_size)
{
    const float* hidden  = (const float*)d_in[0];
    const float* cos_t   = (const float*)d_in[1];
    const float* sin_t   = (const float*)d_in[2];
    const float* w_qkv   = (const float*)d_in[3];
    const float* q_ln    = (const float*)d_in[4];
    const float* k_ln    = (const float*)d_in[5];
    const float* w_dense = (const float*)d_in[6];
    float* out = (float*)d_out;

    void *p_qkv = nullptr, *p_attn = nullptr;
    cudaGetSymbolAddress(&p_qkv, g_qkv);
    cudaGetSymbolAddress(&p_attn, g_attn);
    float* qkv  = (float*)p_qkv;
    float* attn = (float*)p_attn;

    cudaFuncSetAttribute(gemm_mma_kernel,
                         cudaFuncAttributeMaxDynamicSharedMemorySize, GEMM_SMEM);
    cudaFuncSetAttribute(attn_mma_kernel,
                         cudaFuncAttributeMaxDynamicSharedMemorySize, ATTN2_SMEM);

    // 1) QKV projection (fp16 2-term)
    gemm_mma_kernel<<<dim3(QKVO / 128, NTOK / 128), 256, GEMM_SMEM>>>(
        hidden, w_qkv, qkv, QKVO, HID);

    // 2) RMSNorm + RoPE + split
    prep_kernel<<<dim3(NH + 2 * NKV, SS, BB), 128>>>(cos_t, sin_t, q_ln, k_ln);

    // 3) Flash attention (fp16 2-term S and PV)
    attn_mma_kernel<<<dim3(SS / 128, BB * NH), 256, ATTN2_SMEM>>>();

    // 4) Output projection (fp16 2-term)
    gemm_mma_kernel<<<dim3(HID / 128, NTOK / 128), 256, GEMM_SMEM>>>(
        attn, w_dense, out, HID, HID);
}

// round 12
// speedup vs baseline: 2.1557x; 1.0681x over previous
#include <cuda_runtime.h>
#include <cuda_fp16.h>
#include <math_constants.h>
#include <cstdint>

// Problem dims
#define BB   2
#define SS   2048
#define HID  2048
#define NH   16
#define NKV  4
#define HD   128
#define RR   64
#define NTOK (BB*SS)          // 4096
#define QKVO ((NH+2*NKV)*HD)  // 3072

// Scratch (device globals; no allocation allowed)
__device__ float  g_qkv[(size_t)NTOK * QKVO];
__device__ __half g_qh[(size_t)BB * NH  * SS * HD];   // Q hi (pre-scaled)
__device__ __half g_ql[(size_t)BB * NH  * SS * HD];   // Q lo
__device__ __half g_kh[(size_t)BB * NKV * SS * HD];   // K single fp16
__device__ __half g_vh[(size_t)BB * NKV * SS * HD];   // V single fp16
__device__ float  g_attn[(size_t)NTOK * (NH*HD)];

// ---------------------------------------------------------------------------
// PTX helpers (base PTX only — compute_103-safe)
// ---------------------------------------------------------------------------
__device__ __forceinline__ void mma_f16(float* c, const uint32_t* a, const uint32_t* b) {
    asm volatile(
        "mma.sync.aligned.m16n8k16.row.col.f32.f16.f16.f32 "
        "{%0,%1,%2,%3}, {%4,%5,%6,%7}, {%8,%9}, {%0,%1,%2,%3};"
        : "+f"(c[0]), "+f"(c[1]), "+f"(c[2]), "+f"(c[3])
        : "r"(a[0]), "r"(a[1]), "r"(a[2]), "r"(a[3]), "r"(b[0]), "r"(b[1]));
}

__device__ __forceinline__ void ldsm_x4(uint32_t* r, uint32_t addr) {
    asm volatile("ldmatrix.sync.aligned.m8n8.x4.shared.b16 {%0,%1,%2,%3}, [%4];"
        : "=r"(r[0]), "=r"(r[1]), "=r"(r[2]), "=r"(r[3]) : "r"(addr));
}

__device__ __forceinline__ void ldsm_x4_t(uint32_t* r, uint32_t addr) {
    asm volatile("ldmatrix.sync.aligned.m8n8.x4.trans.shared.b16 {%0,%1,%2,%3}, [%4];"
        : "=r"(r[0]), "=r"(r[1]), "=r"(r[2]), "=r"(r[3]) : "r"(addr));
}

__device__ __forceinline__ uint32_t smem_u32(const void* p) {
    uint32_t a;
    asm("{ .reg .u64 t; cvta.to.shared.u64 t, %1; cvt.u32.u64 %0, t; }"
        : "=r"(a) : "l"(p));
    return a;
}

#define CP_ASYNC16(saddr, gptr) \
    asm volatile("cp.async.cg.shared.global [%0], [%1], 16;" \
                 :: "r"(saddr), "l"(gptr))
#define CP_COMMIT() asm volatile("cp.async.commit_group;" ::: "memory")
#define CP_WAIT(n)  asm volatile("cp.async.wait_group %0;" :: "n"(n) : "memory")

__device__ __forceinline__ uint32_t f16x2(float x, float y) {
    __half2 h = __floats2half2_rn(x, y);
    return *(uint32_t*)&h;
}

__device__ __forceinline__ void splitf16(float4 v, uint2& hi, uint2& lo) {
    uint32_t h0 = f16x2(v.x, v.y);
    uint32_t h1 = f16x2(v.z, v.w);
    __half2 hh0 = *(__half2*)&h0;
    __half2 hh1 = *(__half2*)&h1;
    uint32_t l0 = f16x2(v.x - __low2float(hh0), v.y - __high2float(hh0));
    uint32_t l1 = f16x2(v.z - __low2float(hh1), v.w - __high2float(hh1));
    hi = make_uint2(h0, h1);
    lo = make_uint2(l0, l1);
}

// ---------------------------------------------------------------------------
// Tensor GEMM (round-11 proven, 245us): C[M,N] = A[M,K] * B[N,K]^T.
// fp16 2-term: A single fp16, B split hi/lo.
// ---------------------------------------------------------------------------
#define TBK 32
#define ASTR 40
#define ARR (128 * ASTR)
#define STAGE3 (3 * ARR)
#define GEMM_SMEM (2 * STAGE3 * 2)

__global__ __launch_bounds__(256, 1) void gemm_mma_kernel(
    const float* __restrict__ A, const float* __restrict__ Bm,
    float* __restrict__ C, int N, int K)
{
    extern __shared__ __half smb[];
    const int tid  = threadIdx.x;
    const int wid  = tid >> 5;
    const int lane = tid & 31;
    const int wm   = wid >> 2;
    const int wn   = wid & 3;
    const int row0 = blockIdx.y * 128;
    const int col0 = blockIdx.x * 128;

    const int lr = lane >> 2;
    const int lc = (lane & 3) * 2;

    const int ldr  = tid >> 3;
    const int ldc4 = (tid & 7) * 4;

    const uint32_t sb = smem_u32(smb);
    const uint32_t laneA = ((lane & 15) * ASTR + (lane >> 4) * 8) * 2;
    const uint32_t laneB = (((lane >> 4) * 8 + (lane & 7)) * ASTR + ((lane >> 3) & 1) * 8) * 2;

    float acc[4][4][4];
    #pragma unroll
    for (int mt = 0; mt < 4; ++mt)
        #pragma unroll
        for (int nt = 0; nt < 4; ++nt)
            #pragma unroll
            for (int q = 0; q < 4; ++q) acc[mt][nt][q] = 0.f;

    const int nchunk = K / TBK;

    auto putA = [&](__half* dst, int r, int c, float4 v) {
        *(uint2*)&dst[r * ASTR + c] = make_uint2(f16x2(v.x, v.y), f16x2(v.z, v.w));
    };
    auto putB = [&](__half* hi, __half* lo, int r, int c, float4 v) {
        uint2 h, l;
        splitf16(v, h, l);
        *(uint2*)&hi[r * ASTR + c] = h;
        *(uint2*)&lo[r * ASTR + c] = l;
    };

    float4 pa[4], pb[4];

    {
        const float* Ab = A + (size_t)row0 * K;
        const float* Bb = Bm + (size_t)col0 * K;
        __half* s = smb;
        #pragma unroll
        for (int it = 0; it < 4; ++it) {
            int r = ldr + it * 32;
            float4 va = *(const float4*)&Ab[(size_t)r * K + ldc4];
            putA(s, r, ldc4, va);
            float4 vb = *(const float4*)&Bb[(size_t)r * K + ldc4];
            putB(s + ARR, s + 2 * ARR, r, ldc4, vb);
        }
    }
    __syncthreads();

    for (int ic = 0; ic < nchunk; ++ic) {
        const int cur = ic & 1;
        const uint32_t stOff = (uint32_t)cur * (STAGE3 * 2);
        const uint32_t aBase  = sb + stOff + (uint32_t)(wm * 64) * (ASTR * 2) + laneA;
        const uint32_t bhBase = sb + stOff + (uint32_t)ARR * 2
                              + (uint32_t)(wn * 32) * (ASTR * 2) + laneB;
        const uint32_t blBase = bhBase + (uint32_t)ARR * 2;

        if (ic + 1 < nchunk) {
            const float* Ab = A + (size_t)row0 * K + (ic + 1) * TBK;
            const float* Bb = Bm + (size_t)col0 * K + (ic + 1) * TBK;
            #pragma unroll
            for (int it = 0; it < 4; ++it) {
                int r = ldr + it * 32;
                pa[it] = *(const float4*)&Ab[(size_t)r * K + ldc4];
                pb[it] = *(const float4*)&Bb[(size_t)r * K + ldc4];
            }
        }

        #pragma unroll
        for (int ks = 0; ks < 2; ++ks) {
            const uint32_t kkB = ks * 32;
            uint32_t ah[4][4], bh[2][4], bl[2][4];
            #pragma unroll
            for (int mt = 0; mt < 4; ++mt)
                ldsm_x4(ah[mt], aBase + (uint32_t)mt * (16 * ASTR * 2) + kkB);
            #pragma unroll
            for (int np = 0; np < 2; ++np) {
                ldsm_x4(bh[np], bhBase + (uint32_t)np * (16 * ASTR * 2) + kkB);
                ldsm_x4(bl[np], blBase + (uint32_t)np * (16 * ASTR * 2) + kkB);
            }
            #pragma unroll
            for (int mt = 0; mt < 4; ++mt)
                #pragma unroll
                for (int nt = 0; nt < 4; ++nt) {
                    mma_f16(acc[mt][nt], ah[mt], &bh[nt >> 1][(nt & 1) * 2]);
                    mma_f16(acc[mt][nt], ah[mt], &bl[nt >> 1][(nt & 1) * 2]);
                }
        }

        if (ic + 1 < nchunk) {
            __half* d = smb + (1 - cur) * STAGE3;
            #pragma unroll
            for (int it = 0; it < 4; ++it) {
                int r = ldr + it * 32;
                putA(d, r, ldc4, pa[it]);
                putB(d + ARR, d + 2 * ARR, r, ldc4, pb[it]);
            }
        }
        __syncthreads();
    }

    #pragma unroll
    for (int mt = 0; mt < 4; ++mt) {
        int row = row0 + wm * 64 + mt * 16 + lr;
        #pragma unroll
        for (int nt = 0; nt < 4; ++nt) {
            int col = col0 + wn * 32 + nt * 8 + lc;
            *(float2*)&C[(size_t)row * N + col] =
                make_float2(acc[mt][nt][0], acc[mt][nt][1]);
            *(float2*)&C[(size_t)(row + 8) * N + col] =
                make_float2(acc[mt][nt][2], acc[mt][nt][3]);
        }
    }
}

// ---------------------------------------------------------------------------
// Per-head RMSNorm + RoPE. Emits fp16: Q (pre-scaled, hi/lo), K, V (single).
// Values bit-identical to round 11's inline conversions.
// ---------------------------------------------------------------------------
__global__ __launch_bounds__(128) void prep_kernel(
    const float* __restrict__ cos_t, const float* __restrict__ sin_t,
    const float* __restrict__ q_ln, const float* __restrict__ k_ln)
{
    const int hh = blockIdx.x;
    const int s  = blockIdx.y;
    const int b  = blockIdx.z;
    const int d  = threadIdx.x;

    const size_t t = (size_t)b * SS + s;
    float x = g_qkv[t * QKVO + hh * HD + d];

    __shared__ float sy[HD];
    __shared__ float red[4];

    const float qscale = 0.08838834764831845f;  // 1/sqrt(128)

    if (hh < NH + NKV) {
        float sq = x * x;
        #pragma unroll
        for (int o = 16; o; o >>= 1) sq += __shfl_xor_sync(0xFFFFFFFFu, sq, o);
        if ((d & 31) == 0) red[d >> 5] = sq;
        __syncthreads();
        float var = (red[0] + red[1] + red[2] + red[3]) * (1.f / HD);
        const float* w = (hh < NH) ? q_ln : k_ln;
        float y = x * rsqrtf(var + 1e-6f) * w[d];
        sy[d] = y;
        __syncthreads();

        float out = y;
        if (d < RR) {
            float c  = cos_t[t * RR + d];
            float sn = sin_t[t * RR + d];
            float rot = (d < RR / 2) ? -sy[d + RR / 2] : sy[d - RR / 2];
            out = fmaf(y, c, rot * sn);
        }
        if (hh < NH) {
            out *= qscale;
            size_t off = (((size_t)(b * NH + hh)) * SS + s) * HD + d;
            __half hi = __float2half(out);
            g_qh[off] = hi;
            g_ql[off] = __float2half(out - __half2float(hi));
        } else {
            size_t off = (((size_t)(b * NKV + (hh - NH))) * SS + s) * HD + d;
            g_kh[off] = __float2half(out);
        }
    } else {
        size_t off = (((size_t)(b * NKV + (hh - NH - NKV))) * SS + s) * HD + d;
        g_vh[off] = __float2half(x);
    }
}

// ---------------------------------------------------------------------------
// Flash attention on fp16 mma.sync, cp.async double-buffered K/V (fp16 in gmem).
//   S = QK^T: Q split hi/lo (2 terms), K single fp16.
//   PV: P split hi/lo in registers (2 terms), V single fp16.
// CTA: 128 q x (b,h), 8 warps. No conversions in the main loop.
// ---------------------------------------------------------------------------
#define DSTR 136
#define SKV (2 * 64 * DSTR)               // fp16 per stage: Kh + Vh
#define AKV_OFF (2 * 128 * DSTR)          // after Qhi, Qlo
#define ATTN2_F16 (AKV_OFF + 2 * SKV)
#define ATTN2_SMEM (ATTN2_F16 * 2)        // ~136 KB

__global__ __launch_bounds__(256, 1) void attn_mma_kernel()
{
    extern __shared__ __half smh[];
    __half* Qhi = smh;
    __half* Qlo = Qhi + 128 * DSTR;

    const int tid  = threadIdx.x;
    const int wid  = tid >> 5;
    const int lane = tid & 31;
    const int gr   = lane >> 2;
    const int gc   = (lane & 3) * 2;
    const int q0 = blockIdx.x * 128;
    const int bh = blockIdx.y;
    const int b = bh >> 4;
    const int h = bh & 15;
    const int hk = h / (NH / NKV);
    const int m0 = wid * 16;

    const uint32_t sb = smem_u32(smh);
    const uint32_t kvOff = sb + (uint32_t)AKV_OFF * 2;
    const uint32_t laneA = ((lane & 15) * DSTR + (lane >> 4) * 8) * 2;
    const uint32_t laneB = (((lane >> 4) * 8 + (lane & 7)) * DSTR + ((lane >> 3) & 1) * 8) * 2;
    const uint32_t laneV = ((lane & 15) * DSTR + (lane >> 4) * 8) * 2;

    const uint32_t qBaseHi = sb + (uint32_t)(m0 * DSTR) * 2 + laneA;
    const uint32_t qBaseLo = qBaseHi + (uint32_t)(128 * DSTR) * 2;

    const size_t kvg = ((size_t)(b * NKV + hk)) * SS * HD;
    const __half* ksrc = g_kh + kvg;
    const __half* vsrc = g_vh + kvg;

    auto issue_kv = [&](int kt, int stg) {
        uint32_t sbase = kvOff + (uint32_t)stg * (SKV * 2);
        size_t goff = (size_t)kt * 64 * HD;
        #pragma unroll
        for (int it = 0; it < 4; ++it) {
            int id = tid + it * 256;      // 0..1023: 64 rows x 16 chunks
            int r = id >> 4, g = id & 15;
            uint32_t so = (uint32_t)(r * DSTR * 2 + g * 16);
            CP_ASYNC16(sbase + so, ksrc + goff + (size_t)r * HD + g * 8);
            CP_ASYNC16(sbase + (uint32_t)(SKV) + so, vsrc + goff + (size_t)r * HD + g * 8);
        }
    };

    // ---- load Q tile (fp16 hi/lo, already scaled) ----
    {
        const __half* qh = &g_qh[(((size_t)(b * NH + h)) * SS + q0) * HD];
        const __half* ql = &g_ql[(((size_t)(b * NH + h)) * SS + q0) * HD];
        #pragma unroll
        for (int it = 0; it < 8; ++it) {
            int id = tid + it * 256;
            int r = id >> 4, g = id & 15;
            *(uint4*)&Qhi[r * DSTR + g * 8] = *(const uint4*)&qh[(size_t)r * HD + g * 8];
            *(uint4*)&Qlo[r * DSTR + g * 8] = *(const uint4*)&ql[(size_t)r * HD + g * 8];
        }
    }

    issue_kv(0, 0);
    CP_COMMIT();

    float m_[2] = {-CUDART_INF_F, -CUDART_INF_F};
    float l_[2] = {0.f, 0.f};
    float O[16][4];
    #pragma unroll
    for (int nt = 0; nt < 16; ++nt)
        #pragma unroll
        for (int q = 0; q < 4; ++q) O[nt][q] = 0.f;

    __syncthreads();   // Q visible to all warps before first compute

    for (int kt = 0; kt < SS / 64; ++kt) {
        const int cur = kt & 1;
        if (kt + 1 < SS / 64) {
            issue_kv(kt + 1, 1 - cur);
            CP_COMMIT();
            CP_WAIT(1);
        } else {
            CP_WAIT(0);
        }
        __syncthreads();

        const uint32_t st = kvOff + (uint32_t)cur * (SKV * 2);
        const uint32_t kBase = st + laneB;
        const uint32_t vBase = st + (uint32_t)SKV + laneV;   // SKV in f16 units -> *2 bytes? (SKV*2 bytes offset)

        // NOTE: SKV is in fp16 units; byte offset is SKV*2. kBase uses st directly;
        // vBase must add SKV*2 bytes:
        const uint32_t vBaseB = st + (uint32_t)(64 * DSTR) * 2 * 1 + laneV; // Kh is 64*DSTR f16 = 64*DSTR*2 bytes

        // ---- S = Q K^T (Q split, K single: 2 terms) ----
        float sc[8][4];
        #pragma unroll
        for (int nt = 0; nt < 8; ++nt)
            #pragma unroll
            for (int q = 0; q < 4; ++q) sc[nt][q] = 0.f;

        #pragma unroll
        for (int ks = 0; ks < 8; ++ks) {
            const uint32_t kkB = ks * 32;
            uint32_t qh4[4], ql4[4];
            ldsm_x4(qh4, qBaseHi + kkB);
            ldsm_x4(ql4, qBaseLo + kkB);
            #pragma unroll
            for (int np = 0; np < 4; ++np) {
                uint32_t kb4[4];
                ldsm_x4(kb4, kBase + (uint32_t)np * (16 * DSTR * 2) + kkB);
                mma_f16(sc[2*np],   qh4, &kb4[0]);
                mma_f16(sc[2*np],   ql4, &kb4[0]);
                mma_f16(sc[2*np+1], qh4, &kb4[2]);
                mma_f16(sc[2*np+1], ql4, &kb4[2]);
            }
        }

        // ---- online softmax (warp-local) ----
        float mx0 = -CUDART_INF_F, mx1 = -CUDART_INF_F;
        #pragma unroll
        for (int nt = 0; nt < 8; ++nt) {
            mx0 = fmaxf(mx0, fmaxf(sc[nt][0], sc[nt][1]));
            mx1 = fmaxf(mx1, fmaxf(sc[nt][2], sc[nt][3]));
        }
        mx0 = fmaxf(mx0, __shfl_xor_sync(0xFFFFFFFFu, mx0, 1));
        mx0 = fmaxf(mx0, __shfl_xor_sync(0xFFFFFFFFu, mx0, 2));
        mx1 = fmaxf(mx1, __shfl_xor_sync(0xFFFFFFFFu, mx1, 1));
        mx1 = fmaxf(mx1, __shfl_xor_sync(0xFFFFFFFFu, mx1, 2));

        float mn0 = fmaxf(m_[0], mx0);
        float mn1 = fmaxf(m_[1], mx1);
        float scl0 = __expf(m_[0] - mn0);
        float scl1 = __expf(m_[1] - mn1);
        m_[0] = mn0; m_[1] = mn1;

        uint32_t pah[4][4], pal[4][4];
        float rs0 = 0.f, rs1 = 0.f;
        #pragma unroll
        for (int k2 = 0; k2 < 4; ++k2) {
            float p00 = __expf(sc[2*k2][0] - mn0);
            float p01 = __expf(sc[2*k2][1] - mn0);
            float p02 = __expf(sc[2*k2][2] - mn1);
            float p03 = __expf(sc[2*k2][3] - mn1);
            float p10 = __expf(sc[2*k2+1][0] - mn0);
            float p11 = __expf(sc[2*k2+1][1] - mn0);
            float p12 = __expf(sc[2*k2+1][2] - mn1);
            float p13 = __expf(sc[2*k2+1][3] - mn1);
            rs0 += p00 + p01 + p10 + p11;
            rs1 += p02 + p03 + p12 + p13;
            uint32_t hh;
            hh = f16x2(p00, p01); pah[k2][0] = hh;
            {   __half2 t = *(__half2*)&hh;
                pal[k2][0] = f16x2(p00 - __low2float(t), p01 - __high2float(t)); }
            hh = f16x2(p02, p03); pah[k2][1] = hh;
            {   __half2 t = *(__half2*)&hh;
                pal[k2][1] = f16x2(p02 - __low2float(t), p03 - __high2float(t)); }
            hh = f16x2(p10, p11); pah[k2][2] = hh;
            {   __half2 t = *(__half2*)&hh;
                pal[k2][2] = f16x2(p10 - __low2float(t), p11 - __high2float(t)); }
            hh = f16x2(p12, p13); pah[k2][3] = hh;
            {   __half2 t = *(__half2*)&hh;
                pal[k2][3] = f16x2(p12 - __low2float(t), p13 - __high2float(t)); }
        }
        rs0 += __shfl_xor_sync(0xFFFFFFFFu, rs0, 1);
        rs0 += __shfl_xor_sync(0xFFFFFFFFu, rs0, 2);
        rs1 += __shfl_xor_sync(0xFFFFFFFFu, rs1, 1);
        rs1 += __shfl_xor_sync(0xFFFFFFFFu, rs1, 2);
        l_[0] = l_[0] * scl0 + rs0;
        l_[1] = l_[1] * scl1 + rs1;

        #pragma unroll
        for (int nt = 0; nt < 16; ++nt) {
            O[nt][0] *= scl0; O[nt][1] *= scl0;
            O[nt][2] *= scl1; O[nt][3] *= scl1;
        }

        // ---- PV: P split (regs), V single: 2 terms ----
        #pragma unroll
        for (int k2 = 0; k2 < 4; ++k2) {
            const uint32_t kOff = (uint32_t)k2 * (16 * DSTR * 2);
            #pragma unroll
            for (int np = 0; np < 8; ++np) {
                uint32_t vb4[4];
                ldsm_x4_t(vb4, vBaseB + kOff + (uint32_t)np * 32);
                mma_f16(O[2*np],   pah[k2], &vb4[0]);
                mma_f16(O[2*np],   pal[k2], &vb4[0]);
                mma_f16(O[2*np+1], pah[k2], &vb4[2]);
                mma_f16(O[2*np+1], pal[k2], &vb4[2]);
            }
        }
        __syncthreads();
    }

    // ---- epilogue: normalize, write g_attn[b, s, h*128 + c] ----
    const float inv0 = 1.f / l_[0];
    const float inv1 = 1.f / l_[1];
    const int s0 = q0 + m0 + gr;
    #pragma unroll
    for (int nt = 0; nt < 16; ++nt) {
        int col = nt * 8 + gc;
        size_t off0 = (((size_t)b * SS + s0) * NH + h) * HD + col;
        size_t off1 = (((size_t)b * SS + s0 + 8) * NH + h) * HD + col;
        *(float2*)&g_attn[off0] = make_float2(O[nt][0] * inv0, O[nt][1] * inv0);
        *(float2*)&g_attn[off1] = make_float2(O[nt][2] * inv1, O[nt][3] * inv1);
    }
}

// ---------------------------------------------------------------------------
extern "C" void kernel_launch(void* const* d_in, const int* in_sizes, int n_in,
                              void* d_out, int out_size)
{
    const float* hidden  = (const float*)d_in[0];
    const float* cos_t   = (const float*)d_in[1];
    const float* sin_t   = (const float*)d_in[2];
    const float* w_qkv   = (const float*)d_in[3];
    const float* q_ln    = (const float*)d_in[4];
    const float* k_ln    = (const float*)d_in[5];
    const float* w_dense = (const float*)d_in[6];
    float* out = (float*)d_out;

    void *p_qkv = nullptr, *p_attn = nullptr;
    cudaGetSymbolAddress(&p_qkv, g_qkv);
    cudaGetSymbolAddress(&p_attn, g_attn);
    float* qkv  = (float*)p_qkv;
    float* attn = (float*)p_attn;

    cudaFuncSetAttribute(gemm_mma_kernel,
                         cudaFuncAttributeMaxDynamicSharedMemorySize, GEMM_SMEM);
    cudaFuncSetAttribute(attn_mma_kernel,
                         cudaFuncAttributeMaxDynamicSharedMemorySize, ATTN2_SMEM);

    // 1) QKV projection (fp16 2-term, proven)
    gemm_mma_kernel<<<dim3(QKVO / 128, NTOK / 128), 256, GEMM_SMEM>>>(
        hidden, w_qkv, qkv, QKVO, HID);

    // 2) RMSNorm + RoPE -> fp16 Q(hi/lo)/K/V
    prep_kernel<<<dim3(NH + 2 * NKV, SS, BB), 128>>>(cos_t, sin_t, q_ln, k_ln);

    // 3) Flash attention (cp.async double-buffered fp16 K/V)
    attn_mma_kernel<<<dim3(SS / 128, BB * NH), 256, ATTN2_SMEM>>>();

    // 4) Output projection (fp16 2-term, proven)
    gemm_mma_kernel<<<dim3(HID / 128, NTOK / 128), 256, GEMM_SMEM>>>(
        attn, w_dense, out, HID, HID);
}

// round 13
// speedup vs baseline: 2.1862x; 1.0142x over previous
#include <cuda_runtime.h>
#include <cuda_fp16.h>
#include <math_constants.h>
#include <cstdint>

// Problem dims
#define BB   2
#define SS   2048
#define HID  2048
#define NH   16
#define NKV  4
#define HD   128
#define RR   64
#define NTOK (BB*SS)          // 4096
#define QKVO ((NH+2*NKV)*HD)  // 3072

// Scratch (device globals; no allocation allowed)
__device__ float  g_qkv[(size_t)NTOK * QKVO];
__device__ __half g_qh[(size_t)BB * NH  * SS * HD];   // Q hi (pre-scaled)
__device__ __half g_ql[(size_t)BB * NH  * SS * HD];   // Q lo
__device__ __half g_kh[(size_t)BB * NKV * SS * HD];   // K single fp16
__device__ __half g_vh[(size_t)BB * NKV * SS * HD];   // V single fp16
__device__ __half g_attnh[(size_t)NTOK * (NH*HD)];    // attn out, single fp16

// ---------------------------------------------------------------------------
// PTX helpers (base PTX only — compute_103-safe)
// ---------------------------------------------------------------------------
__device__ __forceinline__ void mma_f16(float* c, const uint32_t* a, const uint32_t* b) {
    asm volatile(
        "mma.sync.aligned.m16n8k16.row.col.f32.f16.f16.f32 "
        "{%0,%1,%2,%3}, {%4,%5,%6,%7}, {%8,%9}, {%0,%1,%2,%3};"
        : "+f"(c[0]), "+f"(c[1]), "+f"(c[2]), "+f"(c[3])
        : "r"(a[0]), "r"(a[1]), "r"(a[2]), "r"(a[3]), "r"(b[0]), "r"(b[1]));
}

__device__ __forceinline__ void ldsm_x4(uint32_t* r, uint32_t addr) {
    asm volatile("ldmatrix.sync.aligned.m8n8.x4.shared.b16 {%0,%1,%2,%3}, [%4];"
        : "=r"(r[0]), "=r"(r[1]), "=r"(r[2]), "=r"(r[3]) : "r"(addr));
}

__device__ __forceinline__ void ldsm_x4_t(uint32_t* r, uint32_t addr) {
    asm volatile("ldmatrix.sync.aligned.m8n8.x4.trans.shared.b16 {%0,%1,%2,%3}, [%4];"
        : "=r"(r[0]), "=r"(r[1]), "=r"(r[2]), "=r"(r[3]) : "r"(addr));
}

__device__ __forceinline__ uint32_t smem_u32(const void* p) {
    uint32_t a;
    asm("{ .reg .u64 t; cvta.to.shared.u64 t, %1; cvt.u32.u64 %0, t; }"
        : "=r"(a) : "l"(p));
    return a;
}

#define CP_ASYNC16(saddr, gptr) \
    asm volatile("cp.async.cg.shared.global [%0], [%1], 16;" \
                 :: "r"(saddr), "l"(gptr))
#define CP_COMMIT() asm volatile("cp.async.commit_group;" ::: "memory")
#define CP_WAIT(n)  asm volatile("cp.async.wait_group %0;" :: "n"(n) : "memory")

__device__ __forceinline__ uint32_t f16x2(float x, float y) {
    __half2 h = __floats2half2_rn(x, y);
    return *(uint32_t*)&h;
}

__device__ __forceinline__ void splitf16(float4 v, uint2& hi, uint2& lo) {
    uint32_t h0 = f16x2(v.x, v.y);
    uint32_t h1 = f16x2(v.z, v.w);
    __half2 hh0 = *(__half2*)&h0;
    __half2 hh1 = *(__half2*)&h1;
    uint32_t l0 = f16x2(v.x - __low2float(hh0), v.y - __high2float(hh0));
    uint32_t l1 = f16x2(v.z - __low2float(hh1), v.w - __high2float(hh1));
    hi = make_uint2(h0, h1);
    lo = make_uint2(l0, l1);
}

// ---------------------------------------------------------------------------
// GEMM shared geometry
// ---------------------------------------------------------------------------
#define TBK 32
#define ASTR 40
#define ARR (128 * ASTR)
#define STAGE3 (3 * ARR)
#define GEMM_SMEM (2 * STAGE3 * 2)

// ---------------------------------------------------------------------------
// GEMM v1 (round-11 proven): A fp32 (inline fp16), B fp32 (inline split).
// ---------------------------------------------------------------------------
__global__ __launch_bounds__(256, 1) void gemm_mma_kernel(
    const float* __restrict__ A, const float* __restrict__ Bm,
    float* __restrict__ C, int N, int K)
{
    extern __shared__ __half smb[];
    const int tid  = threadIdx.x;
    const int wid  = tid >> 5;
    const int lane = tid & 31;
    const int wm   = wid >> 2;
    const int wn   = wid & 3;
    const int row0 = blockIdx.y * 128;
    const int col0 = blockIdx.x * 128;

    const int lr = lane >> 2;
    const int lc = (lane & 3) * 2;

    const int ldr  = tid >> 3;
    const int ldc4 = (tid & 7) * 4;

    const uint32_t sb = smem_u32(smb);
    const uint32_t laneA = ((lane & 15) * ASTR + (lane >> 4) * 8) * 2;
    const uint32_t laneB = (((lane >> 4) * 8 + (lane & 7)) * ASTR + ((lane >> 3) & 1) * 8) * 2;

    float acc[4][4][4];
    #pragma unroll
    for (int mt = 0; mt < 4; ++mt)
        #pragma unroll
        for (int nt = 0; nt < 4; ++nt)
            #pragma unroll
            for (int q = 0; q < 4; ++q) acc[mt][nt][q] = 0.f;

    const int nchunk = K / TBK;

    auto putA = [&](__half* dst, int r, int c, float4 v) {
        *(uint2*)&dst[r * ASTR + c] = make_uint2(f16x2(v.x, v.y), f16x2(v.z, v.w));
    };
    auto putB = [&](__half* hi, __half* lo, int r, int c, float4 v) {
        uint2 h, l;
        splitf16(v, h, l);
        *(uint2*)&hi[r * ASTR + c] = h;
        *(uint2*)&lo[r * ASTR + c] = l;
    };

    float4 pa[4], pb[4];

    {
        const float* Ab = A + (size_t)row0 * K;
        const float* Bb = Bm + (size_t)col0 * K;
        __half* s = smb;
        #pragma unroll
        for (int it = 0; it < 4; ++it) {
            int r = ldr + it * 32;
            float4 va = *(const float4*)&Ab[(size_t)r * K + ldc4];
            putA(s, r, ldc4, va);
            float4 vb = *(const float4*)&Bb[(size_t)r * K + ldc4];
            putB(s + ARR, s + 2 * ARR, r, ldc4, vb);
        }
    }
    __syncthreads();

    for (int ic = 0; ic < nchunk; ++ic) {
        const int cur = ic & 1;
        const uint32_t stOff = (uint32_t)cur * (STAGE3 * 2);
        const uint32_t aBase  = sb + stOff + (uint32_t)(wm * 64) * (ASTR * 2) + laneA;
        const uint32_t bhBase = sb + stOff + (uint32_t)ARR * 2
                              + (uint32_t)(wn * 32) * (ASTR * 2) + laneB;
        const uint32_t blBase = bhBase + (uint32_t)ARR * 2;

        if (ic + 1 < nchunk) {
            const float* Ab = A + (size_t)row0 * K + (ic + 1) * TBK;
            const float* Bb = Bm + (size_t)col0 * K + (ic + 1) * TBK;
            #pragma unroll
            for (int it = 0; it < 4; ++it) {
                int r = ldr + it * 32;
                pa[it] = *(const float4*)&Ab[(size_t)r * K + ldc4];
                pb[it] = *(const float4*)&Bb[(size_t)r * K + ldc4];
            }
        }

        #pragma unroll
        for (int ks = 0; ks < 2; ++ks) {
            const uint32_t kkB = ks * 32;
            uint32_t ah[4][4], bh[2][4], bl[2][4];
            #pragma unroll
            for (int mt = 0; mt < 4; ++mt)
                ldsm_x4(ah[mt], aBase + (uint32_t)mt * (16 * ASTR * 2) + kkB);
            #pragma unroll
            for (int np = 0; np < 2; ++np) {
                ldsm_x4(bh[np], bhBase + (uint32_t)np * (16 * ASTR * 2) + kkB);
                ldsm_x4(bl[np], blBase + (uint32_t)np * (16 * ASTR * 2) + kkB);
            }
            #pragma unroll
            for (int mt = 0; mt < 4; ++mt)
                #pragma unroll
                for (int nt = 0; nt < 4; ++nt) {
                    mma_f16(acc[mt][nt], ah[mt], &bh[nt >> 1][(nt & 1) * 2]);
                    mma_f16(acc[mt][nt], ah[mt], &bl[nt >> 1][(nt & 1) * 2]);
                }
        }

        if (ic + 1 < nchunk) {
            __half* d = smb + (1 - cur) * STAGE3;
            #pragma unroll
            for (int it = 0; it < 4; ++it) {
                int r = ldr + it * 32;
                putA(d, r, ldc4, pa[it]);
                putB(d + ARR, d + 2 * ARR, r, ldc4, pb[it]);
            }
        }
        __syncthreads();
    }

    #pragma unroll
    for (int mt = 0; mt < 4; ++mt) {
        int row = row0 + wm * 64 + mt * 16 + lr;
        #pragma unroll
        for (int nt = 0; nt < 4; ++nt) {
            int col = col0 + wn * 32 + nt * 8 + lc;
            *(float2*)&C[(size_t)row * N + col] =
                make_float2(acc[mt][nt][0], acc[mt][nt][1]);
            *(float2*)&C[(size_t)(row + 8) * N + col] =
                make_float2(acc[mt][nt][2], acc[mt][nt][3]);
        }
    }
}

// ---------------------------------------------------------------------------
// GEMM v2: A already fp16 in gmem (cp.async direct), B fp32 (inline split).
// ---------------------------------------------------------------------------
__global__ __launch_bounds__(256, 1) void gemm_af16_kernel(
    const __half* __restrict__ A, const float* __restrict__ Bm,
    float* __restrict__ C, int N, int K)
{
    extern __shared__ __half smb[];
    const int tid  = threadIdx.x;
    const int wid  = tid >> 5;
    const int lane = tid & 31;
    const int wm   = wid >> 2;
    const int wn   = wid & 3;
    const int row0 = blockIdx.y * 128;
    const int col0 = blockIdx.x * 128;

    const int lr = lane >> 2;
    const int lc = (lane & 3) * 2;

    const int ldr  = tid >> 3;
    const int ldc4 = (tid & 7) * 4;

    const uint32_t sb = smem_u32(smb);
    const uint32_t laneA = ((lane & 15) * ASTR + (lane >> 4) * 8) * 2;
    const uint32_t laneB = (((lane >> 4) * 8 + (lane & 7)) * ASTR + ((lane >> 3) & 1) * 8) * 2;

    float acc[4][4][4];
    #pragma unroll
    for (int mt = 0; mt < 4; ++mt)
        #pragma unroll
        for (int nt = 0; nt < 4; ++nt)
            #pragma unroll
            for (int q = 0; q < 4; ++q) acc[mt][nt][q] = 0.f;

    const int nchunk = K / TBK;

    auto putB = [&](__half* hi, __half* lo, int r, int c, float4 v) {
        uint2 h, l;
        splitf16(v, h, l);
        *(uint2*)&hi[r * ASTR + c] = h;
        *(uint2*)&lo[r * ASTR + c] = l;
    };

    // A chunk loader via cp.async: 128 rows x 32 f16 = 512 x 16B
    auto issue_A = [&](int ic, int stg) {
        uint32_t sbase = sb + (uint32_t)stg * (STAGE3 * 2);
        const __half* Ab = A + (size_t)row0 * K + (size_t)ic * TBK;
        #pragma unroll
        for (int it = 0; it < 2; ++it) {
            int id = tid + it * 256;
            int r = id >> 2, g = id & 3;
            CP_ASYNC16(sbase + (uint32_t)(r * ASTR * 2 + g * 16),
                       Ab + (size_t)r * K + g * 8);
        }
    };

    float4 pb[4];

    // prologue: stage 0
    issue_A(0, 0);
    CP_COMMIT();
    {
        const float* Bb = Bm + (size_t)col0 * K;
        #pragma unroll
        for (int it = 0; it < 4; ++it) {
            int r = ldr + it * 32;
            float4 vb = *(const float4*)&Bb[(size_t)r * K + ldc4];
            putB(smb + ARR, smb + 2 * ARR, r, ldc4, vb);
        }
    }
    CP_WAIT(0);
    __syncthreads();

    for (int ic = 0; ic < nchunk; ++ic) {
        const int cur = ic & 1;
        const uint32_t stOff = (uint32_t)cur * (STAGE3 * 2);
        const uint32_t aBase  = sb + stOff + (uint32_t)(wm * 64) * (ASTR * 2) + laneA;
        const uint32_t bhBase = sb + stOff + (uint32_t)ARR * 2
                              + (uint32_t)(wn * 32) * (ASTR * 2) + laneB;
        const uint32_t blBase = bhBase + (uint32_t)ARR * 2;

        if (ic + 1 < nchunk) {
            issue_A(ic + 1, 1 - cur);
            CP_COMMIT();
            const float* Bb = Bm + (size_t)col0 * K + (ic + 1) * TBK;
            #pragma unroll
            for (int it = 0; it < 4; ++it) {
                int r = ldr + it * 32;
                pb[it] = *(const float4*)&Bb[(size_t)r * K + ldc4];
            }
        }

        #pragma unroll
        for (int ks = 0; ks < 2; ++ks) {
            const uint32_t kkB = ks * 32;
            uint32_t ah[4][4], bh[2][4], bl[2][4];
            #pragma unroll
            for (int mt = 0; mt < 4; ++mt)
                ldsm_x4(ah[mt], aBase + (uint32_t)mt * (16 * ASTR * 2) + kkB);
            #pragma unroll
            for (int np = 0; np < 2; ++np) {
                ldsm_x4(bh[np], bhBase + (uint32_t)np * (16 * ASTR * 2) + kkB);
                ldsm_x4(bl[np], blBase + (uint32_t)np * (16 * ASTR * 2) + kkB);
            }
            #pragma unroll
            for (int mt = 0; mt < 4; ++mt)
                #pragma unroll
                for (int nt = 0; nt < 4; ++nt) {
                    mma_f16(acc[mt][nt], ah[mt], &bh[nt >> 1][(nt & 1) * 2]);
                    mma_f16(acc[mt][nt], ah[mt], &bl[nt >> 1][(nt & 1) * 2]);
                }
        }

        if (ic + 1 < nchunk) {
            __half* d = smb + (1 - cur) * STAGE3;
            #pragma unroll
            for (int it = 0; it < 4; ++it) {
                int r = ldr + it * 32;
                putB(d + ARR, d + 2 * ARR, r, ldc4, pb[it]);
            }
            CP_WAIT(0);
        }
        __syncthreads();
    }

    #pragma unroll
    for (int mt = 0; mt < 4; ++mt) {
        int row = row0 + wm * 64 + mt * 16 + lr;
        #pragma unroll
        for (int nt = 0; nt < 4; ++nt) {
            int col = col0 + wn * 32 + nt * 8 + lc;
            *(float2*)&C[(size_t)row * N + col] =
                make_float2(acc[mt][nt][0], acc[mt][nt][1]);
            *(float2*)&C[(size_t)(row + 8) * N + col] =
                make_float2(acc[mt][nt][2], acc[mt][nt][3]);
        }
    }
}

// ---------------------------------------------------------------------------
// Per-head RMSNorm + RoPE. Emits fp16: Q (pre-scaled, hi/lo), K, V (single).
// ---------------------------------------------------------------------------
__global__ __launch_bounds__(128) void prep_kernel(
    const float* __restrict__ cos_t, const float* __restrict__ sin_t,
    const float* __restrict__ q_ln, const float* __restrict__ k_ln)
{
    const int hh = blockIdx.x;
    const int s  = blockIdx.y;
    const int b  = blockIdx.z;
    const int d  = threadIdx.x;

    const size_t t = (size_t)b * SS + s;
    float x = g_qkv[t * QKVO + hh * HD + d];

    __shared__ float sy[HD];
    __shared__ float red[4];

    const float qscale = 0.08838834764831845f;  // 1/sqrt(128)

    if (hh < NH + NKV) {
        float sq = x * x;
        #pragma unroll
        for (int o = 16; o; o >>= 1) sq += __shfl_xor_sync(0xFFFFFFFFu, sq, o);
        if ((d & 31) == 0) red[d >> 5] = sq;
        __syncthreads();
        float var = (red[0] + red[1] + red[2] + red[3]) * (1.f / HD);
        const float* w = (hh < NH) ? q_ln : k_ln;
        float y = x * rsqrtf(var + 1e-6f) * w[d];
        sy[d] = y;
        __syncthreads();

        float out = y;
        if (d < RR) {
            float c  = cos_t[t * RR + d];
            float sn = sin_t[t * RR + d];
            float rot = (d < RR / 2) ? -sy[d + RR / 2] : sy[d - RR / 2];
            out = fmaf(y, c, rot * sn);
        }
        if (hh < NH) {
            out *= qscale;
            size_t off = (((size_t)(b * NH + hh)) * SS + s) * HD + d;
            __half hi = __float2half(out);
            g_qh[off] = hi;
            g_ql[off] = __float2half(out - __half2float(hi));
        } else {
            size_t off = (((size_t)(b * NKV + (hh - NH))) * SS + s) * HD + d;
            g_kh[off] = __float2half(out);
        }
    } else {
        size_t off = (((size_t)(b * NKV + (hh - NH - NKV))) * SS + s) * HD + d;
        g_vh[off] = __float2half(x);
    }
}

// ---------------------------------------------------------------------------
// Flash attention, K-tile 128, cp.async double-buffered fp16 K/V.
//   S: Q split (2 terms), K single.  PV: P split (regs, 2 terms), V single.
// CTA: 128 q x (b,h), 8 warps. Output written as single fp16 (GEMM2 A-ready).
// ---------------------------------------------------------------------------
#define DSTR 136
#define KT   128
#define SKV  (2 * KT * DSTR)              // f16 per stage: Kh[128] + Vh[128]
#define AKV_OFF (2 * 128 * DSTR)          // after Qhi, Qlo
#define ATTN2_F16 (AKV_OFF + 2 * SKV)
#define ATTN2_SMEM (ATTN2_F16 * 2)        // ~204 KB

__global__ __launch_bounds__(256, 1) void attn_mma_kernel()
{
    extern __shared__ __half smh[];
    __half* Qhi = smh;
    __half* Qlo = Qhi + 128 * DSTR;

    const int tid  = threadIdx.x;
    const int wid  = tid >> 5;
    const int lane = tid & 31;
    const int gr   = lane >> 2;
    const int gc   = (lane & 3) * 2;
    const int q0 = blockIdx.x * 128;
    const int bh = blockIdx.y;
    const int b = bh >> 4;
    const int h = bh & 15;
    const int hk = h / (NH / NKV);
    const int m0 = wid * 16;

    const uint32_t sb = smem_u32(smh);
    const uint32_t kvOff = sb + (uint32_t)AKV_OFF * 2;
    const uint32_t laneA = ((lane & 15) * DSTR + (lane >> 4) * 8) * 2;
    const uint32_t laneB = (((lane >> 4) * 8 + (lane & 7)) * DSTR + ((lane >> 3) & 1) * 8) * 2;
    const uint32_t laneV = ((lane & 15) * DSTR + (lane >> 4) * 8) * 2;

    const uint32_t qBaseHi = sb + (uint32_t)(m0 * DSTR) * 2 + laneA;
    const uint32_t qBaseLo = qBaseHi + (uint32_t)(128 * DSTR) * 2;

    const size_t kvg = ((size_t)(b * NKV + hk)) * SS * HD;
    const __half* ksrc = g_kh + kvg;
    const __half* vsrc = g_vh + kvg;

    auto issue_kv = [&](int kt, int stg) {
        uint32_t sbase = kvOff + (uint32_t)stg * (SKV * 2);
        size_t goff = (size_t)kt * KT * HD;
        #pragma unroll
        for (int it = 0; it < 8; ++it) {
            int id = tid + it * 256;      // 0..2047: 128 rows x 16 chunks
            int r = id >> 4, g = id & 15;
            uint32_t so = (uint32_t)(r * DSTR * 2 + g * 16);
            CP_ASYNC16(sbase + so, ksrc + goff + (size_t)r * HD + g * 8);
            CP_ASYNC16(sbase + (uint32_t)(KT * DSTR * 2) + so,
                       vsrc + goff + (size_t)r * HD + g * 8);
        }
    };

    // ---- load Q tile (fp16 hi/lo, already scaled) ----
    {
        const __half* qh = &g_qh[(((size_t)(b * NH + h)) * SS + q0) * HD];
        const __half* ql = &g_ql[(((size_t)(b * NH + h)) * SS + q0) * HD];
        #pragma unroll
        for (int it = 0; it < 8; ++it) {
            int id = tid + it * 256;
            int r = id >> 4, g = id & 15;
            *(uint4*)&Qhi[r * DSTR + g * 8] = *(const uint4*)&qh[(size_t)r * HD + g * 8];
            *(uint4*)&Qlo[r * DSTR + g * 8] = *(const uint4*)&ql[(size_t)r * HD + g * 8];
        }
    }

    issue_kv(0, 0);
    CP_COMMIT();

    float m_[2] = {-CUDART_INF_F, -CUDART_INF_F};
    float l_[2] = {0.f, 0.f};
    float O[16][4];
    #pragma unroll
    for (int nt = 0; nt < 16; ++nt)
        #pragma unroll
        for (int q = 0; q < 4; ++q) O[nt][q] = 0.f;

    __syncthreads();

    for (int kt = 0; kt < SS / KT; ++kt) {
        const int cur = kt & 1;
        if (kt + 1 < SS / KT) {
            issue_kv(kt + 1, 1 - cur);
            CP_COMMIT();
            CP_WAIT(1);
        } else {
            CP_WAIT(0);
        }
        __syncthreads();

        const uint32_t st = kvOff + (uint32_t)cur * (SKV * 2);
        const uint32_t kBase = st + laneB;
        const uint32_t vBase = st + (uint32_t)(KT * DSTR * 2) + laneV;

        // ---- S = Q K^T: 16 n-tiles (128 keys), Q split: 2 terms ----
        float sc[16][4];
        #pragma unroll
        for (int nt = 0; nt < 16; ++nt)
            #pragma unroll
            for (int q = 0; q < 4; ++q) sc[nt][q] = 0.f;

        #pragma unroll
        for (int ks = 0; ks < 8; ++ks) {
            const uint32_t kkB = ks * 32;
            uint32_t qh4[4], ql4[4];
            ldsm_x4(qh4, qBaseHi + kkB);
            ldsm_x4(ql4, qBaseLo + kkB);
            #pragma unroll
            for (int np = 0; np < 8; ++np) {
                uint32_t kb4[4];
                ldsm_x4(kb4, kBase + (uint32_t)np * (16 * DSTR * 2) + kkB);
                mma_f16(sc[2*np],   qh4, &kb4[0]);
                mma_f16(sc[2*np],   ql4, &kb4[0]);
                mma_f16(sc[2*np+1], qh4, &kb4[2]);
                mma_f16(sc[2*np+1], ql4, &kb4[2]);
            }
        }

        // ---- online softmax (warp-local; rows gr, gr+8) ----
        float mx0 = -CUDART_INF_F, mx1 = -CUDART_INF_F;
        #pragma unroll
        for (int nt = 0; nt < 16; ++nt) {
            mx0 = fmaxf(mx0, fmaxf(sc[nt][0], sc[nt][1]));
            mx1 = fmaxf(mx1, fmaxf(sc[nt][2], sc[nt][3]));
        }
        mx0 = fmaxf(mx0, __shfl_xor_sync(0xFFFFFFFFu, mx0, 1));
        mx0 = fmaxf(mx0, __shfl_xor_sync(0xFFFFFFFFu, mx0, 2));
        mx1 = fmaxf(mx1, __shfl_xor_sync(0xFFFFFFFFu, mx1, 1));
        mx1 = fmaxf(mx1, __shfl_xor_sync(0xFFFFFFFFu, mx1, 2));

        float mn0 = fmaxf(m_[0], mx0);
        float mn1 = fmaxf(m_[1], mx1);
        float scl0 = __expf(m_[0] - mn0);
        float scl1 = __expf(m_[1] - mn1);
        m_[0] = mn0; m_[1] = mn1;

        // exp in place; row sums
        float rs0 = 0.f, rs1 = 0.f;
        #pragma unroll
        for (int nt = 0; nt < 16; ++nt) {
            sc[nt][0] = __expf(sc[nt][0] - mn0);
            sc[nt][1] = __expf(sc[nt][1] - mn0);
            sc[nt][2] = __expf(sc[nt][2] - mn1);
            sc[nt][3] = __expf(sc[nt][3] - mn1);
            rs0 += sc[nt][0] + sc[nt][1];
            rs1 += sc[nt][2] + sc[nt][3];
        }
        rs0 += __shfl_xor_sync(0xFFFFFFFFu, rs0, 1);
        rs0 += __shfl_xor_sync(0xFFFFFFFFu, rs0, 2);
        rs1 += __shfl_xor_sync(0xFFFFFFFFu, rs1, 1);
        rs1 += __shfl_xor_sync(0xFFFFFFFFu, rs1, 2);
        l_[0] = l_[0] * scl0 + rs0;
        l_[1] = l_[1] * scl1 + rs1;

        #pragma unroll
        for (int nt = 0; nt < 16; ++nt) {
            O[nt][0] *= scl0; O[nt][1] *= scl0;
            O[nt][2] *= scl1; O[nt][3] *= scl1;
        }

        // ---- PV: per k2 pack P hi/lo then MMA (only 8 P-regs live) ----
        #pragma unroll
        for (int k2 = 0; k2 < 8; ++k2) {
            uint32_t pah[4], pal[4];
            #pragma unroll
            for (int half_ = 0; half_ < 2; ++half_) {
                float a = sc[2*k2 + half_][0], bq = sc[2*k2 + half_][1];
                float c = sc[2*k2 + half_][2], dq = sc[2*k2 + half_][3];
                uint32_t h0 = f16x2(a, bq);
                __half2 t0 = *(__half2*)&h0;
                uint32_t l0 = f16x2(a - __low2float(t0), bq - __high2float(t0));
                uint32_t h1 = f16x2(c, dq);
                __half2 t1 = *(__half2*)&h1;
                uint32_t l1 = f16x2(c - __low2float(t1), dq - __high2float(t1));
                pah[half_ * 2 + 0] = h0; pah[half_ * 2 + 1] = h1;
                pal[half_ * 2 + 0] = l0; pal[half_ * 2 + 1] = l1;
            }
            // fix ordering: fragment expects [r0,r1] = rows gr (k16 lo/hi byte pairs)
            uint32_t paH[4] = {pah[0], pah[1], pah[2], pah[3]};
            uint32_t paL[4] = {pal[0], pal[1], pal[2], pal[3]};

            const uint32_t kOff = (uint32_t)k2 * (16 * DSTR * 2);
            #pragma unroll
            for (int np = 0; np < 8; ++np) {
                uint32_t vb4[4];
                ldsm_x4_t(vb4, vBase + kOff + (uint32_t)np * 32);
                mma_f16(O[2*np],   paH, &vb4[0]);
                mma_f16(O[2*np],   paL, &vb4[0]);
                mma_f16(O[2*np+1], paH, &vb4[2]);
                mma_f16(O[2*np+1], paL, &vb4[2]);
            }
        }
        __syncthreads();
    }

    // ---- epilogue: normalize, write fp16 to g_attnh ----
    const float inv0 = 1.f / l_[0];
    const float inv1 = 1.f / l_[1];
    const int s0 = q0 + m0 + gr;
    #pragma unroll
    for (int nt = 0; nt < 16; ++nt) {
        int col = nt * 8 + gc;
        size_t off0 = (((size_t)b * SS + s0) * NH + h) * HD + col;
        size_t off1 = (((size_t)b * SS + s0 + 8) * NH + h) * HD + col;
        *(uint32_t*)&g_attnh[off0] = f16x2(O[nt][0] * inv0, O[nt][1] * inv0);
        *(uint32_t*)&g_attnh[off1] = f16x2(O[nt][2] * inv1, O[nt][3] * inv1);
    }
}

// ---------------------------------------------------------------------------
extern "C" void kernel_launch(void* const* d_in, const int* in_sizes, int n_in,
                              void* d_out, int out_size)
{
    const float* hidden  = (const float*)d_in[0];
    const float* cos_t   = (const float*)d_in[1];
    const float* sin_t   = (const float*)d_in[2];
    const float* w_qkv   = (const float*)d_in[3];
    const float* q_ln    = (const float*)d_in[4];
    const float* k_ln    = (const float*)d_in[5];
    const float* w_dense = (const float*)d_in[6];
    float* out = (float*)d_out;

    void *p_qkv = nullptr, *p_attnh = nullptr;
    cudaGetSymbolAddress(&p_qkv, g_qkv);
    cudaGetSymbolAddress(&p_attnh, g_attnh);
    float*  qkv   = (float*)p_qkv;
    __half* attnh = (__half*)p_attnh;

    cudaFuncSetAttribute(gemm_mma_kernel,
                         cudaFuncAttributeMaxDynamicSharedMemorySize, GEMM_SMEM);
    cudaFuncSetAttribute(gemm_af16_kernel,
                         cudaFuncAttributeMaxDynamicSharedMemorySize, GEMM_SMEM);
    cudaFuncSetAttribute(attn_mma_kernel,
                         cudaFuncAttributeMaxDynamicSharedMemorySize, ATTN2_SMEM);

    // 1) QKV projection (fp16 2-term, proven)
    gemm_mma_kernel<<<dim3(QKVO / 128, NTOK / 128), 256, GEMM_SMEM>>>(
        hidden, w_qkv, qkv, QKVO, HID);

    // 2) RMSNorm + RoPE -> fp16 Q(hi/lo)/K/V
    prep_kernel<<<dim3(NH + 2 * NKV, SS, BB), 128>>>(cos_t, sin_t, q_ln, k_ln);

    // 3) Flash attention (K-tile 128) -> fp16 output
    attn_mma_kernel<<<dim3(SS / 128, BB * NH), 256, ATTN2_SMEM>>>();

    // 4) Output projection (A fp16 via cp.async)
    gemm_af16_kernel<<<dim3(HID / 128, NTOK / 128), 256, GEMM_SMEM>>>(
        attnh, w_dense, out, HID, HID);
}

// round 14
// speedup vs baseline: 2.2551x; 1.0315x over previous
#include <cuda_runtime.h>
#include <cuda_fp16.h>
#include <math_constants.h>
#include <cstdint>

// Problem dims
#define BB   2
#define SS   2048
#define HID  2048
#define NH   16
#define NKV  4
#define HD   128
#define RR   64
#define NTOK (BB*SS)          // 4096
#define QKVO ((NH+2*NKV)*HD)  // 3072

// Scratch (device globals; no allocation allowed)
__device__ float  g_qkv[(size_t)NTOK * QKVO];
__device__ __half g_ah[(size_t)NTOK * HID];           // hidden, fp16
__device__ __half g_wh[(size_t)QKVO * HID];           // weight hi (w_qkv then w_dense)
__device__ __half g_wl[(size_t)QKVO * HID];           // weight lo
__device__ __half g_qh[(size_t)BB * NH  * SS * HD];   // Q hi (pre-scaled)
__device__ __half g_ql[(size_t)BB * NH  * SS * HD];   // Q lo
__device__ __half g_kh[(size_t)BB * NKV * SS * HD];   // K fp16
__device__ __half g_vh[(size_t)BB * NKV * SS * HD];   // V fp16
__device__ __half g_attnh[(size_t)NTOK * (NH*HD)];    // attn out fp16

// ---------------------------------------------------------------------------
// PTX helpers (base PTX only — compute_103-safe)
// ---------------------------------------------------------------------------
__device__ __forceinline__ void mma_f16(float* c, const uint32_t* a, const uint32_t* b) {
    asm volatile(
        "mma.sync.aligned.m16n8k16.row.col.f32.f16.f16.f32 "
        "{%0,%1,%2,%3}, {%4,%5,%6,%7}, {%8,%9}, {%0,%1,%2,%3};"
        : "+f"(c[0]), "+f"(c[1]), "+f"(c[2]), "+f"(c[3])
        : "r"(a[0]), "r"(a[1]), "r"(a[2]), "r"(a[3]), "r"(b[0]), "r"(b[1]));
}

__device__ __forceinline__ void ldsm_x4(uint32_t* r, uint32_t addr) {
    asm volatile("ldmatrix.sync.aligned.m8n8.x4.shared.b16 {%0,%1,%2,%3}, [%4];"
        : "=r"(r[0]), "=r"(r[1]), "=r"(r[2]), "=r"(r[3]) : "r"(addr));
}

__device__ __forceinline__ void ldsm_x4_t(uint32_t* r, uint32_t addr) {
    asm volatile("ldmatrix.sync.aligned.m8n8.x4.trans.shared.b16 {%0,%1,%2,%3}, [%4];"
        : "=r"(r[0]), "=r"(r[1]), "=r"(r[2]), "=r"(r[3]) : "r"(addr));
}

__device__ __forceinline__ uint32_t smem_u32(const void* p) {
    uint32_t a;
    asm("{ .reg .u64 t; cvta.to.shared.u64 t, %1; cvt.u32.u64 %0, t; }"
        : "=r"(a) : "l"(p));
    return a;
}

#define CP_ASYNC16(saddr, gptr) \
    asm volatile("cp.async.cg.shared.global [%0], [%1], 16;" \
                 :: "r"(saddr), "l"(gptr))
#define CP_COMMIT() asm volatile("cp.async.commit_group;" ::: "memory")
#define CP_WAIT(n)  asm volatile("cp.async.wait_group %0;" :: "n"(n) : "memory")

__device__ __forceinline__ uint32_t f16x2(float x, float y) {
    __half2 h = __floats2half2_rn(x, y);
    return *(uint32_t*)&h;
}

// ---------------------------------------------------------------------------
// Elementwise converters
// ---------------------------------------------------------------------------
__global__ __launch_bounds__(256) void cvt_f16_kernel(
    const float* __restrict__ in, __half* __restrict__ outp, int n4)
{
    int i = blockIdx.x * blockDim.x + threadIdx.x;
    if (i < n4) {
        float4 v = ((const float4*)in)[i];
        ((uint2*)outp)[i] = make_uint2(f16x2(v.x, v.y), f16x2(v.z, v.w));
    }
}

__global__ __launch_bounds__(256) void split_f16_kernel(
    const float* __restrict__ in, __half* __restrict__ hi,
    __half* __restrict__ lo, int n4)
{
    int i = blockIdx.x * blockDim.x + threadIdx.x;
    if (i < n4) {
        float4 v = ((const float4*)in)[i];
        uint32_t h0 = f16x2(v.x, v.y);
        uint32_t h1 = f16x2(v.z, v.w);
        __half2 t0 = *(__half2*)&h0;
        __half2 t1 = *(__half2*)&h1;
        uint32_t l0 = f16x2(v.x - __low2float(t0), v.y - __high2float(t0));
        uint32_t l1 = f16x2(v.z - __low2float(t1), v.w - __high2float(t1));
        ((uint2*)hi)[i] = make_uint2(h0, h1);
        ((uint2*)lo)[i] = make_uint2(l0, l1);
    }
}

// ---------------------------------------------------------------------------
// Tensor GEMM: C[M,N] = A[M,K] * (Bh+Bl)[N,K]^T, all operands fp16 in gmem.
// 128x128 tile, BK=32, 256 threads, pure cp.async double buffer, ldmatrix.
// 2 CTAs/SM (60 KB smem, ~115 regs).
// ---------------------------------------------------------------------------
#define TBK 32
#define ASTR 40
#define ARR (128 * ASTR)
#define STAGE3 (3 * ARR)
#define GEMM_SMEM (2 * STAGE3 * 2)       // 61440 B

__global__ __launch_bounds__(256, 2) void gemm_f16_kernel(
    const __half* __restrict__ A, const __half* __restrict__ Bh,
    const __half* __restrict__ Bl, float* __restrict__ C, int N, int K)
{
    extern __shared__ __half smb[];
    const int tid  = threadIdx.x;
    const int wid  = tid >> 5;
    const int lane = tid & 31;
    const int wm   = wid >> 2;
    const int wn   = wid & 3;
    const int row0 = blockIdx.y * 128;
    const int col0 = blockIdx.x * 128;

    const int lr = lane >> 2;
    const int lc = (lane & 3) * 2;

    const uint32_t sb = smem_u32(smb);
    const uint32_t laneA = ((lane & 15) * ASTR + (lane >> 4) * 8) * 2;
    const uint32_t laneB = (((lane >> 4) * 8 + (lane & 7)) * ASTR + ((lane >> 3) & 1) * 8) * 2;

    float acc[4][4][4];
    #pragma unroll
    for (int mt = 0; mt < 4; ++mt)
        #pragma unroll
        for (int nt = 0; nt < 4; ++nt)
            #pragma unroll
            for (int q = 0; q < 4; ++q) acc[mt][nt][q] = 0.f;

    const int nchunk = K / TBK;

    const __half* src0 = A  + (size_t)row0 * K;
    const __half* src1 = Bh + (size_t)col0 * K;
    const __half* src2 = Bl + (size_t)col0 * K;

    auto issue_chunk = [&](int ic, int stg) {
        uint32_t sbase = sb + (uint32_t)stg * (STAGE3 * 2);
        const size_t koff = (size_t)ic * TBK;
        #pragma unroll
        for (int it = 0; it < 2; ++it) {
            int id = tid + it * 256;
            int r = id >> 2, g = id & 3;
            uint32_t so = (uint32_t)(r * ASTR * 2 + g * 16);
            size_t go = (size_t)r * K + koff + g * 8;
            CP_ASYNC16(sbase + so, src0 + go);
            CP_ASYNC16(sbase + (uint32_t)(ARR * 2) + so, src1 + go);
            CP_ASYNC16(sbase + (uint32_t)(2 * ARR * 2) + so, src2 + go);
        }
    };

    issue_chunk(0, 0);
    CP_COMMIT();

    for (int ic = 0; ic < nchunk; ++ic) {
        const int cur = ic & 1;
        if (ic + 1 < nchunk) {
            issue_chunk(ic + 1, 1 - cur);
            CP_COMMIT();
            CP_WAIT(1);
        } else {
            CP_WAIT(0);
        }
        __syncthreads();

        const uint32_t stOff = (uint32_t)cur * (STAGE3 * 2);
        const uint32_t aBase  = sb + stOff + (uint32_t)(wm * 64) * (ASTR * 2) + laneA;
        const uint32_t bhBase = sb + stOff + (uint32_t)(ARR * 2)
                              + (uint32_t)(wn * 32) * (ASTR * 2) + laneB;
        const uint32_t blBase = bhBase + (uint32_t)(ARR * 2);

        #pragma unroll
        for (int ks = 0; ks < 2; ++ks) {
            const uint32_t kkB = ks * 32;
            uint32_t ah[4][4], bh4[2][4], bl4[2][4];
            #pragma unroll
            for (int mt = 0; mt < 4; ++mt)
                ldsm_x4(ah[mt], aBase + (uint32_t)mt * (16 * ASTR * 2) + kkB);
            #pragma unroll
            for (int np = 0; np < 2; ++np) {
                ldsm_x4(bh4[np], bhBase + (uint32_t)np * (16 * ASTR * 2) + kkB);
                ldsm_x4(bl4[np], blBase + (uint32_t)np * (16 * ASTR * 2) + kkB);
            }
            #pragma unroll
            for (int mt = 0; mt < 4; ++mt)
                #pragma unroll
                for (int nt = 0; nt < 4; ++nt) {
                    mma_f16(acc[mt][nt], ah[mt], &bh4[nt >> 1][(nt & 1) * 2]);
                    mma_f16(acc[mt][nt], ah[mt], &bl4[nt >> 1][(nt & 1) * 2]);
                }
        }
        __syncthreads();
    }

    #pragma unroll
    for (int mt = 0; mt < 4; ++mt) {
        int row = row0 + wm * 64 + mt * 16 + lr;
        #pragma unroll
        for (int nt = 0; nt < 4; ++nt) {
            int col = col0 + wn * 32 + nt * 8 + lc;
            *(float2*)&C[(size_t)row * N + col] =
                make_float2(acc[mt][nt][0], acc[mt][nt][1]);
            *(float2*)&C[(size_t)(row + 8) * N + col] =
                make_float2(acc[mt][nt][2], acc[mt][nt][3]);
        }
    }
}

// ---------------------------------------------------------------------------
// Per-head RMSNorm + RoPE. Emits fp16: Q (pre-scaled, hi/lo), K, V (single).
// ---------------------------------------------------------------------------
__global__ __launch_bounds__(128) void prep_kernel(
    const float* __restrict__ cos_t, const float* __restrict__ sin_t,
    const float* __restrict__ q_ln, const float* __restrict__ k_ln)
{
    const int hh = blockIdx.x;
    const int s  = blockIdx.y;
    const int b  = blockIdx.z;
    const int d  = threadIdx.x;

    const size_t t = (size_t)b * SS + s;
    float x = g_qkv[t * QKVO + hh * HD + d];

    __shared__ float sy[HD];
    __shared__ float red[4];

    const float qscale = 0.08838834764831845f;  // 1/sqrt(128)

    if (hh < NH + NKV) {
        float sq = x * x;
        #pragma unroll
        for (int o = 16; o; o >>= 1) sq += __shfl_xor_sync(0xFFFFFFFFu, sq, o);
        if ((d & 31) == 0) red[d >> 5] = sq;
        __syncthreads();
        float var = (red[0] + red[1] + red[2] + red[3]) * (1.f / HD);
        const float* w = (hh < NH) ? q_ln : k_ln;
        float y = x * rsqrtf(var + 1e-6f) * w[d];
        sy[d] = y;
        __syncthreads();

        float out = y;
        if (d < RR) {
            float c  = cos_t[t * RR + d];
            float sn = sin_t[t * RR + d];
            float rot = (d < RR / 2) ? -sy[d + RR / 2] : sy[d - RR / 2];
            out = fmaf(y, c, rot * sn);
        }
        if (hh < NH) {
            out *= qscale;
            size_t off = (((size_t)(b * NH + hh)) * SS + s) * HD + d;
            __half hi = __float2half(out);
            g_qh[off] = hi;
            g_ql[off] = __float2half(out - __half2float(hi));
        } else {
            size_t off = (((size_t)(b * NKV + (hh - NH))) * SS + s) * HD + d;
            g_kh[off] = __float2half(out);
        }
    } else {
        size_t off = (((size_t)(b * NKV + (hh - NH - NKV))) * SS + s) * HD + d;
        g_vh[off] = __float2half(x);
    }
}

// ---------------------------------------------------------------------------
// Flash attention, K-tile 128, cp.async double-buffered fp16 K/V (round-13).
// ---------------------------------------------------------------------------
#define DSTR 136
#define KT   128
#define SKV  (2 * KT * DSTR)
#define AKV_OFF (2 * 128 * DSTR)
#define ATTN2_F16 (AKV_OFF + 2 * SKV)
#define ATTN2_SMEM (ATTN2_F16 * 2)        // ~204 KB

__global__ __launch_bounds__(256, 1) void attn_mma_kernel()
{
    extern __shared__ __half smh[];
    __half* Qhi = smh;
    __half* Qlo = Qhi + 128 * DSTR;

    const int tid  = threadIdx.x;
    const int wid  = tid >> 5;
    const int lane = tid & 31;
    const int gr   = lane >> 2;
    const int gc   = (lane & 3) * 2;
    const int q0 = blockIdx.x * 128;
    const int bh = blockIdx.y;
    const int b = bh >> 4;
    const int h = bh & 15;
    const int hk = h / (NH / NKV);
    const int m0 = wid * 16;

    const uint32_t sb = smem_u32(smh);
    const uint32_t kvOff = sb + (uint32_t)AKV_OFF * 2;
    const uint32_t laneA = ((lane & 15) * DSTR + (lane >> 4) * 8) * 2;
    const uint32_t laneB = (((lane >> 4) * 8 + (lane & 7)) * DSTR + ((lane >> 3) & 1) * 8) * 2;
    const uint32_t laneV = ((lane & 15) * DSTR + (lane >> 4) * 8) * 2;

    const uint32_t qBaseHi = sb + (uint32_t)(m0 * DSTR) * 2 + laneA;
    const uint32_t qBaseLo = qBaseHi + (uint32_t)(128 * DSTR) * 2;

    const size_t kvg = ((size_t)(b * NKV + hk)) * SS * HD;
    const __half* ksrc = g_kh + kvg;
    const __half* vsrc = g_vh + kvg;

    auto issue_kv = [&](int kt, int stg) {
        uint32_t sbase = kvOff + (uint32_t)stg * (SKV * 2);
        size_t goff = (size_t)kt * KT * HD;
        #pragma unroll
        for (int it = 0; it < 8; ++it) {
            int id = tid + it * 256;
            int r = id >> 4, g = id & 15;
            uint32_t so = (uint32_t)(r * DSTR * 2 + g * 16);
            CP_ASYNC16(sbase + so, ksrc + goff + (size_t)r * HD + g * 8);
            CP_ASYNC16(sbase + (uint32_t)(KT * DSTR * 2) + so,
                       vsrc + goff + (size_t)r * HD + g * 8);
        }
    };

    {
        const __half* qh = &g_qh[(((size_t)(b * NH + h)) * SS + q0) * HD];
        const __half* ql = &g_ql[(((size_t)(b * NH + h)) * SS + q0) * HD];
        #pragma unroll
        for (int it = 0; it < 8; ++it) {
            int id = tid + it * 256;
            int r = id >> 4, g = id & 15;
            *(uint4*)&Qhi[r * DSTR + g * 8] = *(const uint4*)&qh[(size_t)r * HD + g * 8];
            *(uint4*)&Qlo[r * DSTR + g * 8] = *(const uint4*)&ql[(size_t)r * HD + g * 8];
        }
    }

    issue_kv(0, 0);
    CP_COMMIT();

    float m_[2] = {-CUDART_INF_F, -CUDART_INF_F};
    float l_[2] = {0.f, 0.f};
    float O[16][4];
    #pragma unroll
    for (int nt = 0; nt < 16; ++nt)
        #pragma unroll
        for (int q = 0; q < 4; ++q) O[nt][q] = 0.f;

    __syncthreads();

    for (int kt = 0; kt < SS / KT; ++kt) {
        const int cur = kt & 1;
        if (kt + 1 < SS / KT) {
            issue_kv(kt + 1, 1 - cur);
            CP_COMMIT();
            CP_WAIT(1);
        } else {
            CP_WAIT(0);
        }
        __syncthreads();

        const uint32_t st = kvOff + (uint32_t)cur * (SKV * 2);
        const uint32_t kBase = st + laneB;
        const uint32_t vBase = st + (uint32_t)(KT * DSTR * 2) + laneV;

        float sc[16][4];
        #pragma unroll
        for (int nt = 0; nt < 16; ++nt)
            #pragma unroll
            for (int q = 0; q < 4; ++q) sc[nt][q] = 0.f;

        #pragma unroll
        for (int ks = 0; ks < 8; ++ks) {
            const uint32_t kkB = ks * 32;
            uint32_t qh4[4], ql4[4];
            ldsm_x4(qh4, qBaseHi + kkB);
            ldsm_x4(ql4, qBaseLo + kkB);
            #pragma unroll
            for (int np = 0; np < 8; ++np) {
                uint32_t kb4[4];
                ldsm_x4(kb4, kBase + (uint32_t)np * (16 * DSTR * 2) + kkB);
                mma_f16(sc[2*np],   qh4, &kb4[0]);
                mma_f16(sc[2*np],   ql4, &kb4[0]);
                mma_f16(sc[2*np+1], qh4, &kb4[2]);
                mma_f16(sc[2*np+1], ql4, &kb4[2]);
            }
        }

        float mx0 = -CUDART_INF_F, mx1 = -CUDART_INF_F;
        #pragma unroll
        for (int nt = 0; nt < 16; ++nt) {
            mx0 = fmaxf(mx0, fmaxf(sc[nt][0], sc[nt][1]));
            mx1 = fmaxf(mx1, fmaxf(sc[nt][2], sc[nt][3]));
        }
        mx0 = fmaxf(mx0, __shfl_xor_sync(0xFFFFFFFFu, mx0, 1));
        mx0 = fmaxf(mx0, __shfl_xor_sync(0xFFFFFFFFu, mx0, 2));
        mx1 = fmaxf(mx1, __shfl_xor_sync(0xFFFFFFFFu, mx1, 1));
        mx1 = fmaxf(mx1, __shfl_xor_sync(0xFFFFFFFFu, mx1, 2));

        float mn0 = fmaxf(m_[0], mx0);
        float mn1 = fmaxf(m_[1], mx1);
        float scl0 = __expf(m_[0] - mn0);
        float scl1 = __expf(m_[1] - mn1);
        m_[0] = mn0; m_[1] = mn1;

        float rs0 = 0.f, rs1 = 0.f;
        #pragma unroll
        for (int nt = 0; nt < 16; ++nt) {
            sc[nt][0] = __expf(sc[nt][0] - mn0);
            sc[nt][1] = __expf(sc[nt][1] - mn0);
            sc[nt][2] = __expf(sc[nt][2] - mn1);
            sc[nt][3] = __expf(sc[nt][3] - mn1);
            rs0 += sc[nt][0] + sc[nt][1];
            rs1 += sc[nt][2] + sc[nt][3];
        }
        rs0 += __shfl_xor_sync(0xFFFFFFFFu, rs0, 1);
        rs0 += __shfl_xor_sync(0xFFFFFFFFu, rs0, 2);
        rs1 += __shfl_xor_sync(0xFFFFFFFFu, rs1, 1);
        rs1 += __shfl_xor_sync(0xFFFFFFFFu, rs1, 2);
        l_[0] = l_[0] * scl0 + rs0;
        l_[1] = l_[1] * scl1 + rs1;

        #pragma unroll
        for (int nt = 0; nt < 16; ++nt) {
            O[nt][0] *= scl0; O[nt][1] *= scl0;
            O[nt][2] *= scl1; O[nt][3] *= scl1;
        }

        #pragma unroll
        for (int k2 = 0; k2 < 8; ++k2) {
            uint32_t paH[4], paL[4];
            #pragma unroll
            for (int half_ = 0; half_ < 2; ++half_) {
                float a = sc[2*k2 + half_][0], bq = sc[2*k2 + half_][1];
                float c = sc[2*k2 + half_][2], dq = sc[2*k2 + half_][3];
                uint32_t h0 = f16x2(a, bq);
                __half2 t0 = *(__half2*)&h0;
                uint32_t l0 = f16x2(a - __low2float(t0), bq - __high2float(t0));
                uint32_t h1 = f16x2(c, dq);
                __half2 t1 = *(__half2*)&h1;
                uint32_t l1 = f16x2(c - __low2float(t1), dq - __high2float(t1));
                paH[half_ * 2 + 0] = h0; paH[half_ * 2 + 1] = h1;
                paL[half_ * 2 + 0] = l0; paL[half_ * 2 + 1] = l1;
            }
            const uint32_t kOff = (uint32_t)k2 * (16 * DSTR * 2);
            #pragma unroll
            for (int np = 0; np < 8; ++np) {
                uint32_t vb4[4];
                ldsm_x4_t(vb4, vBase + kOff + (uint32_t)np * 32);
                mma_f16(O[2*np],   paH, &vb4[0]);
                mma_f16(O[2*np],   paL, &vb4[0]);
                mma_f16(O[2*np+1], paH, &vb4[2]);
                mma_f16(O[2*np+1], paL, &vb4[2]);
            }
        }
        __syncthreads();
    }

    const float inv0 = 1.f / l_[0];
    const float inv1 = 1.f / l_[1];
    const int s0 = q0 + m0 + gr;
    #pragma unroll
    for (int nt = 0; nt < 16; ++nt) {
        int col = nt * 8 + gc;
        size_t off0 = (((size_t)b * SS + s0) * NH + h) * HD + col;
        size_t off1 = (((size_t)b * SS + s0 + 8) * NH + h) * HD + col;
        *(uint32_t*)&g_attnh[off0] = f16x2(O[nt][0] * inv0, O[nt][1] * inv0);
        *(uint32_t*)&g_attnh[off1] = f16x2(O[nt][2] * inv1, O[nt][3] * inv1);
    }
}

// ---------------------------------------------------------------------------
extern "C" void kernel_launch(void* const* d_in, const int* in_sizes, int n_in,
                              void* d_out, int out_size)
{
    const float* hidden  = (const float*)d_in[0];
    const float* cos_t   = (const float*)d_in[1];
    const float* sin_t   = (const float*)d_in[2];
    const float* w_qkv   = (const float*)d_in[3];
    const float* q_ln    = (const float*)d_in[4];
    const float* k_ln    = (const float*)d_in[5];
    const float* w_dense = (const float*)d_in[6];
    float* out = (float*)d_out;

    void *p_qkv, *p_ah, *p_wh, *p_wl, *p_attnh;
    cudaGetSymbolAddress(&p_qkv, g_qkv);
    cudaGetSymbolAddress(&p_ah, g_ah);
    cudaGetSymbolAddress(&p_wh, g_wh);
    cudaGetSymbolAddress(&p_wl, g_wl);
    cudaGetSymbolAddress(&p_attnh, g_attnh);
    float*  qkv   = (float*)p_qkv;
    __half* ah    = (__half*)p_ah;
    __half* wh    = (__half*)p_wh;
    __half* wl    = (__half*)p_wl;
    __half* attnh = (__half*)p_attnh;

    cudaFuncSetAttribute(gemm_f16_kernel,
                         cudaFuncAttributeMaxDynamicSharedMemorySize, GEMM_SMEM);
    cudaFuncSetAttribute(attn_mma_kernel,
                         cudaFuncAttributeMaxDynamicSharedMemorySize, ATTN2_SMEM);

    // 0) convert hidden -> fp16; split w_qkv -> fp16 hi/lo
    cvt_f16_kernel<<<(NTOK * HID / 4 + 255) / 256, 256>>>(hidden, ah, NTOK * HID / 4);
    split_f16_kernel<<<(QKVO * HID / 4 + 255) / 256, 256>>>(w_qkv, wh, wl, QKVO * HID / 4);

    // 1) QKV projection (all-fp16 cp.async GEMM, 2 CTAs/SM)
    gemm_f16_kernel<<<dim3(QKVO / 128, NTOK / 128), 256, GEMM_SMEM>>>(
        ah, wh, wl, qkv, QKVO, HID);

    // 2) RMSNorm + RoPE -> fp16 Q(hi/lo)/K/V
    prep_kernel<<<dim3(NH + 2 * NKV, SS, BB), 128>>>(cos_t, sin_t, q_ln, k_ln);

    // 3) Flash attention -> fp16 output
    attn_mma_kernel<<<dim3(SS / 128, BB * NH), 256, ATTN2_SMEM>>>();

    // 3b) split w_dense (reuses g_wh/g_wl; safe after GEMM1)
    split_f16_kernel<<<(HID * HID / 4 + 255) / 256, 256>>>(w_dense, wh, wl, HID * HID / 4);

    // 4) Output projection
    gemm_f16_kernel<<<dim3(HID / 128, NTOK / 128), 256, GEMM_SMEM>>>(
        attnh, wh, wl, out, HID, HID);
}

// round 16
// speedup vs baseline: 2.3464x; 1.0405x over previous
#include <cuda_runtime.h>
#include <cuda_fp16.h>
#include <math_constants.h>
#include <cstdint>

// Problem dims
#define BB   2
#define SS   2048
#define HID  2048
#define NH   16
#define NKV  4
#define HD   128
#define RR   64
#define NTOK (BB*SS)          // 4096
#define QKVO ((NH+2*NKV)*HD)  // 3072

// Scratch (device globals; no allocation allowed)
__device__ __half g_ah[(size_t)NTOK * HID];           // hidden, fp16
__device__ __half g_wh[(size_t)QKVO * HID];           // weight hi (w_qkv then w_dense)
__device__ __half g_wl[(size_t)QKVO * HID];           // weight lo
__device__ __half g_qh[(size_t)BB * NH  * SS * HD];   // Q hi (pre-scaled)
__device__ __half g_ql[(size_t)BB * NH  * SS * HD];   // Q lo
__device__ __half g_kh[(size_t)BB * NKV * SS * HD];   // K fp16
__device__ __half g_vh[(size_t)BB * NKV * SS * HD];   // V fp16
__device__ __half g_attnh[(size_t)NTOK * (NH*HD)];    // attn out fp16

// ---------------------------------------------------------------------------
// PTX helpers (base PTX only — compute_103-safe)
// ---------------------------------------------------------------------------
__device__ __forceinline__ void mma_f16(float* c, const uint32_t* a, const uint32_t* b) {
    asm volatile(
        "mma.sync.aligned.m16n8k16.row.col.f32.f16.f16.f32 "
        "{%0,%1,%2,%3}, {%4,%5,%6,%7}, {%8,%9}, {%0,%1,%2,%3};"
        : "+f"(c[0]), "+f"(c[1]), "+f"(c[2]), "+f"(c[3])
        : "r"(a[0]), "r"(a[1]), "r"(a[2]), "r"(a[3]), "r"(b[0]), "r"(b[1]));
}

__device__ __forceinline__ void ldsm_x4(uint32_t* r, uint32_t addr) {
    asm volatile("ldmatrix.sync.aligned.m8n8.x4.shared.b16 {%0,%1,%2,%3}, [%4];"
        : "=r"(r[0]), "=r"(r[1]), "=r"(r[2]), "=r"(r[3]) : "r"(addr));
}

__device__ __forceinline__ void ldsm_x4_t(uint32_t* r, uint32_t addr) {
    asm volatile("ldmatrix.sync.aligned.m8n8.x4.trans.shared.b16 {%0,%1,%2,%3}, [%4];"
        : "=r"(r[0]), "=r"(r[1]), "=r"(r[2]), "=r"(r[3]) : "r"(addr));
}

__device__ __forceinline__ uint32_t smem_u32(const void* p) {
    uint32_t a;
    asm("{ .reg .u64 t; cvta.to.shared.u64 t, %1; cvt.u32.u64 %0, t; }"
        : "=r"(a) : "l"(p));
    return a;
}

#define CP_ASYNC16(saddr, gptr) \
    asm volatile("cp.async.cg.shared.global [%0], [%1], 16;" \
                 :: "r"(saddr), "l"(gptr))
#define CP_COMMIT() asm volatile("cp.async.commit_group;" ::: "memory")
#define CP_WAIT(n)  asm volatile("cp.async.wait_group %0;" :: "n"(n) : "memory")

__device__ __forceinline__ uint32_t f16x2(float x, float y) {
    __half2 h = __floats2half2_rn(x, y);
    return *(uint32_t*)&h;
}

// ---------------------------------------------------------------------------
// Elementwise converters
// ---------------------------------------------------------------------------
__global__ __launch_bounds__(256) void cvt_f16_kernel(
    const float* __restrict__ in, __half* __restrict__ outp, int n4)
{
    int i = blockIdx.x * blockDim.x + threadIdx.x;
    if (i < n4) {
        float4 v = ((const float4*)in)[i];
        ((uint2*)outp)[i] = make_uint2(f16x2(v.x, v.y), f16x2(v.z, v.w));
    }
}

__global__ __launch_bounds__(256) void split_f16_kernel(
    const float* __restrict__ in, __half* __restrict__ hi,
    __half* __restrict__ lo, int n4)
{
    int i = blockIdx.x * blockDim.x + threadIdx.x;
    if (i < n4) {
        float4 v = ((const float4*)in)[i];
        uint32_t h0 = f16x2(v.x, v.y);
        uint32_t h1 = f16x2(v.z, v.w);
        __half2 t0 = *(__half2*)&h0;
        __half2 t1 = *(__half2*)&h1;
        uint32_t l0 = f16x2(v.x - __low2float(t0), v.y - __high2float(t0));
        uint32_t l1 = f16x2(v.z - __low2float(t1), v.w - __high2float(t1));
        ((uint2*)hi)[i] = make_uint2(h0, h1);
        ((uint2*)lo)[i] = make_uint2(l0, l1);
    }
}

// ---------------------------------------------------------------------------
// GEMM geometry (shared)
// ---------------------------------------------------------------------------
#define TBK 32
#define ASTR 40
#define ARR (128 * ASTR)
#define STAGE3 (3 * ARR)
#define GEMM_SMEM (2 * STAGE3 * 2)       // 61440 B

// Main-loop macro body shared by the two GEMM kernels (same as round 14).
#define GEMM_MAINLOOP(A_, Bh_, Bl_, K_)                                          \
    const __half* src0 = (A_)  + (size_t)row0 * (K_);                            \
    const __half* src1 = (Bh_) + (size_t)col0 * (K_);                            \
    const __half* src2 = (Bl_) + (size_t)col0 * (K_);                            \
    auto issue_chunk = [&](int ic, int stg) {                                    \
        uint32_t sbase = sb + (uint32_t)stg * (STAGE3 * 2);                      \
        const size_t koff = (size_t)ic * TBK;                                    \
        _Pragma("unroll")                                                        \
        for (int it = 0; it < 2; ++it) {                                         \
            int id = tid + it * 256;                                             \
            int r = id >> 2, g = id & 3;                                         \
            uint32_t so = (uint32_t)(r * ASTR * 2 + g * 16);                     \
            size_t go = (size_t)r * (K_) + koff + g * 8;                         \
            CP_ASYNC16(sbase + so, src0 + go);                                   \
            CP_ASYNC16(sbase + (uint32_t)(ARR * 2) + so, src1 + go);             \
            CP_ASYNC16(sbase + (uint32_t)(2 * ARR * 2) + so, src2 + go);         \
        }                                                                        \
    };                                                                           \
    issue_chunk(0, 0);                                                           \
    CP_COMMIT();                                                                 \
    const int nchunk = (K_) / TBK;                                               \
    for (int ic = 0; ic < nchunk; ++ic) {                                        \
        const int cur = ic & 1;                                                  \
        if (ic + 1 < nchunk) { issue_chunk(ic + 1, 1 - cur); CP_COMMIT(); CP_WAIT(1); } \
        else                 { CP_WAIT(0); }                                     \
        __syncthreads();                                                         \
        const uint32_t stOff = (uint32_t)cur * (STAGE3 * 2);                     \
        const uint32_t aBase  = sb + stOff + (uint32_t)(wm * 64) * (ASTR * 2) + laneA; \
        const uint32_t bhBase = sb + stOff + (uint32_t)(ARR * 2)                 \
                              + (uint32_t)(wn * 32) * (ASTR * 2) + laneB;        \
        const uint32_t blBase = bhBase + (uint32_t)(ARR * 2);                    \
        _Pragma("unroll")                                                        \
        for (int ks = 0; ks < 2; ++ks) {                                         \
            const uint32_t kkB = ks * 32;                                        \
            uint32_t ah[4][4], bh4[2][4], bl4[2][4];                             \
            _Pragma("unroll")                                                    \
            for (int mt = 0; mt < 4; ++mt)                                       \
                ldsm_x4(ah[mt], aBase + (uint32_t)mt * (16 * ASTR * 2) + kkB);   \
            _Pragma("unroll")                                                    \
            for (int np = 0; np < 2; ++np) {                                     \
                ldsm_x4(bh4[np], bhBase + (uint32_t)np * (16 * ASTR * 2) + kkB); \
                ldsm_x4(bl4[np], blBase + (uint32_t)np * (16 * ASTR * 2) + kkB); \
            }                                                                    \
            _Pragma("unroll")                                                    \
            for (int mt = 0; mt < 4; ++mt)                                       \
                _Pragma("unroll")                                                \
                for (int nt = 0; nt < 4; ++nt) {                                 \
                    mma_f16(acc[mt][nt], ah[mt], &bh4[nt >> 1][(nt & 1) * 2]);   \
                    mma_f16(acc[mt][nt], ah[mt], &bl4[nt >> 1][(nt & 1) * 2]);   \
                }                                                                \
        }                                                                        \
        __syncthreads();                                                         \
    }

// ---------------------------------------------------------------------------
// GEMM (generic, fp32 out) — used for the output projection.
// ---------------------------------------------------------------------------
__global__ __launch_bounds__(256, 2) void gemm_f16_kernel(
    const __half* __restrict__ A, const __half* __restrict__ Bh,
    const __half* __restrict__ Bl, float* __restrict__ C, int N, int K)
{
    extern __shared__ __half smb[];
    const int tid  = threadIdx.x;
    const int wid  = tid >> 5;
    const int lane = tid & 31;
    const int wm   = wid >> 2;
    const int wn   = wid & 3;
    const int row0 = blockIdx.y * 128;
    const int col0 = blockIdx.x * 128;
    const int lr = lane >> 2;
    const int lc = (lane & 3) * 2;
    const uint32_t sb = smem_u32(smb);
    const uint32_t laneA = ((lane & 15) * ASTR + (lane >> 4) * 8) * 2;
    const uint32_t laneB = (((lane >> 4) * 8 + (lane & 7)) * ASTR + ((lane >> 3) & 1) * 8) * 2;

    float acc[4][4][4];
    #pragma unroll
    for (int mt = 0; mt < 4; ++mt)
        #pragma unroll
        for (int nt = 0; nt < 4; ++nt)
            #pragma unroll
            for (int q = 0; q < 4; ++q) acc[mt][nt][q] = 0.f;

    GEMM_MAINLOOP(A, Bh, Bl, K)

    #pragma unroll
    for (int mt = 0; mt < 4; ++mt) {
        int row = row0 + wm * 64 + mt * 16 + lr;
        #pragma unroll
        for (int nt = 0; nt < 4; ++nt) {
            int col = col0 + wn * 32 + nt * 8 + lc;
            *(float2*)&C[(size_t)row * N + col] =
                make_float2(acc[mt][nt][0], acc[mt][nt][1]);
            *(float2*)&C[(size_t)(row + 8) * N + col] =
                make_float2(acc[mt][nt][2], acc[mt][nt][3]);
        }
    }
}

// ---------------------------------------------------------------------------
// Fused QKV GEMM: mainloop identical; epilogue does RMSNorm+RoPE+fp16 writes.
// blockIdx.x = head (col-tile 128 == one head). Heads: 0-15 Q, 16-19 K, 20-23 V.
// ---------------------------------------------------------------------------
__global__ __launch_bounds__(256, 2) void gemm_qkv_kernel(
    const __half* __restrict__ A, const __half* __restrict__ Bh,
    const __half* __restrict__ Bl,
    const float* __restrict__ cos_t, const float* __restrict__ sin_t,
    const float* __restrict__ q_ln, const float* __restrict__ k_ln, int K)
{
    extern __shared__ __half smb[];
    const int tid  = threadIdx.x;
    const int wid  = tid >> 5;
    const int lane = tid & 31;
    const int wm   = wid >> 2;
    const int wn   = wid & 3;
    const int row0 = blockIdx.y * 128;
    const int col0 = blockIdx.x * 128;
    const int lr = lane >> 2;
    const int lc = (lane & 3) * 2;
    const uint32_t sb = smem_u32(smb);
    const uint32_t laneA = ((lane & 15) * ASTR + (lane >> 4) * 8) * 2;
    const uint32_t laneB = (((lane >> 4) * 8 + (lane & 7)) * ASTR + ((lane >> 3) & 1) * 8) * 2;

    float acc[4][4][4];
    #pragma unroll
    for (int mt = 0; mt < 4; ++mt)
        #pragma unroll
        for (int nt = 0; nt < 4; ++nt)
            #pragma unroll
            for (int q = 0; q < 4; ++q) acc[mt][nt][q] = 0.f;

    GEMM_MAINLOOP(A, Bh, Bl, K)

    const int hh = blockIdx.x;   // head 0..23
    const float qscale = 0.08838834764831845f;

    // ---- V heads: direct fp16 store ----
    if (hh >= NH + NKV) {
        const int hv = hh - NH - NKV;
        #pragma unroll
        for (int mt = 0; mt < 4; ++mt) {
            int rA = row0 + wm * 64 + mt * 16 + lr;
            int rB = rA + 8;
            int bA = rA >> 11, sA = rA & (SS - 1);
            int bO = rB >> 11, sB = rB & (SS - 1);
            #pragma unroll
            for (int nt = 0; nt < 4; ++nt) {
                int d = wn * 32 + nt * 8 + lc;
                size_t oA = (((size_t)(bA * NKV + hv)) * SS + sA) * HD + d;
                size_t oB = (((size_t)(bO * NKV + hv)) * SS + sB) * HD + d;
                *(uint32_t*)&g_vh[oA] = f16x2(acc[mt][nt][0], acc[mt][nt][1]);
                *(uint32_t*)&g_vh[oB] = f16x2(acc[mt][nt][2], acc[mt][nt][3]);
            }
        }
        return;
    }

    // ---- Q/K heads: RMSNorm + RoPE ----
    float* red   = (float*)smb;          // [128][4]
    float* ypart = (float*)smb + 512;    // [128][64]

    __syncthreads();   // safe to reuse operand smem

    // per-row sum of squares
    #pragma unroll
    for (int mt = 0; mt < 4; ++mt) {
        float ss0 = 0.f, ss1 = 0.f;
        #pragma unroll
        for (int nt = 0; nt < 4; ++nt) {
            ss0 = fmaf(acc[mt][nt][0], acc[mt][nt][0], ss0);
            ss0 = fmaf(acc[mt][nt][1], acc[mt][nt][1], ss0);
            ss1 = fmaf(acc[mt][nt][2], acc[mt][nt][2], ss1);
            ss1 = fmaf(acc[mt][nt][3], acc[mt][nt][3], ss1);
        }
        ss0 += __shfl_xor_sync(0xFFFFFFFFu, ss0, 1);
        ss0 += __shfl_xor_sync(0xFFFFFFFFu, ss0, 2);
        ss1 += __shfl_xor_sync(0xFFFFFFFFu, ss1, 1);
        ss1 += __shfl_xor_sync(0xFFFFFFFFu, ss1, 2);
        if ((lane & 3) == 0) {
            int rl0 = wm * 64 + mt * 16 + lr;
            red[rl0 * 4 + wn]       = ss0;
            red[(rl0 + 8) * 4 + wn] = ss1;
        }
    }
    __syncthreads();

    // normalize (gamma * rsqrt), stage d<64 in smem for rotate-half
    const float* w = (hh < NH) ? q_ln : k_ln;
    #pragma unroll
    for (int mt = 0; mt < 4; ++mt) {
        int rl0 = wm * 64 + mt * 16 + lr;
        int rl1 = rl0 + 8;
        float v0 = (red[rl0 * 4 + 0] + red[rl0 * 4 + 1] + red[rl0 * 4 + 2] + red[rl0 * 4 + 3]) * (1.f / HD);
        float v1 = (red[rl1 * 4 + 0] + red[rl1 * 4 + 1] + red[rl1 * 4 + 2] + red[rl1 * 4 + 3]) * (1.f / HD);
        float r0 = rsqrtf(v0 + 1e-6f);
        float r1 = rsqrtf(v1 + 1e-6f);
        #pragma unroll
        for (int nt = 0; nt < 4; ++nt) {
            int d = wn * 32 + nt * 8 + lc;
            float w0 = w[d], w1 = w[d + 1];
            acc[mt][nt][0] *= r0 * w0;
            acc[mt][nt][1] *= r0 * w1;
            acc[mt][nt][2] *= r1 * w0;
            acc[mt][nt][3] *= r1 * w1;
            if (d < RR) {
                ypart[rl0 * RR + d]     = acc[mt][nt][0];
                ypart[rl0 * RR + d + 1] = acc[mt][nt][1];
                ypart[rl1 * RR + d]     = acc[mt][nt][2];
                ypart[rl1 * RR + d + 1] = acc[mt][nt][3];
            }
        }
    }
    __syncthreads();

    // RoPE + write
    #pragma unroll
    for (int mt = 0; mt < 4; ++mt) {
        int rl0 = wm * 64 + mt * 16 + lr;
        int rl1 = rl0 + 8;
        size_t t0 = (size_t)(row0 + rl0);   // token index == global row
        size_t t1 = (size_t)(row0 + rl1);
        int b0 = (int)(t0 >> 11), s0 = (int)(t0 & (SS - 1));
        int b1 = (int)(t1 >> 11), s1 = (int)(t1 & (SS - 1));
        #pragma unroll
        for (int nt = 0; nt < 4; ++nt) {
            int d = wn * 32 + nt * 8 + lc;
            float o0 = acc[mt][nt][0], o1 = acc[mt][nt][1];
            float o2 = acc[mt][nt][2], o3 = acc[mt][nt][3];
            if (d < RR) {
                float c0a = cos_t[t0 * RR + d], c0b = cos_t[t0 * RR + d + 1];
                float s0a = sin_t[t0 * RR + d], s0b = sin_t[t0 * RR + d + 1];
                float c1a = cos_t[t1 * RR + d], c1b = cos_t[t1 * RR + d + 1];
                float s1a = sin_t[t1 * RR + d], s1b = sin_t[t1 * RR + d + 1];
                float ra0, ra1, rb0, rb1;
                if (d < RR / 2) {
                    ra0 = -ypart[rl0 * RR + d + RR / 2];
                    ra1 = -ypart[rl0 * RR + d + 1 + RR / 2];
                    rb0 = -ypart[rl1 * RR + d + RR / 2];
                    rb1 = -ypart[rl1 * RR + d + 1 + RR / 2];
                } else {
                    ra0 = ypart[rl0 * RR + d - RR / 2];
                    ra1 = ypart[rl0 * RR + d + 1 - RR / 2];
                    rb0 = ypart[rl1 * RR + d - RR / 2];
                    rb1 = ypart[rl1 * RR + d + 1 - RR / 2];
                }
                o0 = fmaf(o0, c0a, ra0 * s0a);
                o1 = fmaf(o1, c0b, ra1 * s0b);
                o2 = fmaf(o2, c1a, rb0 * s1a);
                o3 = fmaf(o3, c1b, rb1 * s1b);
            }
            if (hh < NH) {
                o0 *= qscale; o1 *= qscale; o2 *= qscale; o3 *= qscale;
                size_t oA = (((size_t)(b0 * NH + hh)) * SS + s0) * HD + d;
                size_t oB = (((size_t)(b1 * NH + hh)) * SS + s1) * HD + d;
                uint32_t h0 = f16x2(o0, o1);
                __half2 th0 = *(__half2*)&h0;
                uint32_t l0 = f16x2(o0 - __low2float(th0), o1 - __high2float(th0));
                uint32_t h1 = f16x2(o2, o3);
                __half2 th1 = *(__half2*)&h1;
                uint32_t l1 = f16x2(o2 - __low2float(th1), o3 - __high2float(th1));
                *(uint32_t*)&g_qh[oA] = h0;
                *(uint32_t*)&g_ql[oA] = l0;
                *(uint32_t*)&g_qh[oB] = h1;
                *(uint32_t*)&g_ql[oB] = l1;
            } else {
                int hk = hh - NH;
                size_t oA = (((size_t)(b0 * NKV + hk)) * SS + s0) * HD + d;
                size_t oB = (((size_t)(b1 * NKV + hk)) * SS + s1) * HD + d;
                *(uint32_t*)&g_kh[oA] = f16x2(o0, o1);
                *(uint32_t*)&g_kh[oB] = f16x2(o2, o3);
            }
        }
    }
}

// ---------------------------------------------------------------------------
// Flash attention, K-tile 128, cp.async double-buffered fp16 K/V (round-13/14).
// ---------------------------------------------------------------------------
#define DSTR 136
#define KT   128
#define SKV  (2 * KT * DSTR)
#define AKV_OFF (2 * 128 * DSTR)
#define ATTN2_F16 (AKV_OFF + 2 * SKV)
#define ATTN2_SMEM (ATTN2_F16 * 2)        // ~204 KB

__global__ __launch_bounds__(256, 1) void attn_mma_kernel()
{
    extern __shared__ __half smh[];
    __half* Qhi = smh;
    __half* Qlo = Qhi + 128 * DSTR;

    const int tid  = threadIdx.x;
    const int wid  = tid >> 5;
    const int lane = tid & 31;
    const int gr   = lane >> 2;
    const int gc   = (lane & 3) * 2;
    const int q0 = blockIdx.x * 128;
    const int bh = blockIdx.y;
    const int b = bh >> 4;
    const int h = bh & 15;
    const int hk = h / (NH / NKV);
    const int m0 = wid * 16;

    const uint32_t sb = smem_u32(smh);
    const uint32_t kvOff = sb + (uint32_t)AKV_OFF * 2;
    const uint32_t laneA = ((lane & 15) * DSTR + (lane >> 4) * 8) * 2;
    const uint32_t laneB = (((lane >> 4) * 8 + (lane & 7)) * DSTR + ((lane >> 3) & 1) * 8) * 2;
    const uint32_t laneV = ((lane & 15) * DSTR + (lane >> 4) * 8) * 2;

    const uint32_t qBaseHi = sb + (uint32_t)(m0 * DSTR) * 2 + laneA;
    const uint32_t qBaseLo = qBaseHi + (uint32_t)(128 * DSTR) * 2;

    const size_t kvg = ((size_t)(b * NKV + hk)) * SS * HD;
    const __half* ksrc = g_kh + kvg;
    const __half* vsrc = g_vh + kvg;

    auto issue_kv = [&](int kt, int stg) {
        uint32_t sbase = kvOff + (uint32_t)stg * (SKV * 2);
        size_t goff = (size_t)kt * KT * HD;
        #pragma unroll
        for (int it = 0; it < 8; ++it) {
            int id = tid + it * 256;
            int r = id >> 4, g = id & 15;
            uint32_t so = (uint32_t)(r * DSTR * 2 + g * 16);
            CP_ASYNC16(sbase + so, ksrc + goff + (size_t)r * HD + g * 8);
            CP_ASYNC16(sbase + (uint32_t)(KT * DSTR * 2) + so,
                       vsrc + goff + (size_t)r * HD + g * 8);
        }
    };

    {
        const __half* qh = &g_qh[(((size_t)(b * NH + h)) * SS + q0) * HD];
        const __half* ql = &g_ql[(((size_t)(b * NH + h)) * SS + q0) * HD];
        #pragma unroll
        for (int it = 0; it < 8; ++it) {
            int id = tid + it * 256;
            int r = id >> 4, g = id & 15;
            *(uint4*)&Qhi[r * DSTR + g * 8] = *(const uint4*)&qh[(size_t)r * HD + g * 8];
            *(uint4*)&Qlo[r * DSTR + g * 8] = *(const uint4*)&ql[(size_t)r * HD + g * 8];
        }
    }

    issue_kv(0, 0);
    CP_COMMIT();

    float m_[2] = {-CUDART_INF_F, -CUDART_INF_F};
    float l_[2] = {0.f, 0.f};
    float O[16][4];
    #pragma unroll
    for (int nt = 0; nt < 16; ++nt)
        #pragma unroll
        for (int q = 0; q < 4; ++q) O[nt][q] = 0.f;

    __syncthreads();

    for (int kt = 0; kt < SS / KT; ++kt) {
        const int cur = kt & 1;
        if (kt + 1 < SS / KT) {
            issue_kv(kt + 1, 1 - cur);
            CP_COMMIT();
            CP_WAIT(1);
        } else {
            CP_WAIT(0);
        }
        __syncthreads();

        const uint32_t st = kvOff + (uint32_t)cur * (SKV * 2);
        const uint32_t kBase = st + laneB;
        const uint32_t vBase = st + (uint32_t)(KT * DSTR * 2) + laneV;

        float sc[16][4];
        #pragma unroll
        for (int nt = 0; nt < 16; ++nt)
            #pragma unroll
            for (int q = 0; q < 4; ++q) sc[nt][q] = 0.f;

        #pragma unroll
        for (int ks = 0; ks < 8; ++ks) {
            const uint32_t kkB = ks * 32;
            uint32_t qh4[4], ql4[4];
            ldsm_x4(qh4, qBaseHi + kkB);
            ldsm_x4(ql4, qBaseLo + kkB);
            #pragma unroll
            for (int np = 0; np < 8; ++np) {
                uint32_t kb4[4];
                ldsm_x4(kb4, kBase + (uint32_t)np * (16 * DSTR * 2) + kkB);
                mma_f16(sc[2*np],   qh4, &kb4[0]);
                mma_f16(sc[2*np],   ql4, &kb4[0]);
                mma_f16(sc[2*np+1], qh4, &kb4[2]);
                mma_f16(sc[2*np+1], ql4, &kb4[2]);
            }
        }

        float mx0 = -CUDART_INF_F, mx1 = -CUDART_INF_F;
        #pragma unroll
        for (int nt = 0; nt < 16; ++nt) {
            mx0 = fmaxf(mx0, fmaxf(sc[nt][0], sc[nt][1]));
            mx1 = fmaxf(mx1, fmaxf(sc[nt][2], sc[nt][3]));
        }
        mx0 = fmaxf(mx0, __shfl_xor_sync(0xFFFFFFFFu, mx0, 1));
        mx0 = fmaxf(mx0, __shfl_xor_sync(0xFFFFFFFFu, mx0, 2));
        mx1 = fmaxf(mx1, __shfl_xor_sync(0xFFFFFFFFu, mx1, 1));
        mx1 = fmaxf(mx1, __shfl_xor_sync(0xFFFFFFFFu, mx1, 2));

        float mn0 = fmaxf(m_[0], mx0);
        float mn1 = fmaxf(m_[1], mx1);
        float scl0 = __expf(m_[0] - mn0);
        float scl1 = __expf(m_[1] - mn1);
        m_[0] = mn0; m_[1] = mn1;

        float rs0 = 0.f, rs1 = 0.f;
        #pragma unroll
        for (int nt = 0; nt < 16; ++nt) {
            sc[nt][0] = __expf(sc[nt][0] - mn0);
            sc[nt][1] = __expf(sc[nt][1] - mn0);
            sc[nt][2] = __expf(sc[nt][2] - mn1);
            sc[nt][3] = __expf(sc[nt][3] - mn1);
            rs0 += sc[nt][0] + sc[nt][1];
            rs1 += sc[nt][2] + sc[nt][3];
        }
        rs0 += __shfl_xor_sync(0xFFFFFFFFu, rs0, 1);
        rs0 += __shfl_xor_sync(0xFFFFFFFFu, rs0, 2);
        rs1 += __shfl_xor_sync(0xFFFFFFFFu, rs1, 1);
        rs1 += __shfl_xor_sync(0xFFFFFFFFu, rs1, 2);
        l_[0] = l_[0] * scl0 + rs0;
        l_[1] = l_[1] * scl1 + rs1;

        #pragma unroll
        for (int nt = 0; nt < 16; ++nt) {
            O[nt][0] *= scl0; O[nt][1] *= scl0;
            O[nt][2] *= scl1; O[nt][3] *= scl1;
        }

        #pragma unroll
        for (int k2 = 0; k2 < 8; ++k2) {
            uint32_t paH[4], paL[4];
            #pragma unroll
            for (int half_ = 0; half_ < 2; ++half_) {
                float a = sc[2*k2 + half_][0], bq = sc[2*k2 + half_][1];
                float c = sc[2*k2 + half_][2], dq = sc[2*k2 + half_][3];
                uint32_t h0 = f16x2(a, bq);
                __half2 t0 = *(__half2*)&h0;
                uint32_t l0 = f16x2(a - __low2float(t0), bq - __high2float(t0));
                uint32_t h1 = f16x2(c, dq);
                __half2 t1 = *(__half2*)&h1;
                uint32_t l1 = f16x2(c - __low2float(t1), dq - __high2float(t1));
                paH[half_ * 2 + 0] = h0; paH[half_ * 2 + 1] = h1;
                paL[half_ * 2 + 0] = l0; paL[half_ * 2 + 1] = l1;
            }
            const uint32_t kOff = (uint32_t)k2 * (16 * DSTR * 2);
            #pragma unroll
            for (int np = 0; np < 8; ++np) {
                uint32_t vb4[4];
                ldsm_x4_t(vb4, vBase + kOff + (uint32_t)np * 32);
                mma_f16(O[2*np],   paH, &vb4[0]);
                mma_f16(O[2*np],   paL, &vb4[0]);
                mma_f16(O[2*np+1], paH, &vb4[2]);
                mma_f16(O[2*np+1], paL, &vb4[2]);
            }
        }
        __syncthreads();
    }

    const float inv0 = 1.f / l_[0];
    const float inv1 = 1.f / l_[1];
    const int s0 = q0 + m0 + gr;
    #pragma unroll
    for (int nt = 0; nt < 16; ++nt) {
        int col = nt * 8 + gc;
        size_t off0 = (((size_t)b * SS + s0) * NH + h) * HD + col;
        size_t off1 = (((size_t)b * SS + s0 + 8) * NH + h) * HD + col;
        *(uint32_t*)&g_attnh[off0] = f16x2(O[nt][0] * inv0, O[nt][1] * inv0);
        *(uint32_t*)&g_attnh[off1] = f16x2(O[nt][2] * inv1, O[nt][3] * inv1);
    }
}

// ---------------------------------------------------------------------------
extern "C" void kernel_launch(void* const* d_in, const int* in_sizes, int n_in,
                              void* d_out, int out_size)
{
    const float* hidden  = (const float*)d_in[0];
    const float* cos_t   = (const float*)d_in[1];
    const float* sin_t   = (const float*)d_in[2];
    const float* w_qkv   = (const float*)d_in[3];
    const float* q_ln    = (const float*)d_in[4];
    const float* k_ln    = (const float*)d_in[5];
    const float* w_dense = (const float*)d_in[6];
    float* out = (float*)d_out;

    void *p_ah, *p_wh, *p_wl, *p_attnh;
    cudaGetSymbolAddress(&p_ah, g_ah);
    cudaGetSymbolAddress(&p_wh, g_wh);
    cudaGetSymbolAddress(&p_wl, g_wl);
    cudaGetSymbolAddress(&p_attnh, g_attnh);
    __half* ah    = (__half*)p_ah;
    __half* wh    = (__half*)p_wh;
    __half* wl    = (__half*)p_wl;
    __half* attnh = (__half*)p_attnh;

    cudaFuncSetAttribute(gemm_f16_kernel,
                         cudaFuncAttributeMaxDynamicSharedMemorySize, GEMM_SMEM);
    cudaFuncSetAttribute(gemm_qkv_kernel,
                         cudaFuncAttributeMaxDynamicSharedMemorySize, GEMM_SMEM);
    cudaFuncSetAttribute(attn_mma_kernel,
                         cudaFuncAttributeMaxDynamicSharedMemorySize, ATTN2_SMEM);

    // 0) convert hidden -> fp16; split w_qkv -> fp16 hi/lo
    cvt_f16_kernel<<<(NTOK * HID / 4 + 255) / 256, 256>>>(hidden, ah, NTOK * HID / 4);
    split_f16_kernel<<<(QKVO * HID / 4 + 255) / 256, 256>>>(w_qkv, wh, wl, QKVO * HID / 4);

    // 1) Fused QKV projection + RMSNorm + RoPE -> fp16 Q(hi/lo)/K/V
    gemm_qkv_kernel<<<dim3(QKVO / 128, NTOK / 128), 256, GEMM_SMEM>>>(
        ah, wh, wl, cos_t, sin_t, q_ln, k_ln, HID);

    // 2) Flash attention -> fp16 output
    attn_mma_kernel<<<dim3(SS / 128, BB * NH), 256, ATTN2_SMEM>>>();

    // 2b) split w_dense (reuses g_wh/g_wl; safe after GEMM1)
    split_f16_kernel<<<(HID * HID / 4 + 255) / 256, 256>>>(w_dense, wh, wl, HID * HID / 4);

    // 3) Output projection
    gemm_f16_kernel<<<dim3(HID / 128, NTOK / 128), 256, GEMM_SMEM>>>(
        attnh, wh, wl, out, HID, HID);
}

// round 17
// speedup vs baseline: 2.7642x; 1.1781x over previous
#include <cuda_runtime.h>
#include <cuda_fp16.h>
#include <math_constants.h>
#include <cstdint>

// Problem dims
#define BB   2
#define SS   2048
#define HID  2048
#define NH   16
#define NKV  4
#define HD   128
#define RR   64
#define NTOK (BB*SS)          // 4096
#define QKVO ((NH+2*NKV)*HD)  // 3072

// Scratch (device globals; no allocation allowed)
__device__ __half g_ah[(size_t)NTOK * HID];           // hidden, fp16
__device__ __half g_wh[(size_t)QKVO * HID];           // weight hi (w_qkv then w_dense)
__device__ __half g_wl[(size_t)QKVO * HID];           // weight lo
__device__ __half g_qh[(size_t)BB * NH  * SS * HD];   // Q fp16 (pre-scaled)
__device__ __half g_kh[(size_t)BB * NKV * SS * HD];   // K fp16
__device__ __half g_vh[(size_t)BB * NKV * SS * HD];   // V fp16
__device__ __half g_attnh[(size_t)NTOK * (NH*HD)];    // attn out fp16

// ---------------------------------------------------------------------------
// PTX helpers (base PTX only — compute_103-safe)
// ---------------------------------------------------------------------------
__device__ __forceinline__ void mma_f16(float* c, const uint32_t* a, const uint32_t* b) {
    asm volatile(
        "mma.sync.aligned.m16n8k16.row.col.f32.f16.f16.f32 "
        "{%0,%1,%2,%3}, {%4,%5,%6,%7}, {%8,%9}, {%0,%1,%2,%3};"
        : "+f"(c[0]), "+f"(c[1]), "+f"(c[2]), "+f"(c[3])
        : "r"(a[0]), "r"(a[1]), "r"(a[2]), "r"(a[3]), "r"(b[0]), "r"(b[1]));
}

__device__ __forceinline__ void ldsm_x4(uint32_t* r, uint32_t addr) {
    asm volatile("ldmatrix.sync.aligned.m8n8.x4.shared.b16 {%0,%1,%2,%3}, [%4];"
        : "=r"(r[0]), "=r"(r[1]), "=r"(r[2]), "=r"(r[3]) : "r"(addr));
}

__device__ __forceinline__ void ldsm_x4_t(uint32_t* r, uint32_t addr) {
    asm volatile("ldmatrix.sync.aligned.m8n8.x4.trans.shared.b16 {%0,%1,%2,%3}, [%4];"
        : "=r"(r[0]), "=r"(r[1]), "=r"(r[2]), "=r"(r[3]) : "r"(addr));
}

__device__ __forceinline__ uint32_t smem_u32(const void* p) {
    uint32_t a;
    asm("{ .reg .u64 t; cvta.to.shared.u64 t, %1; cvt.u32.u64 %0, t; }"
        : "=r"(a) : "l"(p));
    return a;
}

#define CP_ASYNC16(saddr, gptr) \
    asm volatile("cp.async.cg.shared.global [%0], [%1], 16;" \
                 :: "r"(saddr), "l"(gptr))
#define CP_COMMIT() asm volatile("cp.async.commit_group;" ::: "memory")
#define CP_WAIT(n)  asm volatile("cp.async.wait_group %0;" :: "n"(n) : "memory")

__device__ __forceinline__ uint32_t f16x2(float x, float y) {
    __half2 h = __floats2half2_rn(x, y);
    return *(uint32_t*)&h;
}

// ---------------------------------------------------------------------------
// Elementwise converters
// ---------------------------------------------------------------------------
__global__ __launch_bounds__(256) void cvt_f16_kernel(
    const float* __restrict__ in, __half* __restrict__ outp, int n4)
{
    int i = blockIdx.x * blockDim.x + threadIdx.x;
    if (i < n4) {
        float4 v = ((const float4*)in)[i];
        ((uint2*)outp)[i] = make_uint2(f16x2(v.x, v.y), f16x2(v.z, v.w));
    }
}

__global__ __launch_bounds__(256) void split_f16_kernel(
    const float* __restrict__ in, __half* __restrict__ hi,
    __half* __restrict__ lo, int n4)
{
    int i = blockIdx.x * blockDim.x + threadIdx.x;
    if (i < n4) {
        float4 v = ((const float4*)in)[i];
        uint32_t h0 = f16x2(v.x, v.y);
        uint32_t h1 = f16x2(v.z, v.w);
        __half2 t0 = *(__half2*)&h0;
        __half2 t1 = *(__half2*)&h1;
        uint32_t l0 = f16x2(v.x - __low2float(t0), v.y - __high2float(t0));
        uint32_t l1 = f16x2(v.z - __low2float(t1), v.w - __high2float(t1));
        ((uint2*)hi)[i] = make_uint2(h0, h1);
        ((uint2*)lo)[i] = make_uint2(l0, l1);
    }
}

// ---------------------------------------------------------------------------
// GEMM geometry (shared)
// ---------------------------------------------------------------------------
#define TBK 32
#define ASTR 40
#define ARR (128 * ASTR)
#define STAGE3 (3 * ARR)
#define GEMM_SMEM (2 * STAGE3 * 2)       // 61440 B

#define GEMM_MAINLOOP(A_, Bh_, Bl_, K_)                                          \
    const __half* src0 = (A_)  + (size_t)row0 * (K_);                            \
    const __half* src1 = (Bh_) + (size_t)col0 * (K_);                            \
    const __half* src2 = (Bl_) + (size_t)col0 * (K_);                            \
    auto issue_chunk = [&](int ic, int stg) {                                    \
        uint32_t sbase = sb + (uint32_t)stg * (STAGE3 * 2);                      \
        const size_t koff = (size_t)ic * TBK;                                    \
        _Pragma("unroll")                                                        \
        for (int it = 0; it < 2; ++it) {                                         \
            int id = tid + it * 256;                                             \
            int r = id >> 2, g = id & 3;                                         \
            uint32_t so = (uint32_t)(r * ASTR * 2 + g * 16);                     \
            size_t go = (size_t)r * (K_) + koff + g * 8;                         \
            CP_ASYNC16(sbase + so, src0 + go);                                   \
            CP_ASYNC16(sbase + (uint32_t)(ARR * 2) + so, src1 + go);             \
            CP_ASYNC16(sbase + (uint32_t)(2 * ARR * 2) + so, src2 + go);         \
        }                                                                        \
    };                                                                           \
    issue_chunk(0, 0);                                                           \
    CP_COMMIT();                                                                 \
    const int nchunk = (K_) / TBK;                                               \
    for (int ic = 0; ic < nchunk; ++ic) {                                        \
        const int cur = ic & 1;                                                  \
        if (ic + 1 < nchunk) { issue_chunk(ic + 1, 1 - cur); CP_COMMIT(); CP_WAIT(1); } \
        else                 { CP_WAIT(0); }                                     \
        __syncthreads();                                                         \
        const uint32_t stOff = (uint32_t)cur * (STAGE3 * 2);                     \
        const uint32_t aBase  = sb + stOff + (uint32_t)(wm * 64) * (ASTR * 2) + laneA; \
        const uint32_t bhBase = sb + stOff + (uint32_t)(ARR * 2)                 \
                              + (uint32_t)(wn * 32) * (ASTR * 2) + laneB;        \
        const uint32_t blBase = bhBase + (uint32_t)(ARR * 2);                    \
        _Pragma("unroll")                                                        \
        for (int ks = 0; ks < 2; ++ks) {                                         \
            const uint32_t kkB = ks * 32;                                        \
            uint32_t ah[4][4], bh4[2][4], bl4[2][4];                             \
            _Pragma("unroll")                                                    \
            for (int mt = 0; mt < 4; ++mt)                                       \
                ldsm_x4(ah[mt], aBase + (uint32_t)mt * (16 * ASTR * 2) + kkB);   \
            _Pragma("unroll")                                                    \
            for (int np = 0; np < 2; ++np) {                                     \
                ldsm_x4(bh4[np], bhBase + (uint32_t)np * (16 * ASTR * 2) + kkB); \
                ldsm_x4(bl4[np], blBase + (uint32_t)np * (16 * ASTR * 2) + kkB); \
            }                                                                    \
            _Pragma("unroll")                                                    \
            for (int mt = 0; mt < 4; ++mt)                                       \
                _Pragma("unroll")                                                \
                for (int nt = 0; nt < 4; ++nt) {                                 \
                    mma_f16(acc[mt][nt], ah[mt], &bh4[nt >> 1][(nt & 1) * 2]);   \
                    mma_f16(acc[mt][nt], ah[mt], &bl4[nt >> 1][(nt & 1) * 2]);   \
                }                                                                \
        }                                                                        \
        __syncthreads();                                                         \
    }

// ---------------------------------------------------------------------------
// GEMM (generic, fp32 out) — output projection.
// ---------------------------------------------------------------------------
__global__ __launch_bounds__(256, 2) void gemm_f16_kernel(
    const __half* __restrict__ A, const __half* __restrict__ Bh,
    const __half* __restrict__ Bl, float* __restrict__ C, int N, int K)
{
    extern __shared__ __half smb[];
    const int tid  = threadIdx.x;
    const int wid  = tid >> 5;
    const int lane = tid & 31;
    const int wm   = wid >> 2;
    const int wn   = wid & 3;
    const int row0 = blockIdx.y * 128;
    const int col0 = blockIdx.x * 128;
    const int lr = lane >> 2;
    const int lc = (lane & 3) * 2;
    const uint32_t sb = smem_u32(smb);
    const uint32_t laneA = ((lane & 15) * ASTR + (lane >> 4) * 8) * 2;
    const uint32_t laneB = (((lane >> 4) * 8 + (lane & 7)) * ASTR + ((lane >> 3) & 1) * 8) * 2;

    float acc[4][4][4];
    #pragma unroll
    for (int mt = 0; mt < 4; ++mt)
        #pragma unroll
        for (int nt = 0; nt < 4; ++nt)
            #pragma unroll
            for (int q = 0; q < 4; ++q) acc[mt][nt][q] = 0.f;

    GEMM_MAINLOOP(A, Bh, Bl, K)

    #pragma unroll
    for (int mt = 0; mt < 4; ++mt) {
        int row = row0 + wm * 64 + mt * 16 + lr;
        #pragma unroll
        for (int nt = 0; nt < 4; ++nt) {
            int col = col0 + wn * 32 + nt * 8 + lc;
            *(float2*)&C[(size_t)row * N + col] =
                make_float2(acc[mt][nt][0], acc[mt][nt][1]);
            *(float2*)&C[(size_t)(row + 8) * N + col] =
                make_float2(acc[mt][nt][2], acc[mt][nt][3]);
        }
    }
}

// ---------------------------------------------------------------------------
// Fused QKV GEMM + RMSNorm + RoPE epilogue (round-16 proven).
// Q now written single fp16 (no lo).
// ---------------------------------------------------------------------------
__global__ __launch_bounds__(256, 2) void gemm_qkv_kernel(
    const __half* __restrict__ A, const __half* __restrict__ Bh,
    const __half* __restrict__ Bl,
    const float* __restrict__ cos_t, const float* __restrict__ sin_t,
    const float* __restrict__ q_ln, const float* __restrict__ k_ln, int K)
{
    extern __shared__ __half smb[];
    const int tid  = threadIdx.x;
    const int wid  = tid >> 5;
    const int lane = tid & 31;
    const int wm   = wid >> 2;
    const int wn   = wid & 3;
    const int row0 = blockIdx.y * 128;
    const int col0 = blockIdx.x * 128;
    const int lr = lane >> 2;
    const int lc = (lane & 3) * 2;
    const uint32_t sb = smem_u32(smb);
    const uint32_t laneA = ((lane & 15) * ASTR + (lane >> 4) * 8) * 2;
    const uint32_t laneB = (((lane >> 4) * 8 + (lane & 7)) * ASTR + ((lane >> 3) & 1) * 8) * 2;

    float acc[4][4][4];
    #pragma unroll
    for (int mt = 0; mt < 4; ++mt)
        #pragma unroll
        for (int nt = 0; nt < 4; ++nt)
            #pragma unroll
            for (int q = 0; q < 4; ++q) acc[mt][nt][q] = 0.f;

    GEMM_MAINLOOP(A, Bh, Bl, K)

    const int hh = blockIdx.x;   // head 0..23
    const float qscale = 0.08838834764831845f;

    if (hh >= NH + NKV) {
        const int hv = hh - NH - NKV;
        #pragma unroll
        for (int mt = 0; mt < 4; ++mt) {
            int rA = row0 + wm * 64 + mt * 16 + lr;
            int rB = rA + 8;
            int bA = rA >> 11, sA = rA & (SS - 1);
            int bO = rB >> 11, sB = rB & (SS - 1);
            #pragma unroll
            for (int nt = 0; nt < 4; ++nt) {
                int d = wn * 32 + nt * 8 + lc;
                size_t oA = (((size_t)(bA * NKV + hv)) * SS + sA) * HD + d;
                size_t oB = (((size_t)(bO * NKV + hv)) * SS + sB) * HD + d;
                *(uint32_t*)&g_vh[oA] = f16x2(acc[mt][nt][0], acc[mt][nt][1]);
                *(uint32_t*)&g_vh[oB] = f16x2(acc[mt][nt][2], acc[mt][nt][3]);
            }
        }
        return;
    }

    float* red   = (float*)smb;          // [128][4]
    float* ypart = (float*)smb + 512;    // [128][64]

    __syncthreads();

    #pragma unroll
    for (int mt = 0; mt < 4; ++mt) {
        float ss0 = 0.f, ss1 = 0.f;
        #pragma unroll
        for (int nt = 0; nt < 4; ++nt) {
            ss0 = fmaf(acc[mt][nt][0], acc[mt][nt][0], ss0);
            ss0 = fmaf(acc[mt][nt][1], acc[mt][nt][1], ss0);
            ss1 = fmaf(acc[mt][nt][2], acc[mt][nt][2], ss1);
            ss1 = fmaf(acc[mt][nt][3], acc[mt][nt][3], ss1);
        }
        ss0 += __shfl_xor_sync(0xFFFFFFFFu, ss0, 1);
        ss0 += __shfl_xor_sync(0xFFFFFFFFu, ss0, 2);
        ss1 += __shfl_xor_sync(0xFFFFFFFFu, ss1, 1);
        ss1 += __shfl_xor_sync(0xFFFFFFFFu, ss1, 2);
        if ((lane & 3) == 0) {
            int rl0 = wm * 64 + mt * 16 + lr;
            red[rl0 * 4 + wn]       = ss0;
            red[(rl0 + 8) * 4 + wn] = ss1;
        }
    }
    __syncthreads();

    const float* w = (hh < NH) ? q_ln : k_ln;
    #pragma unroll
    for (int mt = 0; mt < 4; ++mt) {
        int rl0 = wm * 64 + mt * 16 + lr;
        int rl1 = rl0 + 8;
        float v0 = (red[rl0 * 4 + 0] + red[rl0 * 4 + 1] + red[rl0 * 4 + 2] + red[rl0 * 4 + 3]) * (1.f / HD);
        float v1 = (red[rl1 * 4 + 0] + red[rl1 * 4 + 1] + red[rl1 * 4 + 2] + red[rl1 * 4 + 3]) * (1.f / HD);
        float r0 = rsqrtf(v0 + 1e-6f);
        float r1 = rsqrtf(v1 + 1e-6f);
        #pragma unroll
        for (int nt = 0; nt < 4; ++nt) {
            int d = wn * 32 + nt * 8 + lc;
            float w0 = w[d], w1 = w[d + 1];
            acc[mt][nt][0] *= r0 * w0;
            acc[mt][nt][1] *= r0 * w1;
            acc[mt][nt][2] *= r1 * w0;
            acc[mt][nt][3] *= r1 * w1;
            if (d < RR) {
                ypart[rl0 * RR + d]     = acc[mt][nt][0];
                ypart[rl0 * RR + d + 1] = acc[mt][nt][1];
                ypart[rl1 * RR + d]     = acc[mt][nt][2];
                ypart[rl1 * RR + d + 1] = acc[mt][nt][3];
            }
        }
    }
    __syncthreads();

    #pragma unroll
    for (int mt = 0; mt < 4; ++mt) {
        int rl0 = wm * 64 + mt * 16 + lr;
        int rl1 = rl0 + 8;
        size_t t0 = (size_t)(row0 + rl0);
        size_t t1 = (size_t)(row0 + rl1);
        int b0 = (int)(t0 >> 11), s0 = (int)(t0 & (SS - 1));
        int b1 = (int)(t1 >> 11), s1 = (int)(t1 & (SS - 1));
        #pragma unroll
        for (int nt = 0; nt < 4; ++nt) {
            int d = wn * 32 + nt * 8 + lc;
            float o0 = acc[mt][nt][0], o1 = acc[mt][nt][1];
            float o2 = acc[mt][nt][2], o3 = acc[mt][nt][3];
            if (d < RR) {
                float c0a = cos_t[t0 * RR + d], c0b = cos_t[t0 * RR + d + 1];
                float s0a = sin_t[t0 * RR + d], s0b = sin_t[t0 * RR + d + 1];
                float c1a = cos_t[t1 * RR + d], c1b = cos_t[t1 * RR + d + 1];
                float s1a = sin_t[t1 * RR + d], s1b = sin_t[t1 * RR + d + 1];
                float ra0, ra1, rb0, rb1;
                if (d < RR / 2) {
                    ra0 = -ypart[rl0 * RR + d + RR / 2];
                    ra1 = -ypart[rl0 * RR + d + 1 + RR / 2];
                    rb0 = -ypart[rl1 * RR + d + RR / 2];
                    rb1 = -ypart[rl1 * RR + d + 1 + RR / 2];
                } else {
                    ra0 = ypart[rl0 * RR + d - RR / 2];
                    ra1 = ypart[rl0 * RR + d + 1 - RR / 2];
                    rb0 = ypart[rl1 * RR + d - RR / 2];
                    rb1 = ypart[rl1 * RR + d + 1 - RR / 2];
                }
                o0 = fmaf(o0, c0a, ra0 * s0a);
                o1 = fmaf(o1, c0b, ra1 * s0b);
                o2 = fmaf(o2, c1a, rb0 * s1a);
                o3 = fmaf(o3, c1b, rb1 * s1b);
            }
            if (hh < NH) {
                o0 *= qscale; o1 *= qscale; o2 *= qscale; o3 *= qscale;
                size_t oA = (((size_t)(b0 * NH + hh)) * SS + s0) * HD + d;
                size_t oB = (((size_t)(b1 * NH + hh)) * SS + s1) * HD + d;
                *(uint32_t*)&g_qh[oA] = f16x2(o0, o1);
                *(uint32_t*)&g_qh[oB] = f16x2(o2, o3);
            } else {
                int hk = hh - NH;
                size_t oA = (((size_t)(b0 * NKV + hk)) * SS + s0) * HD + d;
                size_t oB = (((size_t)(b1 * NKV + hk)) * SS + s1) * HD + d;
                *(uint32_t*)&g_kh[oA] = f16x2(o0, o1);
                *(uint32_t*)&g_kh[oB] = f16x2(o2, o3);
            }
        }
    }
}

// ---------------------------------------------------------------------------
// Flash attention, K-tile 128, all single-fp16 operands (1-term S, 1-term PV).
// ---------------------------------------------------------------------------
#define DSTR 136
#define KT   128
#define SKV  (2 * KT * DSTR)
#define AKV_OFF (128 * DSTR)              // after Qh only
#define ATTN2_F16 (AKV_OFF + 2 * SKV)
#define ATTN2_SMEM (ATTN2_F16 * 2)        // ~174 KB

__global__ __launch_bounds__(256, 1) void attn_mma_kernel()
{
    extern __shared__ __half smh[];
    __half* Qh = smh;

    const int tid  = threadIdx.x;
    const int wid  = tid >> 5;
    const int lane = tid & 31;
    const int gr   = lane >> 2;
    const int gc   = (lane & 3) * 2;
    const int q0 = blockIdx.x * 128;
    const int bh = blockIdx.y;
    const int b = bh >> 4;
    const int h = bh & 15;
    const int hk = h / (NH / NKV);
    const int m0 = wid * 16;

    const uint32_t sb = smem_u32(smh);
    const uint32_t kvOff = sb + (uint32_t)AKV_OFF * 2;
    const uint32_t laneA = ((lane & 15) * DSTR + (lane >> 4) * 8) * 2;
    const uint32_t laneB = (((lane >> 4) * 8 + (lane & 7)) * DSTR + ((lane >> 3) & 1) * 8) * 2;
    const uint32_t laneV = ((lane & 15) * DSTR + (lane >> 4) * 8) * 2;

    const uint32_t qBase = sb + (uint32_t)(m0 * DSTR) * 2 + laneA;

    const size_t kvg = ((size_t)(b * NKV + hk)) * SS * HD;
    const __half* ksrc = g_kh + kvg;
    const __half* vsrc = g_vh + kvg;

    auto issue_kv = [&](int kt, int stg) {
        uint32_t sbase = kvOff + (uint32_t)stg * (SKV * 2);
        size_t goff = (size_t)kt * KT * HD;
        #pragma unroll
        for (int it = 0; it < 8; ++it) {
            int id = tid + it * 256;
            int r = id >> 4, g = id & 15;
            uint32_t so = (uint32_t)(r * DSTR * 2 + g * 16);
            CP_ASYNC16(sbase + so, ksrc + goff + (size_t)r * HD + g * 8);
            CP_ASYNC16(sbase + (uint32_t)(KT * DSTR * 2) + so,
                       vsrc + goff + (size_t)r * HD + g * 8);
        }
    };

    {
        const __half* qh = &g_qh[(((size_t)(b * NH + h)) * SS + q0) * HD];
        #pragma unroll
        for (int it = 0; it < 8; ++it) {
            int id = tid + it * 256;
            int r = id >> 4, g = id & 15;
            *(uint4*)&Qh[r * DSTR + g * 8] = *(const uint4*)&qh[(size_t)r * HD + g * 8];
        }
    }

    issue_kv(0, 0);
    CP_COMMIT();

    float m_[2] = {-CUDART_INF_F, -CUDART_INF_F};
    float l_[2] = {0.f, 0.f};
    float O[16][4];
    #pragma unroll
    for (int nt = 0; nt < 16; ++nt)
        #pragma unroll
        for (int q = 0; q < 4; ++q) O[nt][q] = 0.f;

    __syncthreads();

    for (int kt = 0; kt < SS / KT; ++kt) {
        const int cur = kt & 1;
        if (kt + 1 < SS / KT) {
            issue_kv(kt + 1, 1 - cur);
            CP_COMMIT();
            CP_WAIT(1);
        } else {
            CP_WAIT(0);
        }
        __syncthreads();

        const uint32_t st = kvOff + (uint32_t)cur * (SKV * 2);
        const uint32_t kBase = st + laneB;
        const uint32_t vBase = st + (uint32_t)(KT * DSTR * 2) + laneV;

        // ---- S = Q K^T (single term) ----
        float sc[16][4];
        #pragma unroll
        for (int nt = 0; nt < 16; ++nt)
            #pragma unroll
            for (int q = 0; q < 4; ++q) sc[nt][q] = 0.f;

        #pragma unroll
        for (int ks = 0; ks < 8; ++ks) {
            const uint32_t kkB = ks * 32;
            uint32_t qh4[4];
            ldsm_x4(qh4, qBase + kkB);
            #pragma unroll
            for (int np = 0; np < 8; ++np) {
                uint32_t kb4[4];
                ldsm_x4(kb4, kBase + (uint32_t)np * (16 * DSTR * 2) + kkB);
                mma_f16(sc[2*np],   qh4, &kb4[0]);
                mma_f16(sc[2*np+1], qh4, &kb4[2]);
            }
        }

        // ---- online softmax ----
        float mx0 = -CUDART_INF_F, mx1 = -CUDART_INF_F;
        #pragma unroll
        for (int nt = 0; nt < 16; ++nt) {
            mx0 = fmaxf(mx0, fmaxf(sc[nt][0], sc[nt][1]));
            mx1 = fmaxf(mx1, fmaxf(sc[nt][2], sc[nt][3]));
        }
        mx0 = fmaxf(mx0, __shfl_xor_sync(0xFFFFFFFFu, mx0, 1));
        mx0 = fmaxf(mx0, __shfl_xor_sync(0xFFFFFFFFu, mx0, 2));
        mx1 = fmaxf(mx1, __shfl_xor_sync(0xFFFFFFFFu, mx1, 1));
        mx1 = fmaxf(mx1, __shfl_xor_sync(0xFFFFFFFFu, mx1, 2));

        float mn0 = fmaxf(m_[0], mx0);
        float mn1 = fmaxf(m_[1], mx1);
        float scl0 = __expf(m_[0] - mn0);
        float scl1 = __expf(m_[1] - mn1);
        m_[0] = mn0; m_[1] = mn1;

        float rs0 = 0.f, rs1 = 0.f;
        #pragma unroll
        for (int nt = 0; nt < 16; ++nt) {
            sc[nt][0] = __expf(sc[nt][0] - mn0);
            sc[nt][1] = __expf(sc[nt][1] - mn0);
            sc[nt][2] = __expf(sc[nt][2] - mn1);
            sc[nt][3] = __expf(sc[nt][3] - mn1);
            rs0 += sc[nt][0] + sc[nt][1];
            rs1 += sc[nt][2] + sc[nt][3];
        }
        rs0 += __shfl_xor_sync(0xFFFFFFFFu, rs0, 1);
        rs0 += __shfl_xor_sync(0xFFFFFFFFu, rs0, 2);
        rs1 += __shfl_xor_sync(0xFFFFFFFFu, rs1, 1);
        rs1 += __shfl_xor_sync(0xFFFFFFFFu, rs1, 2);
        l_[0] = l_[0] * scl0 + rs0;
        l_[1] = l_[1] * scl1 + rs1;

        #pragma unroll
        for (int nt = 0; nt < 16; ++nt) {
            O[nt][0] *= scl0; O[nt][1] *= scl0;
            O[nt][2] *= scl1; O[nt][3] *= scl1;
        }

        // ---- PV: single term ----
        #pragma unroll
        for (int k2 = 0; k2 < 8; ++k2) {
            uint32_t paH[4];
            paH[0] = f16x2(sc[2*k2][0],     sc[2*k2][1]);
            paH[1] = f16x2(sc[2*k2][2],     sc[2*k2][3]);
            paH[2] = f16x2(sc[2*k2+1][0],   sc[2*k2+1][1]);
            paH[3] = f16x2(sc[2*k2+1][2],   sc[2*k2+1][3]);
            const uint32_t kOff = (uint32_t)k2 * (16 * DSTR * 2);
            #pragma unroll
            for (int np = 0; np < 8; ++np) {
                uint32_t vb4[4];
                ldsm_x4_t(vb4, vBase + kOff + (uint32_t)np * 32);
                mma_f16(O[2*np],   paH, &vb4[0]);
                mma_f16(O[2*np+1], paH, &vb4[2]);
            }
        }
        __syncthreads();
    }

    const float inv0 = 1.f / l_[0];
    const float inv1 = 1.f / l_[1];
    const int s0 = q0 + m0 + gr;
    #pragma unroll
    for (int nt = 0; nt < 16; ++nt) {
        int col = nt * 8 + gc;
        size_t off0 = (((size_t)b * SS + s0) * NH + h) * HD + col;
        size_t off1 = (((size_t)b * SS + s0 + 8) * NH + h) * HD + col;
        *(uint32_t*)&g_attnh[off0] = f16x2(O[nt][0] * inv0, O[nt][1] * inv0);
        *(uint32_t*)&g_attnh[off1] = f16x2(O[nt][2] * inv1, O[nt][3] * inv1);
    }
}

// ---------------------------------------------------------------------------
extern "C" void kernel_launch(void* const* d_in, const int* in_sizes, int n_in,
                              void* d_out, int out_size)
{
    const float* hidden  = (const float*)d_in[0];
    const float* cos_t   = (const float*)d_in[1];
    const float* sin_t   = (const float*)d_in[2];
    const float* w_qkv   = (const float*)d_in[3];
    const float* q_ln    = (const float*)d_in[4];
    const float* k_ln    = (const float*)d_in[5];
    const float* w_dense = (const float*)d_in[6];
    float* out = (float*)d_out;

    void *p_ah, *p_wh, *p_wl, *p_attnh;
    cudaGetSymbolAddress(&p_ah, g_ah);
    cudaGetSymbolAddress(&p_wh, g_wh);
    cudaGetSymbolAddress(&p_wl, g_wl);
    cudaGetSymbolAddress(&p_attnh, g_attnh);
    __half* ah    = (__half*)p_ah;
    __half* wh    = (__half*)p_wh;
    __half* wl    = (__half*)p_wl;
    __half* attnh = (__half*)p_attnh;

    cudaFuncSetAttribute(gemm_f16_kernel,
                         cudaFuncAttributeMaxDynamicSharedMemorySize, GEMM_SMEM);
    cudaFuncSetAttribute(gemm_qkv_kernel,
                         cudaFuncAttributeMaxDynamicSharedMemorySize, GEMM_SMEM);
    cudaFuncSetAttribute(attn_mma_kernel,
                         cudaFuncAttributeMaxDynamicSharedMemorySize, ATTN2_SMEM);

    // 0) convert hidden -> fp16; split w_qkv -> fp16 hi/lo
    cvt_f16_kernel<<<(NTOK * HID / 4 + 255) / 256, 256>>>(hidden, ah, NTOK * HID / 4);
    split_f16_kernel<<<(QKVO * HID / 4 + 255) / 256, 256>>>(w_qkv, wh, wl, QKVO * HID / 4);

    // 1) Fused QKV projection + RMSNorm + RoPE -> fp16 Q/K/V
    gemm_qkv_kernel<<<dim3(QKVO / 128, NTOK / 128), 256, GEMM_SMEM>>>(
        ah, wh, wl, cos_t, sin_t, q_ln, k_ln, HID);

    // 2) Flash attention (1-term S, 1-term PV) -> fp16 output
    attn_mma_kernel<<<dim3(SS / 128, BB * NH), 256, ATTN2_SMEM>>>();

    // 2b) split w_dense (reuses g_wh/g_wl)
    split_f16_kernel<<<(HID * HID / 4 + 255) / 256, 256>>>(w_dense, wh, wl, HID * HID / 4);

    // 3) Output projection
    gemm_f16_kernel<<<dim3(HID / 128, NTOK / 128), 256, GEMM_SMEM>>>(
        attnh, wh, wl, out, HID, HID);
}